// round 7
// baseline (speedup 1.0000x reference)
#include <cuda_runtime.h>
#include <math.h>

#define NN 100000
#define EE 1600000

typedef unsigned long long u64;

// -------- scratch (device globals; no allocation allowed) --------
__device__ float g_cnt[NN];
__device__ float g_agg[(size_t)NN * 128];
__device__ float g_h1[(size_t)NN * 128];
__device__ float g_h2[(size_t)NN * 128];
__device__ float g_hmT[(size_t)NN * 256];   // hidden MLP layer, TRANSPOSED [256][N]

// -------- helpers --------
__device__ __forceinline__ void red_add_v4(float* addr, float4 v) {
    asm volatile("red.global.add.v4.f32 [%0], {%1,%2,%3,%4};"
                 :: "l"(addr), "f"(v.x), "f"(v.y), "f"(v.z), "f"(v.w) : "memory");
}
__device__ __forceinline__ void red_add_f32(float* addr, float v) {
    asm volatile("red.global.add.f32 [%0], %1;" :: "l"(addr), "f"(v) : "memory");
}
__device__ __forceinline__ float sigmoidf_(float x) {
    return 1.0f / (1.0f + __expf(-x));
}
// packed f32x2 FMA: d = a*b + d  (SASS FFMA2; PTX-only path on sm_103a)
__device__ __forceinline__ void fma2(u64& d, u64 a, u64 b) {
    asm("fma.rn.f32x2 %0, %1, %2, %0;" : "+l"(d) : "l"(a), "l"(b));
}
__device__ __forceinline__ u64 pack2(float lo, float hi) {
    u64 r;
    asm("mov.b64 %0, {%1, %2};" : "=l"(r) : "f"(lo), "f"(hi));
    return r;
}
__device__ __forceinline__ float2 unpack2(u64 v) {
    float2 f;
    asm("mov.b64 {%0, %1}, %2;" : "=f"(f.x), "=f"(f.y) : "l"(v));
    return f;
}
__device__ __forceinline__ void fma4(float4& a, float s, const float4& x) {
    a.x = fmaf(s, x.x, a.x); a.y = fmaf(s, x.y, a.y);
    a.z = fmaf(s, x.z, a.z); a.w = fmaf(s, x.w, a.w);
}

// -------- zero --------
__global__ void zero_kernel(float4* __restrict__ p, int n4) {
    int i = blockIdx.x * blockDim.x + threadIdx.x;
    int stride = gridDim.x * blockDim.x;
    float4 z = make_float4(0.f, 0.f, 0.f, 0.f);
    for (; i < n4; i += stride) p[i] = z;
}

// -------- cnt -> 1/max(cnt,1) --------
__global__ void invcnt_kernel(float* __restrict__ cnt, int n) {
    int i = blockIdx.x * blockDim.x + threadIdx.x;
    if (i < n) cnt[i] = 1.0f / fmaxf(cnt[i], 1.0f);
}

// -------- edge scatter: per-thread = (edge, 16-float chunk); edge_index is int32 --------
template<int D>
__global__ void __launch_bounds__(256) scatter_kernel(
    const int* __restrict__ ei,         // [2, E] int32
    const float* __restrict__ x,        // [N, D]
    float* __restrict__ agg,            // [N, D]
    float* __restrict__ cnt,            // [N]
    int E, int nNodes, int doCnt)
{
    const int CH = D / 16;
    long long tid = (long long)blockIdx.x * blockDim.x + threadIdx.x;
    long long e = tid / CH;
    int c = (int)(tid - e * CH);
    if (e >= E) return;
    int s = ei[e];
    int d = ei[(long long)E + e];
    if ((unsigned)s >= (unsigned)nNodes || (unsigned)d >= (unsigned)nNodes) return;
    const float4* src = (const float4*)(x + (size_t)s * D + c * 16);
    float* dst = agg + (size_t)d * D + c * 16;
    float4 a = src[0], b = src[1], cc = src[2], dd = src[3];
    red_add_v4(dst + 0, a);
    red_add_v4(dst + 4, b);
    red_add_v4(dst + 8, cc);
    red_add_v4(dst + 12, dd);
    if (doCnt && c == 0) red_add_f32(cnt + d, 1.0f);
}

// ============================================================================
// combine: X = concat(self, agg*invc) [K]; out = sigmoid(X @ W + b), 128 outs
// 64 nodes/block, 256 threads. Tile: 4 strided nodes x 8 outs (4 out-PAIRS).
// X stored in smem PRE-DUPLICATED as (x,x) u64 -> zero packing in mainloop.
// Mainloop per k: 4 LDS.64(xdup) + 4 LDS.64(w-pairs) + 16 FFMA2.
// K chunked by 128 (Xd) and 64 (Ws): smem 99,328B -> 2 blocks/SM for both K.
// ============================================================================
template<int K>
__global__ void __launch_bounds__(256) combine_kernel(
    const float* __restrict__ self,   // [N, K/2]
    const float* __restrict__ agg,    // [N, K/2]
    const float* __restrict__ invc,   // [N]  (reciprocal counts)
    const float* __restrict__ W,      // [K, 128] row-major
    const float* __restrict__ b,      // [128]
    float* __restrict__ out,          // [N, 128]
    int nNodes)
{
    constexpr int SELF = K / 2;
    extern __shared__ float smf[];
    u64*   Xd = (u64*)smf;             // [128][65] dup pairs  (66,560 B)
    float* Ws = smf + 128 * 65 * 2;    // [64][128]            (32,768 B)

    const int t = threadIdx.x;
    const int base = blockIdx.x * 64;
    const int ng = t & 15;
    const int og = t >> 4;
    const int j0 = og * 8;

    u64 accp[4][4];
    #pragma unroll
    for (int jp = 0; jp < 4; ++jp) {
        u64 bp = pack2(b[j0 + 2 * jp], b[j0 + 2 * jp + 1]);
        accp[0][jp] = bp; accp[1][jp] = bp; accp[2][jp] = bp; accp[3][jp] = bp;
    }

    for (int c2 = 0; c2 < K / 128; ++c2) {
        __syncthreads();   // prior reads of Xd complete
        // build X chunk, transposed+duplicated: lanes at consecutive kk
        for (int i = t; i < 64 * 128; i += 256) {
            int n = i >> 7, kk = i & 127;
            int kg = c2 * 128 + kk;
            int ngl = base + n;
            float v = 0.f;
            if (ngl < nNodes) {
                if (kg < SELF) v = self[(size_t)ngl * SELF + kg];
                else v = agg[(size_t)ngl * SELF + (kg - SELF)] * invc[ngl];
            }
            Xd[kk * 65 + n] = pack2(v, v);
        }
        for (int c = 0; c < 2; ++c) {
            __syncthreads();   // build done / prev mainloop done reading Ws
            {
                const float4* Wg = (const float4*)(W + (size_t)(c2 * 128 + c * 64) * 128);
                float4* Ws4 = (float4*)Ws;
                for (int i = t; i < 64 * 32; i += 256) Ws4[i] = Wg[i];
            }
            __syncthreads();
            const u64* Xc = Xd + c * 64 * 65;
            #pragma unroll 4
            for (int kk = 0; kk < 64; ++kk) {
                const u64* xr = Xc + kk * 65 + ng;
                u64 xd0 = xr[0], xd1 = xr[16], xd2 = xr[32], xd3 = xr[48];
                const u64* wp = (const u64*)(Ws + kk * 128 + j0);
                u64 w0 = wp[0], w1 = wp[1], w2 = wp[2], w3 = wp[3];
                fma2(accp[0][0], xd0, w0); fma2(accp[0][1], xd0, w1);
                fma2(accp[0][2], xd0, w2); fma2(accp[0][3], xd0, w3);
                fma2(accp[1][0], xd1, w0); fma2(accp[1][1], xd1, w1);
                fma2(accp[1][2], xd1, w2); fma2(accp[1][3], xd1, w3);
                fma2(accp[2][0], xd2, w0); fma2(accp[2][1], xd2, w1);
                fma2(accp[2][2], xd2, w2); fma2(accp[2][3], xd2, w3);
                fma2(accp[3][0], xd3, w0); fma2(accp[3][1], xd3, w1);
                fma2(accp[3][2], xd3, w2); fma2(accp[3][3], xd3, w3);
            }
        }
    }
    __syncthreads();   // all smem reads done; reuse as staging

    float* Rs = smf;   // [64][132]
    #pragma unroll
    for (int m = 0; m < 4; ++m) {
        int node = ng + 16 * m;
        #pragma unroll
        for (int jp = 0; jp < 4; ++jp) {
            float2 v = unpack2(accp[m][jp]);
            Rs[node * 132 + j0 + 2 * jp + 0] = sigmoidf_(v.x);
            Rs[node * 132 + j0 + 2 * jp + 1] = sigmoidf_(v.y);
        }
    }
    __syncthreads();

    const float4* Rs4 = (const float4*)Rs;
    float4* out4 = (float4*)out;
    for (int i = t; i < 64 * 32; i += 256) {
        int n = i >> 5, q = i & 31;
        int ngl = base + n;
        if (ngl < nNodes) out4[(size_t)ngl * 32 + q] = Rs4[n * 33 + q];
    }
}

// ============================================================================
// mlp1: hmT = relu(h2 @ Wm1 + bm1), written TRANSPOSED: hmT[j][n]
// Same FFMA2 tile. Xd built once (K=128); 2 N-passes x 2 W-chunks.
// ============================================================================
__global__ void __launch_bounds__(256) mlp1_kernel(
    const float* __restrict__ h2,     // [N, 128]
    const float* __restrict__ Wm1,    // [128, 256]
    const float* __restrict__ bm1,    // [256]
    float* __restrict__ hmT,          // [256][N]
    int nNodes)
{
    extern __shared__ float smf[];
    u64*   Xd = (u64*)smf;             // [128][65] dup pairs
    float* Ws = smf + 128 * 65 * 2;    // [64][128]; reused as staging [128][64]

    const int t = threadIdx.x;
    const int base = blockIdx.x * 64;
    const int ng = t & 15;
    const int og = t >> 4;
    const int j0 = og * 8;

    for (int i = t; i < 64 * 128; i += 256) {
        int n = i >> 7, kk = i & 127;
        int ngl = base + n;
        float v = (ngl < nNodes) ? h2[(size_t)ngl * 128 + kk] : 0.f;
        Xd[kk * 65 + n] = pack2(v, v);
    }

    for (int pass = 0; pass < 2; ++pass) {
        u64 accp[4][4];
        #pragma unroll
        for (int jp = 0; jp < 4; ++jp) {
            u64 bp = pack2(bm1[pass * 128 + j0 + 2 * jp], bm1[pass * 128 + j0 + 2 * jp + 1]);
            accp[0][jp] = bp; accp[1][jp] = bp; accp[2][jp] = bp; accp[3][jp] = bp;
        }
        for (int c = 0; c < 2; ++c) {
            __syncthreads();   // Xd built / staging drained / prev chunk read
            {
                const float4* Wg = (const float4*)Wm1;
                float4* Ws4 = (float4*)Ws;
                for (int i = t; i < 64 * 32; i += 256) {
                    int kl = i >> 5, q = i & 31;
                    Ws4[kl * 32 + q] = Wg[(c * 64 + kl) * 64 + pass * 32 + q];
                }
            }
            __syncthreads();
            const u64* Xc = Xd + c * 64 * 65;
            #pragma unroll 4
            for (int kk = 0; kk < 64; ++kk) {
                const u64* xr = Xc + kk * 65 + ng;
                u64 xd0 = xr[0], xd1 = xr[16], xd2 = xr[32], xd3 = xr[48];
                const u64* wp = (const u64*)(Ws + kk * 128 + j0);
                u64 w0 = wp[0], w1 = wp[1], w2 = wp[2], w3 = wp[3];
                fma2(accp[0][0], xd0, w0); fma2(accp[0][1], xd0, w1);
                fma2(accp[0][2], xd0, w2); fma2(accp[0][3], xd0, w3);
                fma2(accp[1][0], xd1, w0); fma2(accp[1][1], xd1, w1);
                fma2(accp[1][2], xd1, w2); fma2(accp[1][3], xd1, w3);
                fma2(accp[2][0], xd2, w0); fma2(accp[2][1], xd2, w1);
                fma2(accp[2][2], xd2, w2); fma2(accp[2][3], xd2, w3);
                fma2(accp[3][0], xd3, w0); fma2(accp[3][1], xd3, w1);
                fma2(accp[3][2], xd3, w2); fma2(accp[3][3], xd3, w3);
            }
        }
        __syncthreads();   // done reading Ws; reuse as staging [128][64]
        float* Rst = Ws;
        #pragma unroll
        for (int m = 0; m < 4; ++m) {
            int node = ng + 16 * m;
            #pragma unroll
            for (int jp = 0; jp < 4; ++jp) {
                float2 v = unpack2(accp[m][jp]);
                Rst[(j0 + 2 * jp + 0) * 64 + node] = fmaxf(v.x, 0.f);
                Rst[(j0 + 2 * jp + 1) * 64 + node] = fmaxf(v.y, 0.f);
            }
        }
        __syncthreads();

        if (base + 64 <= nNodes) {
            const float4* Rst4 = (const float4*)Rst;
            for (int i = t; i < 128 * 16; i += 256) {
                int j = i >> 4, q = i & 15;
                *(float4*)(hmT + (size_t)(pass * 128 + j) * nNodes + base + q * 4) = Rst4[j * 16 + q];
            }
        } else {
            for (int i = t; i < 128 * 64; i += 256) {
                int j = i >> 6, n = i & 63;
                if (base + n < nNodes)
                    hmT[(size_t)(pass * 128 + j) * nNodes + base + n] = Rst[j * 64 + n];
            }
        }
    }
}

// ============================================================================
// mlp2: out = hmT^T @ Wm2 + bm2  (K=256, NOUT=40)
// 256 nodes/block, 256 threads, tile 4n x 10o. hmT read coalesced via LDG.128.
// ============================================================================
__global__ void __launch_bounds__(256) mlp2_kernel(
    const float* __restrict__ hmT,    // [256][N]
    const float* __restrict__ Wm2,    // [256, 40]
    const float* __restrict__ bm2,    // [40]
    float* __restrict__ out,          // [N, 40]
    int nNodes)
{
    extern __shared__ float smf[];
    float* Ws = smf;                  // [256][40]
    float* Rs = smf + 256 * 40;       // [256][44]

    const int t = threadIdx.x;
    const int base = blockIdx.x * 256;
    const int ng = t & 63;
    const int og = t >> 6;
    const int n0 = base + ng * 4;
    const int j0 = og * 10;

    {
        const float4* Wg = (const float4*)Wm2;
        float4* Ws4 = (float4*)Ws;
        for (int i = t; i < 2560; i += 256) Ws4[i] = Wg[i];
    }
    __syncthreads();

    float4 acc[10];
    #pragma unroll
    for (int j = 0; j < 10; ++j) {
        float bv = bm2[j0 + j];
        acc[j] = make_float4(bv, bv, bv, bv);
    }

    if (n0 + 3 < nNodes) {
        #pragma unroll 2
        for (int k = 0; k < 256; ++k) {
            float4 x4 = *(const float4*)(hmT + (size_t)k * nNodes + n0);
            const float2* wr = (const float2*)(Ws + k * 40 + j0);
            float2 w0 = wr[0], w1 = wr[1], w2 = wr[2], w3 = wr[3], w4 = wr[4];
            fma4(acc[0], w0.x, x4); fma4(acc[1], w0.y, x4);
            fma4(acc[2], w1.x, x4); fma4(acc[3], w1.y, x4);
            fma4(acc[4], w2.x, x4); fma4(acc[5], w2.y, x4);
            fma4(acc[6], w3.x, x4); fma4(acc[7], w3.y, x4);
            fma4(acc[8], w4.x, x4); fma4(acc[9], w4.y, x4);
        }
    } else {
        for (int k = 0; k < 256; ++k) {
            float4 x4;
            const float* row = hmT + (size_t)k * nNodes;
            x4.x = (n0 + 0 < nNodes) ? row[n0 + 0] : 0.f;
            x4.y = (n0 + 1 < nNodes) ? row[n0 + 1] : 0.f;
            x4.z = (n0 + 2 < nNodes) ? row[n0 + 2] : 0.f;
            x4.w = (n0 + 3 < nNodes) ? row[n0 + 3] : 0.f;
            const float2* wr = (const float2*)(Ws + k * 40 + j0);
            float2 w0 = wr[0], w1 = wr[1], w2 = wr[2], w3 = wr[3], w4 = wr[4];
            fma4(acc[0], w0.x, x4); fma4(acc[1], w0.y, x4);
            fma4(acc[2], w1.x, x4); fma4(acc[3], w1.y, x4);
            fma4(acc[4], w2.x, x4); fma4(acc[5], w2.y, x4);
            fma4(acc[6], w3.x, x4); fma4(acc[7], w3.y, x4);
            fma4(acc[8], w4.x, x4); fma4(acc[9], w4.y, x4);
        }
    }

    int nl = ng * 4;
    #pragma unroll
    for (int j = 0; j < 10; ++j) {
        Rs[(nl + 0) * 44 + j0 + j] = acc[j].x;
        Rs[(nl + 1) * 44 + j0 + j] = acc[j].y;
        Rs[(nl + 2) * 44 + j0 + j] = acc[j].z;
        Rs[(nl + 3) * 44 + j0 + j] = acc[j].w;
    }
    __syncthreads();

    const float4* Rs4 = (const float4*)Rs;
    float4* out4 = (float4*)out;
    for (int i = t; i < 256 * 10; i += 256) {
        int n = i / 10, q = i - n * 10;
        int ngl = base + n;
        if (ngl < nNodes) out4[(size_t)ngl * 10 + q] = Rs4[n * 11 + q];
    }
}

// -------- launch --------
extern "C" void kernel_launch(void* const* d_in, const int* in_sizes, int n_in,
                              void* d_out, int out_size)
{
    const float* feat = (const float*)d_in[0];
    const int*   ei   = (const int*)d_in[1];     // int32 (JAX x64 disabled)
    const float* W1  = (const float*)d_in[2];
    const float* b1  = (const float*)d_in[3];
    const float* W2  = (const float*)d_in[4];
    const float* b2  = (const float*)d_in[5];
    const float* Wm1 = (const float*)d_in[6];
    const float* bm1 = (const float*)d_in[7];
    const float* Wm2 = (const float*)d_in[8];
    const float* bm2 = (const float*)d_in[9];
    float* out = (float*)d_out;

    const int N = in_sizes[0] / 64;     // 100000
    const int E = in_sizes[1] / 2;      // 1600000

    float *agg, *cnt, *h1, *h2, *hmT;
    cudaGetSymbolAddress((void**)&agg, g_agg);
    cudaGetSymbolAddress((void**)&cnt, g_cnt);
    cudaGetSymbolAddress((void**)&h1,  g_h1);
    cudaGetSymbolAddress((void**)&h2,  g_h2);
    cudaGetSymbolAddress((void**)&hmT, g_hmT);

    const int SM_GEMM = (128 * 65 * 2 + 64 * 128) * 4;   // 99,328 B -> 2 blocks/SM
    const int SM_MLP2 = (256 * 40 + 256 * 44) * 4;       // 86,016 B
    cudaFuncSetAttribute(combine_kernel<128>, cudaFuncAttributeMaxDynamicSharedMemorySize, SM_GEMM);
    cudaFuncSetAttribute(combine_kernel<256>, cudaFuncAttributeMaxDynamicSharedMemorySize, SM_GEMM);
    cudaFuncSetAttribute(mlp1_kernel,         cudaFuncAttributeMaxDynamicSharedMemorySize, SM_GEMM);
    cudaFuncSetAttribute(mlp2_kernel,         cudaFuncAttributeMaxDynamicSharedMemorySize, SM_MLP2);

    const int nodeBlocks = (N + 63) / 64;        // 1563
    const int mlp2Blocks = (N + 255) / 256;      // 391

    // Layer 1
    {
        int n4 = (N * 64) / 4;
        zero_kernel<<<4096, 256>>>((float4*)agg, n4);
        zero_kernel<<<256, 256>>>((float4*)cnt, N / 4);
        long long tot = (long long)E * 4;
        int blocks = (int)((tot + 255) / 256);
        scatter_kernel<64><<<blocks, 256>>>(ei, feat, agg, cnt, E, N, 1);
        invcnt_kernel<<<(N + 255) / 256, 256>>>(cnt, N);
        combine_kernel<128><<<nodeBlocks, 256, SM_GEMM>>>(feat, agg, cnt, W1, b1, h1, N);
    }
    // Layer 2
    {
        int n4 = (N * 128) / 4;
        zero_kernel<<<4096, 256>>>((float4*)agg, n4);
        long long tot = (long long)E * 8;
        int blocks = (int)((tot + 255) / 256);
        scatter_kernel<128><<<blocks, 256>>>(ei, h1, agg, cnt, E, N, 0);
        combine_kernel<256><<<nodeBlocks, 256, SM_GEMM>>>(h1, agg, cnt, W2, b2, h2, N);
    }
    // MLP
    mlp1_kernel<<<nodeBlocks, 256, SM_GEMM>>>(h2, Wm1, bm1, hmT, N);
    mlp2_kernel<<<mlp2Blocks, 256, SM_MLP2>>>(hmT, Wm2, bm2, out, N);
}

// round 8
// speedup vs baseline: 1.0153x; 1.0153x over previous
#include <cuda_runtime.h>
#include <math.h>

#define NN 100000
#define EE 1600000

// -------- scratch (device globals; no allocation allowed) --------
__device__ float g_cnt[NN];
__device__ float g_agg[(size_t)NN * 128];
__device__ float g_h1[(size_t)NN * 128];
__device__ float g_h2[(size_t)NN * 128];
__device__ float g_hmT[(size_t)NN * 256];   // hidden MLP layer, TRANSPOSED [256][N]

// -------- helpers --------
__device__ __forceinline__ void red_add_v4(float* addr, float4 v) {
    asm volatile("red.global.add.v4.f32 [%0], {%1,%2,%3,%4};"
                 :: "l"(addr), "f"(v.x), "f"(v.y), "f"(v.z), "f"(v.w) : "memory");
}
__device__ __forceinline__ void red_add_f32(float* addr, float v) {
    asm volatile("red.global.add.f32 [%0], %1;" :: "l"(addr), "f"(v) : "memory");
}
__device__ __forceinline__ float sigmoidf_(float x) {
    return 1.0f / (1.0f + __expf(-x));
}
__device__ __forceinline__ void fma4(float4& a, float s, const float4& x) {
    a.x = fmaf(s, x.x, a.x); a.y = fmaf(s, x.y, a.y);
    a.z = fmaf(s, x.z, a.z); a.w = fmaf(s, x.w, a.w);
}

// -------- zero two buffers in one launch --------
__global__ void zero2_kernel(float4* __restrict__ a, int n4a,
                             float4* __restrict__ b, int n4b) {
    int i = blockIdx.x * blockDim.x + threadIdx.x;
    int stride = gridDim.x * blockDim.x;
    float4 z = make_float4(0.f, 0.f, 0.f, 0.f);
    for (int k = i; k < n4a; k += stride) a[k] = z;
    if (b) for (int k = i; k < n4b; k += stride) b[k] = z;
}

// -------- cnt -> 1/max(cnt,1) --------
__global__ void invcnt_kernel(float* __restrict__ cnt, int n) {
    int i = blockIdx.x * blockDim.x + threadIdx.x;
    if (i < n) cnt[i] = 1.0f / fmaxf(cnt[i], 1.0f);
}

// -------- edge scatter: per-thread = (edge, 16-float chunk); edge_index is int32 --------
template<int D>
__global__ void __launch_bounds__(256) scatter_kernel(
    const int* __restrict__ ei,         // [2, E] int32
    const float* __restrict__ x,        // [N, D]
    float* __restrict__ agg,            // [N, D]
    float* __restrict__ cnt,            // [N]
    int E, int nNodes, int doCnt)
{
    const int CH = D / 16;
    long long tid = (long long)blockIdx.x * blockDim.x + threadIdx.x;
    long long e = tid / CH;
    int c = (int)(tid - e * CH);
    if (e >= E) return;
    int s = ei[e];
    int d = ei[(long long)E + e];
    if ((unsigned)s >= (unsigned)nNodes || (unsigned)d >= (unsigned)nNodes) return;
    const float4* src = (const float4*)(x + (size_t)s * D + c * 16);
    float* dst = agg + (size_t)d * D + c * 16;
    float4 a = src[0], b = src[1], cc = src[2], dd = src[3];
    red_add_v4(dst + 0, a);
    red_add_v4(dst + 4, b);
    red_add_v4(dst + 8, cc);
    red_add_v4(dst + 12, dd);
    if (doCnt && c == 0) red_add_f32(cnt + d, 1.0f);
}

#define XPAD 130   // Xs row stride (floats); even (float2 aligned), %32==2

// ============================================================================
// combine: X = concat(self, agg*invc) [K]; out = sigmoid(X @ W + b), 128 outs
// 128 nodes/block, 256 threads. Thread tile: 8 nodes (4 float2 pairs, cols
// {2ng,2ng+1}+32m) x 8 outs. Per k: 4 LDS.64(x) + 2 LDS.128(w) + 64 FFMA.
// Xs[128][130] + Ws[64][128] = 99,328 B smem -> 2 blocks/SM.
// ============================================================================
template<int K>
__global__ void __launch_bounds__(256) combine_kernel(
    const float* __restrict__ self,   // [N, K/2]
    const float* __restrict__ agg,    // [N, K/2]
    const float* __restrict__ invc,   // [N]
    const float* __restrict__ W,      // [K, 128] row-major
    const float* __restrict__ b,      // [128]
    float* __restrict__ out,          // [N, 128]
    int nNodes)
{
    constexpr int SELF = K / 2;
    extern __shared__ float smf[];
    float* Xs = smf;                  // [128][XPAD]
    float* Ws = smf + 128 * XPAD;     // [64][128]

    const int t = threadIdx.x;
    const int base = blockIdx.x * 128;
    const int ng = t & 15;
    const int og = t >> 4;
    const int j0 = og * 8;
    const int n0 = 2 * ng;            // first node col of this thread's pairs

    float2 acc[4][8];
    #pragma unroll
    for (int j = 0; j < 8; ++j) {
        float bv = b[j0 + j];
        #pragma unroll
        for (int m = 0; m < 4; ++m) acc[m][j] = make_float2(bv, bv);
    }

    for (int c2 = 0; c2 < K / 128; ++c2) {
        __syncthreads();   // prior reads of Xs/Ws complete
        // build X chunk, transposed: lanes at consecutive kk -> coalesced LDG
        for (int i = t; i < 128 * 128; i += 256) {
            int n = i >> 7, kk = i & 127;
            int kg = c2 * 128 + kk;
            int ngl = base + n;
            float v = 0.f;
            if (ngl < nNodes) {
                if (kg < SELF) v = self[(size_t)ngl * SELF + kg];
                else v = agg[(size_t)ngl * SELF + (kg - SELF)] * invc[ngl];
            }
            Xs[kk * XPAD + n] = v;
        }
        for (int c = 0; c < 2; ++c) {
            __syncthreads();   // build done / prev mainloop done with Ws
            {
                const float4* Wg = (const float4*)(W + (size_t)(c2 * 128 + c * 64) * 128);
                float4* Ws4 = (float4*)Ws;
                for (int i = t; i < 64 * 32; i += 256) Ws4[i] = Wg[i];
            }
            __syncthreads();
            const float* Xc = Xs + c * 64 * XPAD;
            #pragma unroll 2
            for (int kk = 0; kk < 64; ++kk) {
                const float* xr = Xc + kk * XPAD + n0;
                float2 x0 = *(const float2*)(xr +  0);
                float2 x1 = *(const float2*)(xr + 32);
                float2 x2 = *(const float2*)(xr + 64);
                float2 x3 = *(const float2*)(xr + 96);
                float4 wa = *(const float4*)(Ws + kk * 128 + j0);
                float4 wb = *(const float4*)(Ws + kk * 128 + j0 + 4);
                float w[8] = {wa.x, wa.y, wa.z, wa.w, wb.x, wb.y, wb.z, wb.w};
                #pragma unroll
                for (int j = 0; j < 8; ++j) {
                    acc[0][j].x = fmaf(x0.x, w[j], acc[0][j].x);
                    acc[0][j].y = fmaf(x0.y, w[j], acc[0][j].y);
                    acc[1][j].x = fmaf(x1.x, w[j], acc[1][j].x);
                    acc[1][j].y = fmaf(x1.y, w[j], acc[1][j].y);
                    acc[2][j].x = fmaf(x2.x, w[j], acc[2][j].x);
                    acc[2][j].y = fmaf(x2.y, w[j], acc[2][j].y);
                    acc[3][j].x = fmaf(x3.x, w[j], acc[3][j].x);
                    acc[3][j].y = fmaf(x3.y, w[j], acc[3][j].y);
                }
            }
        }
    }
    __syncthreads();   // all smem reads done; reuse as staging

    float* Rs = smf;   // [128][132]
    #pragma unroll
    for (int m = 0; m < 4; ++m) {
        int ne = n0 + 32 * m;
        #pragma unroll
        for (int j = 0; j < 8; ++j) {
            Rs[(ne + 0) * 132 + j0 + j] = sigmoidf_(acc[m][j].x);
            Rs[(ne + 1) * 132 + j0 + j] = sigmoidf_(acc[m][j].y);
        }
    }
    __syncthreads();

    const float4* Rs4 = (const float4*)Rs;
    float4* out4 = (float4*)out;
    for (int i = t; i < 128 * 32; i += 256) {
        int n = i >> 5, q = i & 31;
        int ngl = base + n;
        if (ngl < nNodes) out4[(size_t)ngl * 32 + q] = Rs4[n * 33 + q];
    }
}

// ============================================================================
// mlp1: hmT = relu(h2 @ Wm1 + bm1), TRANSPOSED out: hmT[j][n], j in [0,256)
// Same 128-node tile. Xs built once; 2 N-passes x 2 W-chunks.
// Writes hmT directly from registers via STG.64 (coalesced per half-warp).
// ============================================================================
__global__ void __launch_bounds__(256) mlp1_kernel(
    const float* __restrict__ h2,     // [N, 128]
    const float* __restrict__ Wm1,    // [128, 256]
    const float* __restrict__ bm1,    // [256]
    float* __restrict__ hmT,          // [256][N]
    int nNodes)
{
    extern __shared__ float smf[];
    float* Xs = smf;                  // [128][XPAD]
    float* Ws = smf + 128 * XPAD;     // [64][128]

    const int t = threadIdx.x;
    const int base = blockIdx.x * 128;
    const int ng = t & 15;
    const int og = t >> 4;
    const int j0 = og * 8;
    const int n0 = 2 * ng;

    for (int i = t; i < 128 * 128; i += 256) {
        int n = i >> 7, kk = i & 127;
        int ngl = base + n;
        Xs[kk * XPAD + n] = (ngl < nNodes) ? h2[(size_t)ngl * 128 + kk] : 0.f;
    }

    for (int pass = 0; pass < 2; ++pass) {
        float2 acc[4][8];
        #pragma unroll
        for (int j = 0; j < 8; ++j) {
            float bv = bm1[pass * 128 + j0 + j];
            #pragma unroll
            for (int m = 0; m < 4; ++m) acc[m][j] = make_float2(bv, bv);
        }
        for (int c = 0; c < 2; ++c) {
            __syncthreads();   // Xs built / prev mainloop done with Ws
            {
                const float4* Wg = (const float4*)Wm1;
                float4* Ws4 = (float4*)Ws;
                for (int i = t; i < 64 * 32; i += 256) {
                    int kl = i >> 5, q = i & 31;
                    Ws4[kl * 32 + q] = Wg[(c * 64 + kl) * 64 + pass * 32 + q];
                }
            }
            __syncthreads();
            const float* Xc = Xs + c * 64 * XPAD;
            #pragma unroll 2
            for (int kk = 0; kk < 64; ++kk) {
                const float* xr = Xc + kk * XPAD + n0;
                float2 x0 = *(const float2*)(xr +  0);
                float2 x1 = *(const float2*)(xr + 32);
                float2 x2 = *(const float2*)(xr + 64);
                float2 x3 = *(const float2*)(xr + 96);
                float4 wa = *(const float4*)(Ws + kk * 128 + j0);
                float4 wb = *(const float4*)(Ws + kk * 128 + j0 + 4);
                float w[8] = {wa.x, wa.y, wa.z, wa.w, wb.x, wb.y, wb.z, wb.w};
                #pragma unroll
                for (int j = 0; j < 8; ++j) {
                    acc[0][j].x = fmaf(x0.x, w[j], acc[0][j].x);
                    acc[0][j].y = fmaf(x0.y, w[j], acc[0][j].y);
                    acc[1][j].x = fmaf(x1.x, w[j], acc[1][j].x);
                    acc[1][j].y = fmaf(x1.y, w[j], acc[1][j].y);
                    acc[2][j].x = fmaf(x2.x, w[j], acc[2][j].x);
                    acc[2][j].y = fmaf(x2.y, w[j], acc[2][j].y);
                    acc[3][j].x = fmaf(x3.x, w[j], acc[3][j].x);
                    acc[3][j].y = fmaf(x3.y, w[j], acc[3][j].y);
                }
            }
        }
        // write hmT rows directly (coalesced STG.64 across lanes 0..15)
        #pragma unroll
        for (int m = 0; m < 4; ++m) {
            int col = base + n0 + 32 * m;
            #pragma unroll
            for (int j = 0; j < 8; ++j) {
                float2 v = make_float2(fmaxf(acc[m][j].x, 0.f), fmaxf(acc[m][j].y, 0.f));
                float* dst = hmT + (size_t)(pass * 128 + j0 + j) * nNodes + col;
                if (col + 1 < nNodes)      *(float2*)dst = v;
                else if (col < nNodes)     dst[0] = v.x;
            }
        }
    }
}

// ============================================================================
// mlp2: out = hmT^T @ Wm2 + bm2  (K=256, NOUT=40)
// 256 nodes/block, 256 threads, tile 4n x 10o. hmT read coalesced via LDG.128.
// ============================================================================
__global__ void __launch_bounds__(256) mlp2_kernel(
    const float* __restrict__ hmT,    // [256][N]
    const float* __restrict__ Wm2,    // [256, 40]
    const float* __restrict__ bm2,    // [40]
    float* __restrict__ out,          // [N, 40]
    int nNodes)
{
    extern __shared__ float smf[];
    float* Ws = smf;                  // [256][40]
    float* Rs = smf + 256 * 40;       // [256][44]

    const int t = threadIdx.x;
    const int base = blockIdx.x * 256;
    const int ng = t & 63;
    const int og = t >> 6;
    const int n0 = base + ng * 4;
    const int j0 = og * 10;

    {
        const float4* Wg = (const float4*)Wm2;
        float4* Ws4 = (float4*)Ws;
        for (int i = t; i < 2560; i += 256) Ws4[i] = Wg[i];
    }
    __syncthreads();

    float4 acc[10];
    #pragma unroll
    for (int j = 0; j < 10; ++j) {
        float bv = bm2[j0 + j];
        acc[j] = make_float4(bv, bv, bv, bv);
    }

    if (n0 + 3 < nNodes) {
        #pragma unroll 2
        for (int k = 0; k < 256; ++k) {
            float4 x4 = *(const float4*)(hmT + (size_t)k * nNodes + n0);
            const float2* wr = (const float2*)(Ws + k * 40 + j0);
            float2 w0 = wr[0], w1 = wr[1], w2 = wr[2], w3 = wr[3], w4 = wr[4];
            fma4(acc[0], w0.x, x4); fma4(acc[1], w0.y, x4);
            fma4(acc[2], w1.x, x4); fma4(acc[3], w1.y, x4);
            fma4(acc[4], w2.x, x4); fma4(acc[5], w2.y, x4);
            fma4(acc[6], w3.x, x4); fma4(acc[7], w3.y, x4);
            fma4(acc[8], w4.x, x4); fma4(acc[9], w4.y, x4);
        }
    } else {
        for (int k = 0; k < 256; ++k) {
            float4 x4;
            const float* row = hmT + (size_t)k * nNodes;
            x4.x = (n0 + 0 < nNodes) ? row[n0 + 0] : 0.f;
            x4.y = (n0 + 1 < nNodes) ? row[n0 + 1] : 0.f;
            x4.z = (n0 + 2 < nNodes) ? row[n0 + 2] : 0.f;
            x4.w = (n0 + 3 < nNodes) ? row[n0 + 3] : 0.f;
            const float2* wr = (const float2*)(Ws + k * 40 + j0);
            float2 w0 = wr[0], w1 = wr[1], w2 = wr[2], w3 = wr[3], w4 = wr[4];
            fma4(acc[0], w0.x, x4); fma4(acc[1], w0.y, x4);
            fma4(acc[2], w1.x, x4); fma4(acc[3], w1.y, x4);
            fma4(acc[4], w2.x, x4); fma4(acc[5], w2.y, x4);
            fma4(acc[6], w3.x, x4); fma4(acc[7], w3.y, x4);
            fma4(acc[8], w4.x, x4); fma4(acc[9], w4.y, x4);
        }
    }

    int nl = ng * 4;
    #pragma unroll
    for (int j = 0; j < 10; ++j) {
        Rs[(nl + 0) * 44 + j0 + j] = acc[j].x;
        Rs[(nl + 1) * 44 + j0 + j] = acc[j].y;
        Rs[(nl + 2) * 44 + j0 + j] = acc[j].z;
        Rs[(nl + 3) * 44 + j0 + j] = acc[j].w;
    }
    __syncthreads();

    const float4* Rs4 = (const float4*)Rs;
    float4* out4 = (float4*)out;
    for (int i = t; i < 256 * 10; i += 256) {
        int n = i / 10, q = i - n * 10;
        int ngl = base + n;
        if (ngl < nNodes) out4[(size_t)ngl * 10 + q] = Rs4[n * 11 + q];
    }
}

// -------- launch --------
extern "C" void kernel_launch(void* const* d_in, const int* in_sizes, int n_in,
                              void* d_out, int out_size)
{
    const float* feat = (const float*)d_in[0];
    const int*   ei   = (const int*)d_in[1];     // int32 (JAX x64 disabled)
    const float* W1  = (const float*)d_in[2];
    const float* b1  = (const float*)d_in[3];
    const float* W2  = (const float*)d_in[4];
    const float* b2  = (const float*)d_in[5];
    const float* Wm1 = (const float*)d_in[6];
    const float* bm1 = (const float*)d_in[7];
    const float* Wm2 = (const float*)d_in[8];
    const float* bm2 = (const float*)d_in[9];
    float* out = (float*)d_out;

    const int N = in_sizes[0] / 64;     // 100000
    const int E = in_sizes[1] / 2;      // 1600000

    float *agg, *cnt, *h1, *h2, *hmT;
    cudaGetSymbolAddress((void**)&agg, g_agg);
    cudaGetSymbolAddress((void**)&cnt, g_cnt);
    cudaGetSymbolAddress((void**)&h1,  g_h1);
    cudaGetSymbolAddress((void**)&h2,  g_h2);
    cudaGetSymbolAddress((void**)&hmT, g_hmT);

    const int SM_GEMM = (128 * XPAD + 64 * 128) * 4;   // 99,328 B -> 2 blocks/SM
    const int SM_MLP2 = (256 * 40 + 256 * 44) * 4;     // 86,016 B
    cudaFuncSetAttribute(combine_kernel<128>, cudaFuncAttributeMaxDynamicSharedMemorySize, SM_GEMM);
    cudaFuncSetAttribute(combine_kernel<256>, cudaFuncAttributeMaxDynamicSharedMemorySize, SM_GEMM);
    cudaFuncSetAttribute(mlp1_kernel,         cudaFuncAttributeMaxDynamicSharedMemorySize, SM_GEMM);
    cudaFuncSetAttribute(mlp2_kernel,         cudaFuncAttributeMaxDynamicSharedMemorySize, SM_MLP2);

    const int nodeBlocks = (N + 127) / 128;      // 782
    const int mlp2Blocks = (N + 255) / 256;      // 391

    // Layer 1   (launch order keeps combine<128> at profiler capture slot #4)
    {
        zero2_kernel<<<4096, 256>>>((float4*)agg, (N * 64) / 4, (float4*)cnt, N / 4);
        long long tot = (long long)E * 4;
        int blocks = (int)((tot + 255) / 256);
        scatter_kernel<64><<<blocks, 256>>>(ei, feat, agg, cnt, E, N, 1);
        invcnt_kernel<<<(N + 255) / 256, 256>>>(cnt, N);
        combine_kernel<128><<<nodeBlocks, 256, SM_GEMM>>>(feat, agg, cnt, W1, b1, h1, N);
    }
    // Layer 2
    {
        zero2_kernel<<<4096, 256>>>((float4*)agg, (N * 128) / 4, (float4*)0, 0);
        long long tot = (long long)E * 8;
        int blocks = (int)((tot + 255) / 256);
        scatter_kernel<128><<<blocks, 256>>>(ei, h1, agg, cnt, E, N, 0);
        combine_kernel<256><<<nodeBlocks, 256, SM_GEMM>>>(h1, agg, cnt, W2, b2, h2, N);
    }
    // MLP
    mlp1_kernel<<<nodeBlocks, 256, SM_GEMM>>>(h2, Wm1, bm1, hmT, N);
    mlp2_kernel<<<mlp2Blocks, 256, SM_MLP2>>>(hmT, Wm2, bm2, out, N);
}

// round 9
// speedup vs baseline: 1.1947x; 1.1767x over previous
#include <cuda_runtime.h>
#include <math.h>
#include <stdint.h>

#define NN 100000
#define EE 1600000
#define KP 136    // smem row stride (floats): 136 % 32 == 8 -> conflict-free frag loads

// -------- scratch (device globals; no allocation allowed) --------
__device__ float g_cnt[NN];
__device__ float g_agg[(size_t)NN * 128];
__device__ float g_h1[(size_t)NN * 128];
__device__ float g_h2[(size_t)NN * 128];
__device__ float g_hmT[(size_t)NN * 256];   // hidden MLP layer, TRANSPOSED [256][N]

// -------- helpers --------
__device__ __forceinline__ void red_add_v4(float* addr, float4 v) {
    asm volatile("red.global.add.v4.f32 [%0], {%1,%2,%3,%4};"
                 :: "l"(addr), "f"(v.x), "f"(v.y), "f"(v.z), "f"(v.w) : "memory");
}
__device__ __forceinline__ void red_add_f32(float* addr, float v) {
    asm volatile("red.global.add.f32 [%0], %1;" :: "l"(addr), "f"(v) : "memory");
}
__device__ __forceinline__ float sigmoidf_(float x) {
    return 1.0f / (1.0f + __expf(-x));
}
__device__ __forceinline__ void fma4(float4& a, float s, const float4& x) {
    a.x = fmaf(s, x.x, a.x); a.y = fmaf(s, x.y, a.y);
    a.z = fmaf(s, x.z, a.z); a.w = fmaf(s, x.w, a.w);
}
__device__ __forceinline__ uint32_t f2tf(float x) {
    uint32_t r;
    asm("cvt.rna.tf32.f32 %0, %1;" : "=r"(r) : "f"(x));
    return r;
}
// D += A(16x8,row) * B(8x8,col); tf32 inputs, fp32 accum
__device__ __forceinline__ void mma_tf32(float4& d, const uint32_t* a, const uint32_t* b) {
    asm("mma.sync.aligned.m16n8k8.row.col.f32.tf32.tf32.f32 "
        "{%0,%1,%2,%3}, {%4,%5,%6,%7}, {%8,%9}, {%0,%1,%2,%3};"
        : "+f"(d.x), "+f"(d.y), "+f"(d.z), "+f"(d.w)
        : "r"(a[0]), "r"(a[1]), "r"(a[2]), "r"(a[3]), "r"(b[0]), "r"(b[1]));
}
// split v into tf32 hi + tf32 lo, store to smem
__device__ __forceinline__ void split_store(float v, float* ph, float* pl) {
    uint32_t hb = f2tf(v);
    float hi = __uint_as_float(hb);
    *ph = hi;
    *pl = __uint_as_float(f2tf(v - hi));
}

// -------- zero two buffers in one launch --------
__global__ void zero2_kernel(float4* __restrict__ a, int n4a,
                             float4* __restrict__ b, int n4b) {
    int i = blockIdx.x * blockDim.x + threadIdx.x;
    int stride = gridDim.x * blockDim.x;
    float4 z = make_float4(0.f, 0.f, 0.f, 0.f);
    for (int k = i; k < n4a; k += stride) a[k] = z;
    if (b) for (int k = i; k < n4b; k += stride) b[k] = z;
}

// -------- cnt -> 1/max(cnt,1) --------
__global__ void invcnt_kernel(float* __restrict__ cnt, int n) {
    int i = blockIdx.x * blockDim.x + threadIdx.x;
    if (i < n) cnt[i] = 1.0f / fmaxf(cnt[i], 1.0f);
}

// -------- edge scatter: per-thread = (edge, 16-float chunk); edge_index is int32 --------
template<int D>
__global__ void __launch_bounds__(256) scatter_kernel(
    const int* __restrict__ ei,         // [2, E] int32
    const float* __restrict__ x,        // [N, D]
    float* __restrict__ agg,            // [N, D]
    float* __restrict__ cnt,            // [N]
    int E, int nNodes, int doCnt)
{
    const int CH = D / 16;
    long long tid = (long long)blockIdx.x * blockDim.x + threadIdx.x;
    long long e = tid / CH;
    int c = (int)(tid - e * CH);
    if (e >= E) return;
    int s = ei[e];
    int d = ei[(long long)E + e];
    if ((unsigned)s >= (unsigned)nNodes || (unsigned)d >= (unsigned)nNodes) return;
    const float4* src = (const float4*)(x + (size_t)s * D + c * 16);
    float* dst = agg + (size_t)d * D + c * 16;
    float4 a = src[0], b = src[1], cc = src[2], dd = src[3];
    red_add_v4(dst + 0, a);
    red_add_v4(dst + 4, b);
    red_add_v4(dst + 8, cc);
    red_add_v4(dst + 12, dd);
    if (doCnt && c == 0) red_add_f32(cnt + d, 1.0f);
}

// ============================================================================
// combine (tf32 mma): out[128n x 128j] = sigmoid(concat(self, agg*invc) @ W + b)
// 8 warps = 4m x 2n; warp tile 32x64 (2 m16-frags x 8 n8-frags).
// K chunks of 32 in smem as tf32 hi/lo pairs (error-compensated: 3 mmas/tile).
// smem = 4 * 32*136*4 = 69,632 B -> 2 blocks/SM.
// ============================================================================
template<int K>
__global__ void __launch_bounds__(256, 2) combine_kernel(
    const float* __restrict__ self,   // [N, K/2]
    const float* __restrict__ agg,    // [N, K/2]
    const float* __restrict__ invc,   // [N]
    const float* __restrict__ W,      // [K, 128] row-major
    const float* __restrict__ b,      // [128]
    float* __restrict__ out,          // [N, 128]
    int nNodes)
{
    constexpr int SELF = K / 2;
    constexpr int NCH = K / 32;
    extern __shared__ float smf[];
    float* Xh = smf;
    float* Xl = Xh + 32 * KP;
    float* Wh = Xl + 32 * KP;
    float* Wl = Wh + 32 * KP;

    const int t = threadIdx.x;
    const int lane = t & 31, warp = t >> 5;
    const int wm = (warp & 3) * 32;   // node offset
    const int wn = (warp >> 2) * 64;  // out offset
    const int base = blockIdx.x * 128;
    const int ar = lane >> 2, ac = lane & 3;

    float4 C[2][8];
    #pragma unroll
    for (int nt = 0; nt < 8; ++nt) {
        int j = wn + nt * 8 + 2 * ac;
        float bx = b[j], by = b[j + 1];
        C[0][nt] = make_float4(bx, by, bx, by);
        C[1][nt] = make_float4(bx, by, bx, by);
    }

    for (int ch = 0; ch < NCH; ++ch) {
        __syncthreads();   // previous mainloop done reading tiles
        // ---- X chunk [32k][128n]: lanes (k=lane&3, n=lane>>2); STS conflict-free ----
        {
            int kloc = lane & 3, n8 = lane >> 2;
            #pragma unroll
            for (int it = 0; it < 16; ++it) {
                int k = kloc + 4 * (it & 7);
                int n = n8 + 8 * ((warp << 1) + (it >> 3));
                int kg = ch * 32 + k;
                int ngl = base + n;
                float v = 0.f;
                if (ngl < nNodes)
                    v = (kg < SELF) ? self[(size_t)ngl * SELF + kg]
                                    : agg[(size_t)ngl * SELF + (kg - SELF)] * invc[ngl];
                split_store(v, Xh + k * KP + n, Xl + k * KP + n);
            }
        }
        // ---- W chunk [32k][128j]: lanes (k=lane>>3, n=lane&7) ----
        {
            int k4w = lane >> 3, nn = lane & 7;
            #pragma unroll
            for (int it = 0; it < 16; ++it) {
                int k = k4w + 4 * (it & 7);
                int n = nn + 8 * ((warp << 1) + (it >> 3));
                float v = W[(size_t)(ch * 32 + k) * 128 + n];
                split_store(v, Wh + k * KP + n, Wl + k * KP + n);
            }
        }
        __syncthreads();
        // ---- 4 k8-steps ----
        #pragma unroll
        for (int s = 0; s < 4; ++s) {
            const int ko = s * 8;
            uint32_t Ah[2][4], Al[2][4];
            #pragma unroll
            for (int mt = 0; mt < 2; ++mt) {
                const float* ph = Xh + (ko + ac) * KP + wm + mt * 16 + ar;
                const float* pl = Xl + (ko + ac) * KP + wm + mt * 16 + ar;
                Ah[mt][0] = __float_as_uint(ph[0]);
                Ah[mt][1] = __float_as_uint(ph[8]);
                Ah[mt][2] = __float_as_uint(ph[4 * KP]);
                Ah[mt][3] = __float_as_uint(ph[4 * KP + 8]);
                Al[mt][0] = __float_as_uint(pl[0]);
                Al[mt][1] = __float_as_uint(pl[8]);
                Al[mt][2] = __float_as_uint(pl[4 * KP]);
                Al[mt][3] = __float_as_uint(pl[4 * KP + 8]);
            }
            #pragma unroll
            for (int nt = 0; nt < 8; ++nt) {
                const float* qh = Wh + (ko + ac) * KP + wn + nt * 8 + ar;
                const float* ql = Wl + (ko + ac) * KP + wn + nt * 8 + ar;
                uint32_t Bh[2] = { __float_as_uint(qh[0]), __float_as_uint(qh[4 * KP]) };
                uint32_t Bl[2] = { __float_as_uint(ql[0]), __float_as_uint(ql[4 * KP]) };
                mma_tf32(C[0][nt], Ah[0], Bh);
                mma_tf32(C[1][nt], Ah[1], Bh);
                mma_tf32(C[0][nt], Al[0], Bh);
                mma_tf32(C[1][nt], Al[1], Bh);
                mma_tf32(C[0][nt], Ah[0], Bl);
                mma_tf32(C[1][nt], Ah[1], Bl);
            }
        }
    }
    __syncthreads();   // tiles no longer needed; reuse smem as staging

    float* Rs = smf;   // [128 node][132]
    #pragma unroll
    for (int mt = 0; mt < 2; ++mt) {
        int row = wm + mt * 16 + ar;
        #pragma unroll
        for (int nt = 0; nt < 8; ++nt) {
            int col = wn + nt * 8 + 2 * ac;
            float4 c = C[mt][nt];
            *(float2*)(Rs + row * 132 + col)       = make_float2(sigmoidf_(c.x), sigmoidf_(c.y));
            *(float2*)(Rs + (row + 8) * 132 + col) = make_float2(sigmoidf_(c.z), sigmoidf_(c.w));
        }
    }
    __syncthreads();

    const float4* Rs4 = (const float4*)Rs;
    float4* out4 = (float4*)out;
    for (int i = t; i < 128 * 32; i += 256) {
        int n = i >> 5, q = i & 31;
        int ngl = base + n;
        if (ngl < nNodes) out4[(size_t)ngl * 32 + q] = Rs4[n * 33 + q];
    }
}

// ============================================================================
// mlp1 (tf32 mma): hmT[j][n] = relu(h2 @ Wm1 + bm1), j in [0,256), 2 N-passes.
// Same tiling as combine; output staged TRANSPOSED (Rs[j][node]) conflict-free.
// ============================================================================
__global__ void __launch_bounds__(256, 2) mlp1_kernel(
    const float* __restrict__ h2,     // [N, 128]
    const float* __restrict__ Wm1,    // [128, 256]
    const float* __restrict__ bm1,    // [256]
    float* __restrict__ hmT,          // [256][N]
    int nNodes)
{
    extern __shared__ float smf[];
    float* Xh = smf;
    float* Xl = Xh + 32 * KP;
    float* Wh = Xl + 32 * KP;
    float* Wl = Wh + 32 * KP;

    const int t = threadIdx.x;
    const int lane = t & 31, warp = t >> 5;
    const int wm = (warp & 3) * 32;
    const int wn = (warp >> 2) * 64;
    const int base = blockIdx.x * 128;
    const int ar = lane >> 2, ac = lane & 3;

    for (int pass = 0; pass < 2; ++pass) {
        float4 C[2][8];
        #pragma unroll
        for (int nt = 0; nt < 8; ++nt) {
            int j = pass * 128 + wn + nt * 8 + 2 * ac;
            float bx = bm1[j], by = bm1[j + 1];
            C[0][nt] = make_float4(bx, by, bx, by);
            C[1][nt] = make_float4(bx, by, bx, by);
        }

        for (int ch = 0; ch < 4; ++ch) {
            __syncthreads();
            {
                int kloc = lane & 3, n8 = lane >> 2;
                #pragma unroll
                for (int it = 0; it < 16; ++it) {
                    int k = kloc + 4 * (it & 7);
                    int n = n8 + 8 * ((warp << 1) + (it >> 3));
                    int ngl = base + n;
                    float v = (ngl < nNodes) ? h2[(size_t)ngl * 128 + ch * 32 + k] : 0.f;
                    split_store(v, Xh + k * KP + n, Xl + k * KP + n);
                }
            }
            {
                int k4w = lane >> 3, nn = lane & 7;
                #pragma unroll
                for (int it = 0; it < 16; ++it) {
                    int k = k4w + 4 * (it & 7);
                    int n = nn + 8 * ((warp << 1) + (it >> 3));
                    float v = Wm1[(size_t)(ch * 32 + k) * 256 + pass * 128 + n];
                    split_store(v, Wh + k * KP + n, Wl + k * KP + n);
                }
            }
            __syncthreads();
            #pragma unroll
            for (int s = 0; s < 4; ++s) {
                const int ko = s * 8;
                uint32_t Ah[2][4], Al[2][4];
                #pragma unroll
                for (int mt = 0; mt < 2; ++mt) {
                    const float* ph = Xh + (ko + ac) * KP + wm + mt * 16 + ar;
                    const float* pl = Xl + (ko + ac) * KP + wm + mt * 16 + ar;
                    Ah[mt][0] = __float_as_uint(ph[0]);
                    Ah[mt][1] = __float_as_uint(ph[8]);
                    Ah[mt][2] = __float_as_uint(ph[4 * KP]);
                    Ah[mt][3] = __float_as_uint(ph[4 * KP + 8]);
                    Al[mt][0] = __float_as_uint(pl[0]);
                    Al[mt][1] = __float_as_uint(pl[8]);
                    Al[mt][2] = __float_as_uint(pl[4 * KP]);
                    Al[mt][3] = __float_as_uint(pl[4 * KP + 8]);
                }
                #pragma unroll
                for (int nt = 0; nt < 8; ++nt) {
                    const float* qh = Wh + (ko + ac) * KP + wn + nt * 8 + ar;
                    const float* ql = Wl + (ko + ac) * KP + wn + nt * 8 + ar;
                    uint32_t Bh[2] = { __float_as_uint(qh[0]), __float_as_uint(qh[4 * KP]) };
                    uint32_t Bl[2] = { __float_as_uint(ql[0]), __float_as_uint(ql[4 * KP]) };
                    mma_tf32(C[0][nt], Ah[0], Bh);
                    mma_tf32(C[1][nt], Ah[1], Bh);
                    mma_tf32(C[0][nt], Al[0], Bh);
                    mma_tf32(C[1][nt], Al[1], Bh);
                    mma_tf32(C[0][nt], Ah[0], Bl);
                    mma_tf32(C[1][nt], Ah[1], Bl);
                }
            }
        }
        __syncthreads();   // tiles free; stage TRANSPOSED: Rs[j][node], stride 132

        float* Rs = smf;
        #pragma unroll
        for (int mt = 0; mt < 2; ++mt) {
            int row = wm + mt * 16 + ar;   // node
            #pragma unroll
            for (int nt = 0; nt < 8; ++nt) {
                int col = wn + nt * 8 + 2 * ac;   // j
                float4 c = C[mt][nt];
                Rs[col * 132 + row]             = fmaxf(c.x, 0.f);
                Rs[(col + 1) * 132 + row]       = fmaxf(c.y, 0.f);
                Rs[col * 132 + row + 8]         = fmaxf(c.z, 0.f);
                Rs[(col + 1) * 132 + row + 8]   = fmaxf(c.w, 0.f);
            }
        }
        __syncthreads();

        if (base + 128 <= nNodes) {
            const float4* Rs4 = (const float4*)Rs;
            for (int i = t; i < 128 * 32; i += 256) {
                int j = i >> 5, q = i & 31;
                *(float4*)(hmT + (size_t)(pass * 128 + j) * nNodes + base + 4 * q) = Rs4[j * 33 + q];
            }
        } else {
            for (int i = t; i < 128 * 128; i += 256) {
                int j = i >> 7, n = i & 127;
                if (base + n < nNodes)
                    hmT[(size_t)(pass * 128 + j) * nNodes + base + n] = Rs[j * 132 + n];
            }
        }
        __syncthreads();   // writeout reads done before next pass overwrites smem
    }
}

// ============================================================================
// mlp2: out = hmT^T @ Wm2 + bm2  (K=256, NOUT=40) — scalar path
// ============================================================================
__global__ void __launch_bounds__(256) mlp2_kernel(
    const float* __restrict__ hmT,    // [256][N]
    const float* __restrict__ Wm2,    // [256, 40]
    const float* __restrict__ bm2,    // [40]
    float* __restrict__ out,          // [N, 40]
    int nNodes)
{
    extern __shared__ float smf[];
    float* Ws = smf;                  // [256][40]
    float* Rs = smf + 256 * 40;       // [256][44]

    const int t = threadIdx.x;
    const int base = blockIdx.x * 256;
    const int ng = t & 63;
    const int og = t >> 6;
    const int n0 = base + ng * 4;
    const int j0 = og * 10;

    {
        const float4* Wg = (const float4*)Wm2;
        float4* Ws4 = (float4*)Ws;
        for (int i = t; i < 2560; i += 256) Ws4[i] = Wg[i];
    }
    __syncthreads();

    float4 acc[10];
    #pragma unroll
    for (int j = 0; j < 10; ++j) {
        float bv = bm2[j0 + j];
        acc[j] = make_float4(bv, bv, bv, bv);
    }

    if (n0 + 3 < nNodes) {
        #pragma unroll 2
        for (int k = 0; k < 256; ++k) {
            float4 x4 = *(const float4*)(hmT + (size_t)k * nNodes + n0);
            const float2* wr = (const float2*)(Ws + k * 40 + j0);
            float2 w0 = wr[0], w1 = wr[1], w2 = wr[2], w3 = wr[3], w4 = wr[4];
            fma4(acc[0], w0.x, x4); fma4(acc[1], w0.y, x4);
            fma4(acc[2], w1.x, x4); fma4(acc[3], w1.y, x4);
            fma4(acc[4], w2.x, x4); fma4(acc[5], w2.y, x4);
            fma4(acc[6], w3.x, x4); fma4(acc[7], w3.y, x4);
            fma4(acc[8], w4.x, x4); fma4(acc[9], w4.y, x4);
        }
    } else {
        for (int k = 0; k < 256; ++k) {
            float4 x4;
            const float* row = hmT + (size_t)k * nNodes;
            x4.x = (n0 + 0 < nNodes) ? row[n0 + 0] : 0.f;
            x4.y = (n0 + 1 < nNodes) ? row[n0 + 1] : 0.f;
            x4.z = (n0 + 2 < nNodes) ? row[n0 + 2] : 0.f;
            x4.w = (n0 + 3 < nNodes) ? row[n0 + 3] : 0.f;
            const float2* wr = (const float2*)(Ws + k * 40 + j0);
            float2 w0 = wr[0], w1 = wr[1], w2 = wr[2], w3 = wr[3], w4 = wr[4];
            fma4(acc[0], w0.x, x4); fma4(acc[1], w0.y, x4);
            fma4(acc[2], w1.x, x4); fma4(acc[3], w1.y, x4);
            fma4(acc[4], w2.x, x4); fma4(acc[5], w2.y, x4);
            fma4(acc[6], w3.x, x4); fma4(acc[7], w3.y, x4);
            fma4(acc[8], w4.x, x4); fma4(acc[9], w4.y, x4);
        }
    }

    int nl = ng * 4;
    #pragma unroll
    for (int j = 0; j < 10; ++j) {
        Rs[(nl + 0) * 44 + j0 + j] = acc[j].x;
        Rs[(nl + 1) * 44 + j0 + j] = acc[j].y;
        Rs[(nl + 2) * 44 + j0 + j] = acc[j].z;
        Rs[(nl + 3) * 44 + j0 + j] = acc[j].w;
    }
    __syncthreads();

    const float4* Rs4 = (const float4*)Rs;
    float4* out4 = (float4*)out;
    for (int i = t; i < 256 * 10; i += 256) {
        int n = i / 10, q = i - n * 10;
        int ngl = base + n;
        if (ngl < nNodes) out4[(size_t)ngl * 10 + q] = Rs4[n * 11 + q];
    }
}

// -------- launch --------
extern "C" void kernel_launch(void* const* d_in, const int* in_sizes, int n_in,
                              void* d_out, int out_size)
{
    const float* feat = (const float*)d_in[0];
    const int*   ei   = (const int*)d_in[1];     // int32 (JAX x64 disabled)
    const float* W1  = (const float*)d_in[2];
    const float* b1  = (const float*)d_in[3];
    const float* W2  = (const float*)d_in[4];
    const float* b2  = (const float*)d_in[5];
    const float* Wm1 = (const float*)d_in[6];
    const float* bm1 = (const float*)d_in[7];
    const float* Wm2 = (const float*)d_in[8];
    const float* bm2 = (const float*)d_in[9];
    float* out = (float*)d_out;

    const int N = in_sizes[0] / 64;     // 100000
    const int E = in_sizes[1] / 2;      // 1600000

    float *agg, *cnt, *h1, *h2, *hmT;
    cudaGetSymbolAddress((void**)&agg, g_agg);
    cudaGetSymbolAddress((void**)&cnt, g_cnt);
    cudaGetSymbolAddress((void**)&h1,  g_h1);
    cudaGetSymbolAddress((void**)&h2,  g_h2);
    cudaGetSymbolAddress((void**)&hmT, g_hmT);

    const int SM_GEMM = 4 * 32 * KP * 4;            // 69,632 B -> 2 blocks/SM
    const int SM_MLP2 = (256 * 40 + 256 * 44) * 4;  // 86,016 B
    cudaFuncSetAttribute(combine_kernel<128>, cudaFuncAttributeMaxDynamicSharedMemorySize, SM_GEMM);
    cudaFuncSetAttribute(combine_kernel<256>, cudaFuncAttributeMaxDynamicSharedMemorySize, SM_GEMM);
    cudaFuncSetAttribute(mlp1_kernel,         cudaFuncAttributeMaxDynamicSharedMemorySize, SM_GEMM);
    cudaFuncSetAttribute(mlp2_kernel,         cudaFuncAttributeMaxDynamicSharedMemorySize, SM_MLP2);

    const int nodeBlocks = (N + 127) / 128;      // 782
    const int mlp2Blocks = (N + 255) / 256;      // 391

    // Layer 1   (launch order keeps combine<128> at profiler capture slot)
    {
        zero2_kernel<<<4096, 256>>>((float4*)agg, (N * 64) / 4, (float4*)cnt, N / 4);
        long long tot = (long long)E * 4;
        int blocks = (int)((tot + 255) / 256);
        scatter_kernel<64><<<blocks, 256>>>(ei, feat, agg, cnt, E, N, 1);
        invcnt_kernel<<<(N + 255) / 256, 256>>>(cnt, N);
        combine_kernel<128><<<nodeBlocks, 256, SM_GEMM>>>(feat, agg, cnt, W1, b1, h1, N);
    }
    // Layer 2
    {
        zero2_kernel<<<4096, 256>>>((float4*)agg, (N * 128) / 4, (float4*)0, 0);
        long long tot = (long long)E * 8;
        int blocks = (int)((tot + 255) / 256);
        scatter_kernel<128><<<blocks, 256>>>(ei, h1, agg, cnt, E, N, 0);
        combine_kernel<256><<<nodeBlocks, 256, SM_GEMM>>>(h1, agg, cnt, W2, b2, h2, N);
    }
    // MLP
    mlp1_kernel<<<nodeBlocks, 256, SM_GEMM>>>(h2, Wm1, bm1, hmT, N);
    mlp2_kernel<<<mlp2Blocks, 256, SM_MLP2>>>(hmT, Wm2, bm2, out, N);
}

// round 10
// speedup vs baseline: 1.3186x; 1.1037x over previous
#include <cuda_runtime.h>
#include <math.h>
#include <stdint.h>

#define NN 100000
#define EE 1600000
#define KP 136    // split-tile row stride (floats): conflict-free frag loads
#define XRS 36    // raw X tile row stride (floats)

// -------- scratch (device globals; no allocation allowed) --------
__device__ float g_cnt[NN];
__device__ float g_agg[(size_t)NN * 128];
__device__ float g_h1[(size_t)NN * 128];
__device__ float g_h2[(size_t)NN * 128];
__device__ float g_hmT[(size_t)NN * 256];   // hidden MLP layer, TRANSPOSED [256][N]
__device__ float g_wh[81920];               // tf32-hi of [W1|W2|Wm1]
__device__ float g_wl[81920];               // tf32-lo of [W1|W2|Wm1]

// -------- helpers --------
__device__ __forceinline__ void red_add_v4(float* addr, float4 v) {
    asm volatile("red.global.add.v4.f32 [%0], {%1,%2,%3,%4};"
                 :: "l"(addr), "f"(v.x), "f"(v.y), "f"(v.z), "f"(v.w) : "memory");
}
__device__ __forceinline__ void red_add_f32(float* addr, float v) {
    asm volatile("red.global.add.f32 [%0], %1;" :: "l"(addr), "f"(v) : "memory");
}
__device__ __forceinline__ float sigmoidf_(float x) {
    return 1.0f / (1.0f + __expf(-x));
}
__device__ __forceinline__ void fma4(float4& a, float s, const float4& x) {
    a.x = fmaf(s, x.x, a.x); a.y = fmaf(s, x.y, a.y);
    a.z = fmaf(s, x.z, a.z); a.w = fmaf(s, x.w, a.w);
}
__device__ __forceinline__ uint32_t f2tf(float x) {
    uint32_t r;
    asm("cvt.rna.tf32.f32 %0, %1;" : "=r"(r) : "f"(x));
    return r;
}
__device__ __forceinline__ void mma_tf32(float4& d, const uint32_t* a, const uint32_t* b) {
    asm("mma.sync.aligned.m16n8k8.row.col.f32.tf32.tf32.f32 "
        "{%0,%1,%2,%3}, {%4,%5,%6,%7}, {%8,%9}, {%0,%1,%2,%3};"
        : "+f"(d.x), "+f"(d.y), "+f"(d.z), "+f"(d.w)
        : "r"(a[0]), "r"(a[1]), "r"(a[2]), "r"(a[3]), "r"(b[0]), "r"(b[1]));
}
__device__ __forceinline__ void split_store(float v, float* ph, float* pl) {
    uint32_t hb = f2tf(v);
    float hi = __uint_as_float(hb);
    *ph = hi;
    *pl = __uint_as_float(f2tf(v - hi));
}
__device__ __forceinline__ void cpasync16(uint32_t dst, const void* src, int srcsize) {
    asm volatile("cp.async.ca.shared.global [%0], [%1], 16, %2;"
                 :: "r"(dst), "l"(src), "r"(srcsize) : "memory");
}
#define CP_COMMIT() asm volatile("cp.async.commit_group;" ::: "memory")
#define CP_WAIT0()  asm volatile("cp.async.wait_group 0;" ::: "memory")

// -------- prep: zero agg+cnt AND pre-split weights to tf32 hi/lo --------
__global__ void prep1_kernel(float4* __restrict__ agg4, int n4a,
                             float4* __restrict__ cnt4, int n4c,
                             const float* __restrict__ W1,
                             const float* __restrict__ W2,
                             const float* __restrict__ Wm1,
                             float* __restrict__ wh, float* __restrict__ wl)
{
    int idx = blockIdx.x * blockDim.x + threadIdx.x;
    int stride = gridDim.x * blockDim.x;
    float4 z = make_float4(0.f, 0.f, 0.f, 0.f);
    for (int i = idx; i < n4a; i += stride) agg4[i] = z;
    for (int i = idx; i < n4c; i += stride) cnt4[i] = z;
    for (int i = idx; i < 81920; i += stride) {
        float v;
        if (i < 16384)      v = W1[i];
        else if (i < 49152) v = W2[i - 16384];
        else                v = Wm1[i - 49152];
        uint32_t hb = f2tf(v);
        float hi = __uint_as_float(hb);
        wh[i] = hi;
        wl[i] = __uint_as_float(f2tf(v - hi));
    }
}

// -------- zero --------
__global__ void zero_kernel(float4* __restrict__ p, int n4) {
    int i = blockIdx.x * blockDim.x + threadIdx.x;
    int stride = gridDim.x * blockDim.x;
    float4 z = make_float4(0.f, 0.f, 0.f, 0.f);
    for (; i < n4; i += stride) p[i] = z;
}

// -------- cnt -> 1/max(cnt,1) --------
__global__ void invcnt_kernel(float* __restrict__ cnt, int n) {
    int i = blockIdx.x * blockDim.x + threadIdx.x;
    if (i < n) cnt[i] = 1.0f / fmaxf(cnt[i], 1.0f);
}

// -------- edge scatter: per-thread = (edge, 16-float chunk); edge_index is int32 --------
template<int D>
__global__ void __launch_bounds__(256) scatter_kernel(
    const int* __restrict__ ei,         // [2, E] int32
    const float* __restrict__ x,        // [N, D]
    float* __restrict__ agg,            // [N, D]
    float* __restrict__ cnt,            // [N]
    int E, int nNodes, int doCnt)
{
    const int CH = D / 16;
    long long tid = (long long)blockIdx.x * blockDim.x + threadIdx.x;
    long long e = tid / CH;
    int c = (int)(tid - e * CH);
    if (e >= E) return;
    int s = ei[e];
    int d = ei[(long long)E + e];
    if ((unsigned)s >= (unsigned)nNodes || (unsigned)d >= (unsigned)nNodes) return;
    const float4* src = (const float4*)(x + (size_t)s * D + c * 16);
    float* dst = agg + (size_t)d * D + c * 16;
    float4 a = src[0], b = src[1], cc = src[2], dd = src[3];
    red_add_v4(dst + 0, a);
    red_add_v4(dst + 4, b);
    red_add_v4(dst + 8, cc);
    red_add_v4(dst + 12, dd);
    if (doCnt && c == 0) red_add_f32(cnt + d, 1.0f);
}

// smem float offsets (shared by combine / mlp1)
#define OF_XH 0
#define OF_XL 4352
#define OF_WH 8704
#define OF_WL 13056
#define OF_XR 17408            // 128 x XRS raw X
#define OF_IC 22016            // 128 invc values
#define SMF_TOTAL 22144        // floats -> 88,576 B

// ============================================================================
// combine (tf32 mma, cp.async-pipelined):
// out[128n x 128j] = sigmoid(concat(self, agg*invc) @ W + b)
// W pre-split in global (whG/wlG). X raw chunk prefetched one ahead into Xr.
// ============================================================================
template<int K>
__global__ void __launch_bounds__(256, 2) combine_kernel(
    const float* __restrict__ self,   // [N, K/2]
    const float* __restrict__ agg,    // [N, K/2]
    const float* __restrict__ invc,   // [N]
    const float* __restrict__ whG,    // [K][128] tf32-hi
    const float* __restrict__ wlG,    // [K][128] tf32-lo
    const float* __restrict__ b,      // [128]
    float* __restrict__ out,          // [N, 128]
    int nNodes)
{
    constexpr int SELF = K / 2;
    constexpr int NCH = K / 32;
    extern __shared__ float smf[];
    float* Xh = smf + OF_XH;
    float* Xl = smf + OF_XL;
    float* Wh = smf + OF_WH;
    float* Wl = smf + OF_WL;
    float* Xr = smf + OF_XR;
    float* invcS = smf + OF_IC;
    const uint32_t xrAddr = (uint32_t)__cvta_generic_to_shared(Xr);

    const int t = threadIdx.x;
    const int lane = t & 31, warp = t >> 5;
    const int wm = (warp & 3) * 32;
    const int wn = (warp >> 2) * 64;
    const int base = blockIdx.x * 128;
    const int ar = lane >> 2, ac = lane & 3;

    if (t < 128) invcS[t] = (base + t < nNodes) ? invc[base + t] : 1.0f;

    float4 C[2][8];
    #pragma unroll
    for (int nt = 0; nt < 8; ++nt) {
        int j = wn + nt * 8 + 2 * ac;
        float bx = b[j], by = b[j + 1];
        C[0][nt] = make_float4(bx, by, bx, by);
        C[1][nt] = make_float4(bx, by, bx, by);
    }

    // ---- prefetch helper (chunk ch: 32 k's; region uniform per chunk) ----
    auto prefetch = [&](int ch) {
        int g = t & 7;
        int kg = ch * 32 + g * 4;
        const float* src0 = (kg < SELF) ? (self + kg) : (agg + (kg - SELF));
        #pragma unroll
        for (int it = 0; it < 4; ++it) {
            int n = (t >> 3) + 32 * it;
            int ngl = base + n;
            int sz = (ngl < nNodes) ? 16 : 0;
            cpasync16(xrAddr + (uint32_t)(n * XRS + g * 4) * 4,
                      src0 + (size_t)ngl * SELF, sz);
        }
    };

    prefetch(0); CP_COMMIT(); CP_WAIT0();

    for (int ch = 0; ch < NCH; ++ch) {
        __syncthreads();   // prev mainloop done with tiles; Xr data visible
        // ---- split X chunk from Xr (LDS, conflict-free) ----
        {
            const bool isAgg = (ch >= SELF / 32);
            int kloc = lane & 3, n8 = lane >> 2;
            #pragma unroll
            for (int it = 0; it < 16; ++it) {
                int k = kloc + 4 * (it & 7);
                int n = n8 + 8 * ((warp << 1) + (it >> 3));
                float v = Xr[n * XRS + k];
                if (isAgg) v *= invcS[n];
                split_store(v, Xh + k * KP + n, Xl + k * KP + n);
            }
        }
        // ---- copy pre-split W chunk (plain float4, L2-hot) ----
        {
            const float4* WhG4 = (const float4*)whG;
            const float4* WlG4 = (const float4*)wlG;
            for (int i = t; i < 1024; i += 256) {
                int k = i >> 5, q = i & 31;
                ((float4*)(Wh + k * KP))[q] = WhG4[(ch * 32 + k) * 32 + q];
                ((float4*)(Wl + k * KP))[q] = WlG4[(ch * 32 + k) * 32 + q];
            }
        }
        __syncthreads();
        if (ch + 1 < NCH) { prefetch(ch + 1); CP_COMMIT(); }
        // ---- mainloop: 4 k8-steps ----
        #pragma unroll
        for (int s = 0; s < 4; ++s) {
            const int ko = s * 8;
            uint32_t Ah[2][4], Al[2][4];
            #pragma unroll
            for (int mt = 0; mt < 2; ++mt) {
                const float* ph = Xh + (ko + ac) * KP + wm + mt * 16 + ar;
                const float* pl = Xl + (ko + ac) * KP + wm + mt * 16 + ar;
                Ah[mt][0] = __float_as_uint(ph[0]);
                Ah[mt][1] = __float_as_uint(ph[8]);
                Ah[mt][2] = __float_as_uint(ph[4 * KP]);
                Ah[mt][3] = __float_as_uint(ph[4 * KP + 8]);
                Al[mt][0] = __float_as_uint(pl[0]);
                Al[mt][1] = __float_as_uint(pl[8]);
                Al[mt][2] = __float_as_uint(pl[4 * KP]);
                Al[mt][3] = __float_as_uint(pl[4 * KP + 8]);
            }
            #pragma unroll
            for (int nt = 0; nt < 8; ++nt) {
                const float* qh = Wh + (ko + ac) * KP + wn + nt * 8 + ar;
                const float* ql = Wl + (ko + ac) * KP + wn + nt * 8 + ar;
                uint32_t Bh[2] = { __float_as_uint(qh[0]), __float_as_uint(qh[4 * KP]) };
                uint32_t Bl[2] = { __float_as_uint(ql[0]), __float_as_uint(ql[4 * KP]) };
                mma_tf32(C[0][nt], Ah[0], Bh);
                mma_tf32(C[1][nt], Ah[1], Bh);
                mma_tf32(C[0][nt], Al[0], Bh);
                mma_tf32(C[1][nt], Al[1], Bh);
                mma_tf32(C[0][nt], Ah[0], Bl);
                mma_tf32(C[1][nt], Ah[1], Bl);
            }
        }
        if (ch + 1 < NCH) CP_WAIT0();
    }
    __syncthreads();   // tiles free; reuse as staging (does NOT overlap Xr)

    float* Rs = smf;   // [128 node][132]
    #pragma unroll
    for (int mt = 0; mt < 2; ++mt) {
        int row = wm + mt * 16 + ar;
        #pragma unroll
        for (int nt = 0; nt < 8; ++nt) {
            int col = wn + nt * 8 + 2 * ac;
            float4 c = C[mt][nt];
            *(float2*)(Rs + row * 132 + col)       = make_float2(sigmoidf_(c.x), sigmoidf_(c.y));
            *(float2*)(Rs + (row + 8) * 132 + col) = make_float2(sigmoidf_(c.z), sigmoidf_(c.w));
        }
    }
    __syncthreads();

    const float4* Rs4 = (const float4*)Rs;
    float4* out4 = (float4*)out;
    for (int i = t; i < 128 * 32; i += 256) {
        int n = i >> 5, q = i & 31;
        int ngl = base + n;
        if (ngl < nNodes) out4[(size_t)ngl * 32 + q] = Rs4[n * 33 + q];
    }
}

// ============================================================================
// mlp1 (tf32 mma, cp.async-pipelined): hmT[j][n] = relu(h2 @ Wm1 + bm1)
// 8 iterations = 2 passes x 4 K-chunks; epilogue per pass (transposed staging).
// ============================================================================
__global__ void __launch_bounds__(256, 2) mlp1_kernel(
    const float* __restrict__ h2,     // [N, 128]
    const float* __restrict__ whG,    // Wm1 tf32-hi [128][256]
    const float* __restrict__ wlG,    // Wm1 tf32-lo
    const float* __restrict__ bm1,    // [256]
    float* __restrict__ hmT,          // [256][N]
    int nNodes)
{
    extern __shared__ float smf[];
    float* Xh = smf + OF_XH;
    float* Xl = smf + OF_XL;
    float* Wh = smf + OF_WH;
    float* Wl = smf + OF_WL;
    float* Xr = smf + OF_XR;
    const uint32_t xrAddr = (uint32_t)__cvta_generic_to_shared(Xr);

    const int t = threadIdx.x;
    const int lane = t & 31, warp = t >> 5;
    const int wm = (warp & 3) * 32;
    const int wn = (warp >> 2) * 64;
    const int base = blockIdx.x * 128;
    const int ar = lane >> 2, ac = lane & 3;

    auto prefetch = [&](int ch) {
        int g = t & 7;
        int col = ch * 32 + g * 4;
        #pragma unroll
        for (int it = 0; it < 4; ++it) {
            int n = (t >> 3) + 32 * it;
            int ngl = base + n;
            int sz = (ngl < nNodes) ? 16 : 0;
            cpasync16(xrAddr + (uint32_t)(n * XRS + g * 4) * 4,
                      h2 + (size_t)ngl * 128 + col, sz);
        }
    };

    prefetch(0); CP_COMMIT(); CP_WAIT0();

    float4 C[2][8];
    for (int it8 = 0; it8 < 8; ++it8) {
        const int ch = it8 & 3, pass = it8 >> 2;
        if (ch == 0) {
            #pragma unroll
            for (int nt = 0; nt < 8; ++nt) {
                int j = pass * 128 + wn + nt * 8 + 2 * ac;
                float bx = bm1[j], by = bm1[j + 1];
                C[0][nt] = make_float4(bx, by, bx, by);
                C[1][nt] = make_float4(bx, by, bx, by);
            }
        }
        __syncthreads();
        {
            int kloc = lane & 3, n8 = lane >> 2;
            #pragma unroll
            for (int it = 0; it < 16; ++it) {
                int k = kloc + 4 * (it & 7);
                int n = n8 + 8 * ((warp << 1) + (it >> 3));
                float v = Xr[n * XRS + k];
                split_store(v, Xh + k * KP + n, Xl + k * KP + n);
            }
        }
        {
            const float4* WhG4 = (const float4*)whG;
            const float4* WlG4 = (const float4*)wlG;
            for (int i = t; i < 1024; i += 256) {
                int k = i >> 5, q = i & 31;
                int srci = (ch * 32 + k) * 64 + pass * 32 + q;
                ((float4*)(Wh + k * KP))[q] = WhG4[srci];
                ((float4*)(Wl + k * KP))[q] = WlG4[srci];
            }
        }
        __syncthreads();
        if (it8 + 1 < 8) { prefetch((it8 + 1) & 3); CP_COMMIT(); }
        #pragma unroll
        for (int s = 0; s < 4; ++s) {
            const int ko = s * 8;
            uint32_t Ah[2][4], Al[2][4];
            #pragma unroll
            for (int mt = 0; mt < 2; ++mt) {
                const float* ph = Xh + (ko + ac) * KP + wm + mt * 16 + ar;
                const float* pl = Xl + (ko + ac) * KP + wm + mt * 16 + ar;
                Ah[mt][0] = __float_as_uint(ph[0]);
                Ah[mt][1] = __float_as_uint(ph[8]);
                Ah[mt][2] = __float_as_uint(ph[4 * KP]);
                Ah[mt][3] = __float_as_uint(ph[4 * KP + 8]);
                Al[mt][0] = __float_as_uint(pl[0]);
                Al[mt][1] = __float_as_uint(pl[8]);
                Al[mt][2] = __float_as_uint(pl[4 * KP]);
                Al[mt][3] = __float_as_uint(pl[4 * KP + 8]);
            }
            #pragma unroll
            for (int nt = 0; nt < 8; ++nt) {
                const float* qh = Wh + (ko + ac) * KP + wn + nt * 8 + ar;
                const float* ql = Wl + (ko + ac) * KP + wn + nt * 8 + ar;
                uint32_t Bh[2] = { __float_as_uint(qh[0]), __float_as_uint(qh[4 * KP]) };
                uint32_t Bl[2] = { __float_as_uint(ql[0]), __float_as_uint(ql[4 * KP]) };
                mma_tf32(C[0][nt], Ah[0], Bh);
                mma_tf32(C[1][nt], Ah[1], Bh);
                mma_tf32(C[0][nt], Al[0], Bh);
                mma_tf32(C[1][nt], Al[1], Bh);
                mma_tf32(C[0][nt], Ah[0], Bl);
                mma_tf32(C[1][nt], Ah[1], Bl);
            }
        }
        if (it8 + 1 < 8) CP_WAIT0();

        if (ch == 3) {   // pass epilogue
            __syncthreads();   // all warps done reading tiles
            float* Rs = smf;   // [128 j][132] transposed staging (no Xr overlap)
            #pragma unroll
            for (int mt = 0; mt < 2; ++mt) {
                int row = wm + mt * 16 + ar;   // node
                #pragma unroll
                for (int nt = 0; nt < 8; ++nt) {
                    int col = wn + nt * 8 + 2 * ac;   // j
                    float4 c = C[mt][nt];
                    Rs[col * 132 + row]           = fmaxf(c.x, 0.f);
                    Rs[(col + 1) * 132 + row]     = fmaxf(c.y, 0.f);
                    Rs[col * 132 + row + 8]       = fmaxf(c.z, 0.f);
                    Rs[(col + 1) * 132 + row + 8] = fmaxf(c.w, 0.f);
                }
            }
            __syncthreads();
            if (base + 128 <= nNodes) {
                const float4* Rs4 = (const float4*)Rs;
                for (int i = t; i < 128 * 32; i += 256) {
                    int j = i >> 5, q = i & 31;
                    *(float4*)(hmT + (size_t)(pass * 128 + j) * nNodes + base + 4 * q) = Rs4[j * 33 + q];
                }
            } else {
                for (int i = t; i < 128 * 128; i += 256) {
                    int j = i >> 7, n = i & 127;
                    if (base + n < nNodes)
                        hmT[(size_t)(pass * 128 + j) * nNodes + base + n] = Rs[j * 132 + n];
                }
            }
            // next iteration's entering __syncthreads protects Rs before split overwrites
        }
    }
}

// ============================================================================
// mlp2: out = hmT^T @ Wm2 + bm2  (K=256, NOUT=40) — scalar path
// ============================================================================
__global__ void __launch_bounds__(256) mlp2_kernel(
    const float* __restrict__ hmT,    // [256][N]
    const float* __restrict__ Wm2,    // [256, 40]
    const float* __restrict__ bm2,    // [40]
    float* __restrict__ out,          // [N, 40]
    int nNodes)
{
    extern __shared__ float smf[];
    float* Ws = smf;                  // [256][40]
    float* Rs = smf + 256 * 40;       // [256][44]

    const int t = threadIdx.x;
    const int base = blockIdx.x * 256;
    const int ng = t & 63;
    const int og = t >> 6;
    const int n0 = base + ng * 4;
    const int j0 = og * 10;

    {
        const float4* Wg = (const float4*)Wm2;
        float4* Ws4 = (float4*)Ws;
        for (int i = t; i < 2560; i += 256) Ws4[i] = Wg[i];
    }
    __syncthreads();

    float4 acc[10];
    #pragma unroll
    for (int j = 0; j < 10; ++j) {
        float bv = bm2[j0 + j];
        acc[j] = make_float4(bv, bv, bv, bv);
    }

    if (n0 + 3 < nNodes) {
        #pragma unroll 2
        for (int k = 0; k < 256; ++k) {
            float4 x4 = *(const float4*)(hmT + (size_t)k * nNodes + n0);
            const float2* wr = (const float2*)(Ws + k * 40 + j0);
            float2 w0 = wr[0], w1 = wr[1], w2 = wr[2], w3 = wr[3], w4 = wr[4];
            fma4(acc[0], w0.x, x4); fma4(acc[1], w0.y, x4);
            fma4(acc[2], w1.x, x4); fma4(acc[3], w1.y, x4);
            fma4(acc[4], w2.x, x4); fma4(acc[5], w2.y, x4);
            fma4(acc[6], w3.x, x4); fma4(acc[7], w3.y, x4);
            fma4(acc[8], w4.x, x4); fma4(acc[9], w4.y, x4);
        }
    } else {
        for (int k = 0; k < 256; ++k) {
            float4 x4;
            const float* row = hmT + (size_t)k * nNodes;
            x4.x = (n0 + 0 < nNodes) ? row[n0 + 0] : 0.f;
            x4.y = (n0 + 1 < nNodes) ? row[n0 + 1] : 0.f;
            x4.z = (n0 + 2 < nNodes) ? row[n0 + 2] : 0.f;
            x4.w = (n0 + 3 < nNodes) ? row[n0 + 3] : 0.f;
            const float2* wr = (const float2*)(Ws + k * 40 + j0);
            float2 w0 = wr[0], w1 = wr[1], w2 = wr[2], w3 = wr[3], w4 = wr[4];
            fma4(acc[0], w0.x, x4); fma4(acc[1], w0.y, x4);
            fma4(acc[2], w1.x, x4); fma4(acc[3], w1.y, x4);
            fma4(acc[4], w2.x, x4); fma4(acc[5], w2.y, x4);
            fma4(acc[6], w3.x, x4); fma4(acc[7], w3.y, x4);
            fma4(acc[8], w4.x, x4); fma4(acc[9], w4.y, x4);
        }
    }

    int nl = ng * 4;
    #pragma unroll
    for (int j = 0; j < 10; ++j) {
        Rs[(nl + 0) * 44 + j0 + j] = acc[j].x;
        Rs[(nl + 1) * 44 + j0 + j] = acc[j].y;
        Rs[(nl + 2) * 44 + j0 + j] = acc[j].z;
        Rs[(nl + 3) * 44 + j0 + j] = acc[j].w;
    }
    __syncthreads();

    const float4* Rs4 = (const float4*)Rs;
    float4* out4 = (float4*)out;
    for (int i = t; i < 256 * 10; i += 256) {
        int n = i / 10, q = i - n * 10;
        int ngl = base + n;
        if (ngl < nNodes) out4[(size_t)ngl * 10 + q] = Rs4[n * 11 + q];
    }
}

// -------- launch --------
extern "C" void kernel_launch(void* const* d_in, const int* in_sizes, int n_in,
                              void* d_out, int out_size)
{
    const float* feat = (const float*)d_in[0];
    const int*   ei   = (const int*)d_in[1];     // int32 (JAX x64 disabled)
    const float* W1  = (const float*)d_in[2];
    const float* b1  = (const float*)d_in[3];
    const float* W2  = (const float*)d_in[4];
    const float* b2  = (const float*)d_in[5];
    const float* Wm1 = (const float*)d_in[6];
    const float* bm1 = (const float*)d_in[7];
    const float* Wm2 = (const float*)d_in[8];
    const float* bm2 = (const float*)d_in[9];
    float* out = (float*)d_out;

    const int N = in_sizes[0] / 64;     // 100000
    const int E = in_sizes[1] / 2;      // 1600000

    float *agg, *cnt, *h1, *h2, *hmT, *wh, *wl;
    cudaGetSymbolAddress((void**)&agg, g_agg);
    cudaGetSymbolAddress((void**)&cnt, g_cnt);
    cudaGetSymbolAddress((void**)&h1,  g_h1);
    cudaGetSymbolAddress((void**)&h2,  g_h2);
    cudaGetSymbolAddress((void**)&hmT, g_hmT);
    cudaGetSymbolAddress((void**)&wh,  g_wh);
    cudaGetSymbolAddress((void**)&wl,  g_wl);

    const int SM_GEMM = SMF_TOTAL * 4;              // 88,576 B -> 2 blocks/SM
    const int SM_MLP2 = (256 * 40 + 256 * 44) * 4;  // 86,016 B
    cudaFuncSetAttribute(combine_kernel<128>, cudaFuncAttributeMaxDynamicSharedMemorySize, SM_GEMM);
    cudaFuncSetAttribute(combine_kernel<256>, cudaFuncAttributeMaxDynamicSharedMemorySize, SM_GEMM);
    cudaFuncSetAttribute(mlp1_kernel,         cudaFuncAttributeMaxDynamicSharedMemorySize, SM_GEMM);
    cudaFuncSetAttribute(mlp2_kernel,         cudaFuncAttributeMaxDynamicSharedMemorySize, SM_MLP2);

    const int nodeBlocks = (N + 127) / 128;      // 782
    const int mlp2Blocks = (N + 255) / 256;      // 391

    // Layer 1   (prep also pre-splits W1/W2/Wm1; launch count/order preserved)
    {
        prep1_kernel<<<4096, 256>>>((float4*)agg, (N * 64) / 4, (float4*)cnt, N / 4,
                                    W1, W2, Wm1, wh, wl);
        long long tot = (long long)E * 4;
        int blocks = (int)((tot + 255) / 256);
        scatter_kernel<64><<<blocks, 256>>>(ei, feat, agg, cnt, E, N, 1);
        invcnt_kernel<<<(N + 255) / 256, 256>>>(cnt, N);
        combine_kernel<128><<<nodeBlocks, 256, SM_GEMM>>>(feat, agg, cnt, wh, wl, b1, h1, N);
    }
    // Layer 2
    {
        zero_kernel<<<4096, 256>>>((float4*)agg, (N * 128) / 4);
        long long tot = (long long)E * 8;
        int blocks = (int)((tot + 255) / 256);
        scatter_kernel<128><<<blocks, 256>>>(ei, h1, agg, cnt, E, N, 0);
        combine_kernel<256><<<nodeBlocks, 256, SM_GEMM>>>(h1, agg, cnt, wh + 16384, wl + 16384, b2, h2, N);
    }
    // MLP
    mlp1_kernel<<<nodeBlocks, 256, SM_GEMM>>>(h2, wh + 49152, wl + 49152, bm1, hmT, N);
    mlp2_kernel<<<mlp2Blocks, 256, SM_MLP2>>>(hmT, Wm2, bm2, out, N);
}

// round 11
// speedup vs baseline: 1.8164x; 1.3775x over previous
#include <cuda_runtime.h>
#include <math.h>
#include <stdint.h>

#define NN 100000
#define EE 1600000
#define KP 136    // split-tile row stride (floats): conflict-free frag loads
#define XRS 36    // raw X tile row stride (floats)

// -------- scratch (device globals; no allocation allowed) --------
__device__ float g_agg[(size_t)NN * 128];
__device__ float g_h1[(size_t)NN * 128];
__device__ float g_h2[(size_t)NN * 128];
__device__ float g_hmT[(size_t)NN * 256];   // hidden MLP layer, TRANSPOSED [256][N]
__device__ float g_wh[81920];               // tf32-hi of [W1|W2|Wm1]
__device__ float g_wl[81920];               // tf32-lo of [W1|W2|Wm1]
__device__ int   g_deg[NN];
__device__ int   g_off[NN];
__device__ int   g_cur[NN];
__device__ int   g_csr[EE];
__device__ int   g_bsum[512];

// -------- helpers --------
__device__ __forceinline__ float sigmoidf_(float x) {
    return 1.0f / (1.0f + __expf(-x));
}
__device__ __forceinline__ void fma4(float4& a, float s, const float4& x) {
    a.x = fmaf(s, x.x, a.x); a.y = fmaf(s, x.y, a.y);
    a.z = fmaf(s, x.z, a.z); a.w = fmaf(s, x.w, a.w);
}
__device__ __forceinline__ uint32_t f2tf(float x) {
    uint32_t r;
    asm("cvt.rna.tf32.f32 %0, %1;" : "=r"(r) : "f"(x));
    return r;
}
__device__ __forceinline__ void mma_tf32(float4& d, const uint32_t* a, const uint32_t* b) {
    asm("mma.sync.aligned.m16n8k8.row.col.f32.tf32.tf32.f32 "
        "{%0,%1,%2,%3}, {%4,%5,%6,%7}, {%8,%9}, {%0,%1,%2,%3};"
        : "+f"(d.x), "+f"(d.y), "+f"(d.z), "+f"(d.w)
        : "r"(a[0]), "r"(a[1]), "r"(a[2]), "r"(a[3]), "r"(b[0]), "r"(b[1]));
}
__device__ __forceinline__ void split_store(float v, float* ph, float* pl) {
    uint32_t hb = f2tf(v);
    float hi = __uint_as_float(hb);
    *ph = hi;
    *pl = __uint_as_float(f2tf(v - hi));
}
__device__ __forceinline__ void cpasync16(uint32_t dst, const void* src, int srcsize) {
    asm volatile("cp.async.ca.shared.global [%0], [%1], 16, %2;"
                 :: "r"(dst), "l"(src), "r"(srcsize) : "memory");
}
#define CP_COMMIT() asm volatile("cp.async.commit_group;" ::: "memory")
#define CP_WAIT0()  asm volatile("cp.async.wait_group 0;" ::: "memory")

// -------- prep: zero deg AND pre-split weights to tf32 hi/lo --------
__global__ void prep1_kernel(int* __restrict__ deg, int n,
                             const float* __restrict__ W1,
                             const float* __restrict__ W2,
                             const float* __restrict__ Wm1,
                             float* __restrict__ wh, float* __restrict__ wl)
{
    int idx = blockIdx.x * blockDim.x + threadIdx.x;
    int stride = gridDim.x * blockDim.x;
    for (int i = idx; i < n; i += stride) deg[i] = 0;
    for (int i = idx; i < 81920; i += stride) {
        float v;
        if (i < 16384)      v = W1[i];
        else if (i < 49152) v = W2[i - 16384];
        else                v = Wm1[i - 49152];
        uint32_t hb = f2tf(v);
        float hi = __uint_as_float(hb);
        wh[i] = hi;
        wl[i] = __uint_as_float(f2tf(v - hi));
    }
}

// -------- CSR build: histogram over dst --------
__global__ void hist_kernel(const int* __restrict__ ei, int* __restrict__ deg,
                            int E, int nNodes) {
    int e = blockIdx.x * blockDim.x + threadIdx.x;
    if (e >= E) return;
    int d = ei[E + e];
    if ((unsigned)d < (unsigned)nNodes) atomicAdd(&deg[d], 1);
}

// -------- scan phase 1: per-block (1024) exclusive scan --------
__global__ void scan1_kernel(const int* __restrict__ deg, int* __restrict__ off,
                             int* __restrict__ bsum, int n) {
    __shared__ int sh[1024];
    int tid = threadIdx.x;
    int i = blockIdx.x * 1024 + tid;
    int v = (i < n) ? deg[i] : 0;
    sh[tid] = v;
    __syncthreads();
    #pragma unroll
    for (int d = 1; d < 1024; d <<= 1) {
        int t = (tid >= d) ? sh[tid - d] : 0;
        __syncthreads();
        sh[tid] += t;
        __syncthreads();
    }
    if (i < n) off[i] = sh[tid] - v;   // exclusive
    if (tid == 1023) bsum[blockIdx.x] = sh[1023];
}

// -------- scan phase 2: serial scan of block sums (tiny) --------
__global__ void scan2_kernel(int* __restrict__ bsum, int nb) {
    if (threadIdx.x == 0 && blockIdx.x == 0) {
        int acc = 0;
        for (int i = 0; i < nb; ++i) { int v = bsum[i]; bsum[i] = acc; acc += v; }
    }
}

// -------- scan phase 3: add block offsets; init cur --------
__global__ void scan3_kernel(int* __restrict__ off, int* __restrict__ cur,
                             const int* __restrict__ bsum, int n) {
    int i = blockIdx.x * 1024 + threadIdx.x;
    if (i < n) {
        int o = off[i] + bsum[blockIdx.x];
        off[i] = o;
        cur[i] = o;
    }
}

// -------- CSR placement: csr[pos] = src, grouped by dst --------
__global__ void place_kernel(const int* __restrict__ ei, int* __restrict__ cur,
                             int* __restrict__ csr, int E, int nNodes) {
    int e = blockIdx.x * blockDim.x + threadIdx.x;
    if (e >= E) return;
    int s = ei[e];
    int d = ei[E + e];
    if ((unsigned)s >= (unsigned)nNodes || (unsigned)d >= (unsigned)nNodes) return;
    int pos = atomicAdd(&cur[d], 1);
    csr[pos] = s;
}

// -------- gather aggregate: warp per node, agg[node] = mean of x[neighbors] --------
__global__ void __launch_bounds__(256) gather64_kernel(
    const int* __restrict__ off, const int* __restrict__ deg,
    const int* __restrict__ csr, const float* __restrict__ x,
    float* __restrict__ agg, int nNodes)
{
    int node = blockIdx.x * 8 + (threadIdx.x >> 5);
    if (node >= nNodes) return;
    int lane = threadIdx.x & 31;
    int beg = off[node], dg = deg[node];
    float2 acc = make_float2(0.f, 0.f);
    for (int e = beg; e < beg + dg; ++e) {
        int s = csr[e];
        float2 v = *(const float2*)(x + (size_t)s * 64 + lane * 2);
        acc.x += v.x; acc.y += v.y;
    }
    float sc = 1.0f / (float)max(dg, 1);
    acc.x *= sc; acc.y *= sc;
    *(float2*)(agg + (size_t)node * 64 + lane * 2) = acc;
}

__global__ void __launch_bounds__(256) gather128_kernel(
    const int* __restrict__ off, const int* __restrict__ deg,
    const int* __restrict__ csr, const float* __restrict__ x,
    float* __restrict__ agg, int nNodes)
{
    int node = blockIdx.x * 8 + (threadIdx.x >> 5);
    if (node >= nNodes) return;
    int lane = threadIdx.x & 31;
    int beg = off[node], dg = deg[node];
    float4 acc = make_float4(0.f, 0.f, 0.f, 0.f);
    for (int e = beg; e < beg + dg; ++e) {
        int s = csr[e];
        float4 v = *(const float4*)(x + (size_t)s * 128 + lane * 4);
        acc.x += v.x; acc.y += v.y; acc.z += v.z; acc.w += v.w;
    }
    float sc = 1.0f / (float)max(dg, 1);
    acc.x *= sc; acc.y *= sc; acc.z *= sc; acc.w *= sc;
    *(float4*)(agg + (size_t)node * 128 + lane * 4) = acc;
}

// smem float offsets (shared by combine / mlp1)
#define OF_XH 0
#define OF_XL 4352
#define OF_WH 8704
#define OF_WL 13056
#define OF_XR 17408            // 128 x XRS raw X
#define SMF_TOTAL 22016        // floats -> 88,064 B

// ============================================================================
// combine (tf32 mma, cp.async-pipelined):
// out[128n x 128j] = sigmoid(concat(self, agg) @ W + b)   (agg pre-divided)
// ============================================================================
template<int K>
__global__ void __launch_bounds__(256, 2) combine_kernel(
    const float* __restrict__ self,   // [N, K/2]
    const float* __restrict__ agg,    // [N, K/2]  (already mean)
    const float* __restrict__ whG,    // [K][128] tf32-hi
    const float* __restrict__ wlG,    // [K][128] tf32-lo
    const float* __restrict__ b,      // [128]
    float* __restrict__ out,          // [N, 128]
    int nNodes)
{
    constexpr int SELF = K / 2;
    constexpr int NCH = K / 32;
    extern __shared__ float smf[];
    float* Xh = smf + OF_XH;
    float* Xl = smf + OF_XL;
    float* Wh = smf + OF_WH;
    float* Wl = smf + OF_WL;
    float* Xr = smf + OF_XR;
    const uint32_t xrAddr = (uint32_t)__cvta_generic_to_shared(Xr);

    const int t = threadIdx.x;
    const int lane = t & 31, warp = t >> 5;
    const int wm = (warp & 3) * 32;
    const int wn = (warp >> 2) * 64;
    const int base = blockIdx.x * 128;
    const int ar = lane >> 2, ac = lane & 3;

    float4 C[2][8];
    #pragma unroll
    for (int nt = 0; nt < 8; ++nt) {
        int j = wn + nt * 8 + 2 * ac;
        float bx = b[j], by = b[j + 1];
        C[0][nt] = make_float4(bx, by, bx, by);
        C[1][nt] = make_float4(bx, by, bx, by);
    }

    auto prefetch = [&](int ch) {
        int g = t & 7;
        int kg = ch * 32 + g * 4;
        const float* src0 = (kg < SELF) ? (self + kg) : (agg + (kg - SELF));
        #pragma unroll
        for (int it = 0; it < 4; ++it) {
            int n = (t >> 3) + 32 * it;
            int ngl = base + n;
            int sz = (ngl < nNodes) ? 16 : 0;
            cpasync16(xrAddr + (uint32_t)(n * XRS + g * 4) * 4,
                      src0 + (size_t)ngl * SELF, sz);
        }
    };

    prefetch(0); CP_COMMIT(); CP_WAIT0();

    for (int ch = 0; ch < NCH; ++ch) {
        __syncthreads();
        {
            int kloc = lane & 3, n8 = lane >> 2;
            #pragma unroll
            for (int it = 0; it < 16; ++it) {
                int k = kloc + 4 * (it & 7);
                int n = n8 + 8 * ((warp << 1) + (it >> 3));
                float v = Xr[n * XRS + k];
                split_store(v, Xh + k * KP + n, Xl + k * KP + n);
            }
        }
        {
            const float4* WhG4 = (const float4*)whG;
            const float4* WlG4 = (const float4*)wlG;
            for (int i = t; i < 1024; i += 256) {
                int k = i >> 5, q = i & 31;
                ((float4*)(Wh + k * KP))[q] = WhG4[(ch * 32 + k) * 32 + q];
                ((float4*)(Wl + k * KP))[q] = WlG4[(ch * 32 + k) * 32 + q];
            }
        }
        __syncthreads();
        if (ch + 1 < NCH) { prefetch(ch + 1); CP_COMMIT(); }
        #pragma unroll
        for (int s = 0; s < 4; ++s) {
            const int ko = s * 8;
            uint32_t Ah[2][4], Al[2][4];
            #pragma unroll
            for (int mt = 0; mt < 2; ++mt) {
                const float* ph = Xh + (ko + ac) * KP + wm + mt * 16 + ar;
                const float* pl = Xl + (ko + ac) * KP + wm + mt * 16 + ar;
                Ah[mt][0] = __float_as_uint(ph[0]);
                Ah[mt][1] = __float_as_uint(ph[8]);
                Ah[mt][2] = __float_as_uint(ph[4 * KP]);
                Ah[mt][3] = __float_as_uint(ph[4 * KP + 8]);
                Al[mt][0] = __float_as_uint(pl[0]);
                Al[mt][1] = __float_as_uint(pl[8]);
                Al[mt][2] = __float_as_uint(pl[4 * KP]);
                Al[mt][3] = __float_as_uint(pl[4 * KP + 8]);
            }
            #pragma unroll
            for (int nt = 0; nt < 8; ++nt) {
                const float* qh = Wh + (ko + ac) * KP + wn + nt * 8 + ar;
                const float* ql = Wl + (ko + ac) * KP + wn + nt * 8 + ar;
                uint32_t Bh[2] = { __float_as_uint(qh[0]), __float_as_uint(qh[4 * KP]) };
                uint32_t Bl[2] = { __float_as_uint(ql[0]), __float_as_uint(ql[4 * KP]) };
                mma_tf32(C[0][nt], Ah[0], Bh);
                mma_tf32(C[1][nt], Ah[1], Bh);
                mma_tf32(C[0][nt], Al[0], Bh);
                mma_tf32(C[1][nt], Al[1], Bh);
                mma_tf32(C[0][nt], Ah[0], Bl);
                mma_tf32(C[1][nt], Ah[1], Bl);
            }
        }
        if (ch + 1 < NCH) CP_WAIT0();
    }
    __syncthreads();

    float* Rs = smf;   // [128 node][132]
    #pragma unroll
    for (int mt = 0; mt < 2; ++mt) {
        int row = wm + mt * 16 + ar;
        #pragma unroll
        for (int nt = 0; nt < 8; ++nt) {
            int col = wn + nt * 8 + 2 * ac;
            float4 c = C[mt][nt];
            *(float2*)(Rs + row * 132 + col)       = make_float2(sigmoidf_(c.x), sigmoidf_(c.y));
            *(float2*)(Rs + (row + 8) * 132 + col) = make_float2(sigmoidf_(c.z), sigmoidf_(c.w));
        }
    }
    __syncthreads();

    const float4* Rs4 = (const float4*)Rs;
    float4* out4 = (float4*)out;
    for (int i = t; i < 128 * 32; i += 256) {
        int n = i >> 5, q = i & 31;
        int ngl = base + n;
        if (ngl < nNodes) out4[(size_t)ngl * 32 + q] = Rs4[n * 33 + q];
    }
}

// ============================================================================
// mlp1 (tf32 mma, cp.async-pipelined): hmT[j][n] = relu(h2 @ Wm1 + bm1)
// ============================================================================
__global__ void __launch_bounds__(256, 2) mlp1_kernel(
    const float* __restrict__ h2,     // [N, 128]
    const float* __restrict__ whG,    // Wm1 tf32-hi [128][256]
    const float* __restrict__ wlG,    // Wm1 tf32-lo
    const float* __restrict__ bm1,    // [256]
    float* __restrict__ hmT,          // [256][N]
    int nNodes)
{
    extern __shared__ float smf[];
    float* Xh = smf + OF_XH;
    float* Xl = smf + OF_XL;
    float* Wh = smf + OF_WH;
    float* Wl = smf + OF_WL;
    float* Xr = smf + OF_XR;
    const uint32_t xrAddr = (uint32_t)__cvta_generic_to_shared(Xr);

    const int t = threadIdx.x;
    const int lane = t & 31, warp = t >> 5;
    const int wm = (warp & 3) * 32;
    const int wn = (warp >> 2) * 64;
    const int base = blockIdx.x * 128;
    const int ar = lane >> 2, ac = lane & 3;

    auto prefetch = [&](int ch) {
        int g = t & 7;
        int col = ch * 32 + g * 4;
        #pragma unroll
        for (int it = 0; it < 4; ++it) {
            int n = (t >> 3) + 32 * it;
            int ngl = base + n;
            int sz = (ngl < nNodes) ? 16 : 0;
            cpasync16(xrAddr + (uint32_t)(n * XRS + g * 4) * 4,
                      h2 + (size_t)ngl * 128 + col, sz);
        }
    };

    prefetch(0); CP_COMMIT(); CP_WAIT0();

    float4 C[2][8];
    for (int it8 = 0; it8 < 8; ++it8) {
        const int ch = it8 & 3, pass = it8 >> 2;
        if (ch == 0) {
            #pragma unroll
            for (int nt = 0; nt < 8; ++nt) {
                int j = pass * 128 + wn + nt * 8 + 2 * ac;
                float bx = bm1[j], by = bm1[j + 1];
                C[0][nt] = make_float4(bx, by, bx, by);
                C[1][nt] = make_float4(bx, by, bx, by);
            }
        }
        __syncthreads();
        {
            int kloc = lane & 3, n8 = lane >> 2;
            #pragma unroll
            for (int it = 0; it < 16; ++it) {
                int k = kloc + 4 * (it & 7);
                int n = n8 + 8 * ((warp << 1) + (it >> 3));
                float v = Xr[n * XRS + k];
                split_store(v, Xh + k * KP + n, Xl + k * KP + n);
            }
        }
        {
            const float4* WhG4 = (const float4*)whG;
            const float4* WlG4 = (const float4*)wlG;
            for (int i = t; i < 1024; i += 256) {
                int k = i >> 5, q = i & 31;
                int srci = (ch * 32 + k) * 64 + pass * 32 + q;
                ((float4*)(Wh + k * KP))[q] = WhG4[srci];
                ((float4*)(Wl + k * KP))[q] = WlG4[srci];
            }
        }
        __syncthreads();
        if (it8 + 1 < 8) { prefetch((it8 + 1) & 3); CP_COMMIT(); }
        #pragma unroll
        for (int s = 0; s < 4; ++s) {
            const int ko = s * 8;
            uint32_t Ah[2][4], Al[2][4];
            #pragma unroll
            for (int mt = 0; mt < 2; ++mt) {
                const float* ph = Xh + (ko + ac) * KP + wm + mt * 16 + ar;
                const float* pl = Xl + (ko + ac) * KP + wm + mt * 16 + ar;
                Ah[mt][0] = __float_as_uint(ph[0]);
                Ah[mt][1] = __float_as_uint(ph[8]);
                Ah[mt][2] = __float_as_uint(ph[4 * KP]);
                Ah[mt][3] = __float_as_uint(ph[4 * KP + 8]);
                Al[mt][0] = __float_as_uint(pl[0]);
                Al[mt][1] = __float_as_uint(pl[8]);
                Al[mt][2] = __float_as_uint(pl[4 * KP]);
                Al[mt][3] = __float_as_uint(pl[4 * KP + 8]);
            }
            #pragma unroll
            for (int nt = 0; nt < 8; ++nt) {
                const float* qh = Wh + (ko + ac) * KP + wn + nt * 8 + ar;
                const float* ql = Wl + (ko + ac) * KP + wn + nt * 8 + ar;
                uint32_t Bh[2] = { __float_as_uint(qh[0]), __float_as_uint(qh[4 * KP]) };
                uint32_t Bl[2] = { __float_as_uint(ql[0]), __float_as_uint(ql[4 * KP]) };
                mma_tf32(C[0][nt], Ah[0], Bh);
                mma_tf32(C[1][nt], Ah[1], Bh);
                mma_tf32(C[0][nt], Al[0], Bh);
                mma_tf32(C[1][nt], Al[1], Bh);
                mma_tf32(C[0][nt], Ah[0], Bl);
                mma_tf32(C[1][nt], Ah[1], Bl);
            }
        }
        if (it8 + 1 < 8) CP_WAIT0();

        if (ch == 3) {
            __syncthreads();
            float* Rs = smf;   // [128 j][132] transposed staging
            #pragma unroll
            for (int mt = 0; mt < 2; ++mt) {
                int row = wm + mt * 16 + ar;
                #pragma unroll
                for (int nt = 0; nt < 8; ++nt) {
                    int col = wn + nt * 8 + 2 * ac;
                    float4 c = C[mt][nt];
                    Rs[col * 132 + row]           = fmaxf(c.x, 0.f);
                    Rs[(col + 1) * 132 + row]     = fmaxf(c.y, 0.f);
                    Rs[col * 132 + row + 8]       = fmaxf(c.z, 0.f);
                    Rs[(col + 1) * 132 + row + 8] = fmaxf(c.w, 0.f);
                }
            }
            __syncthreads();
            if (base + 128 <= nNodes) {
                const float4* Rs4 = (const float4*)Rs;
                for (int i = t; i < 128 * 32; i += 256) {
                    int j = i >> 5, q = i & 31;
                    *(float4*)(hmT + (size_t)(pass * 128 + j) * nNodes + base + 4 * q) = Rs4[j * 33 + q];
                }
            } else {
                for (int i = t; i < 128 * 128; i += 256) {
                    int j = i >> 7, n = i & 127;
                    if (base + n < nNodes)
                        hmT[(size_t)(pass * 128 + j) * nNodes + base + n] = Rs[j * 132 + n];
                }
            }
        }
    }
}

// ============================================================================
// mlp2: out = hmT^T @ Wm2 + bm2  (K=256, NOUT=40) — scalar path
// ============================================================================
__global__ void __launch_bounds__(256) mlp2_kernel(
    const float* __restrict__ hmT,    // [256][N]
    const float* __restrict__ Wm2,    // [256, 40]
    const float* __restrict__ bm2,    // [40]
    float* __restrict__ out,          // [N, 40]
    int nNodes)
{
    extern __shared__ float smf[];
    float* Ws = smf;                  // [256][40]
    float* Rs = smf + 256 * 40;       // [256][44]

    const int t = threadIdx.x;
    const int base = blockIdx.x * 256;
    const int ng = t & 63;
    const int og = t >> 6;
    const int n0 = base + ng * 4;
    const int j0 = og * 10;

    {
        const float4* Wg = (const float4*)Wm2;
        float4* Ws4 = (float4*)Ws;
        for (int i = t; i < 2560; i += 256) Ws4[i] = Wg[i];
    }
    __syncthreads();

    float4 acc[10];
    #pragma unroll
    for (int j = 0; j < 10; ++j) {
        float bv = bm2[j0 + j];
        acc[j] = make_float4(bv, bv, bv, bv);
    }

    if (n0 + 3 < nNodes) {
        #pragma unroll 2
        for (int k = 0; k < 256; ++k) {
            float4 x4 = *(const float4*)(hmT + (size_t)k * nNodes + n0);
            const float2* wr = (const float2*)(Ws + k * 40 + j0);
            float2 w0 = wr[0], w1 = wr[1], w2 = wr[2], w3 = wr[3], w4 = wr[4];
            fma4(acc[0], w0.x, x4); fma4(acc[1], w0.y, x4);
            fma4(acc[2], w1.x, x4); fma4(acc[3], w1.y, x4);
            fma4(acc[4], w2.x, x4); fma4(acc[5], w2.y, x4);
            fma4(acc[6], w3.x, x4); fma4(acc[7], w3.y, x4);
            fma4(acc[8], w4.x, x4); fma4(acc[9], w4.y, x4);
        }
    } else {
        for (int k = 0; k < 256; ++k) {
            float4 x4;
            const float* row = hmT + (size_t)k * nNodes;
            x4.x = (n0 + 0 < nNodes) ? row[n0 + 0] : 0.f;
            x4.y = (n0 + 1 < nNodes) ? row[n0 + 1] : 0.f;
            x4.z = (n0 + 2 < nNodes) ? row[n0 + 2] : 0.f;
            x4.w = (n0 + 3 < nNodes) ? row[n0 + 3] : 0.f;
            const float2* wr = (const float2*)(Ws + k * 40 + j0);
            float2 w0 = wr[0], w1 = wr[1], w2 = wr[2], w3 = wr[3], w4 = wr[4];
            fma4(acc[0], w0.x, x4); fma4(acc[1], w0.y, x4);
            fma4(acc[2], w1.x, x4); fma4(acc[3], w1.y, x4);
            fma4(acc[4], w2.x, x4); fma4(acc[5], w2.y, x4);
            fma4(acc[6], w3.x, x4); fma4(acc[7], w3.y, x4);
            fma4(acc[8], w4.x, x4); fma4(acc[9], w4.y, x4);
        }
    }

    int nl = ng * 4;
    #pragma unroll
    for (int j = 0; j < 10; ++j) {
        Rs[(nl + 0) * 44 + j0 + j] = acc[j].x;
        Rs[(nl + 1) * 44 + j0 + j] = acc[j].y;
        Rs[(nl + 2) * 44 + j0 + j] = acc[j].z;
        Rs[(nl + 3) * 44 + j0 + j] = acc[j].w;
    }
    __syncthreads();

    const float4* Rs4 = (const float4*)Rs;
    float4* out4 = (float4*)out;
    for (int i = t; i < 256 * 10; i += 256) {
        int n = i / 10, q = i - n * 10;
        int ngl = base + n;
        if (ngl < nNodes) out4[(size_t)ngl * 10 + q] = Rs4[n * 11 + q];
    }
}

// -------- launch --------
extern "C" void kernel_launch(void* const* d_in, const int* in_sizes, int n_in,
                              void* d_out, int out_size)
{
    const float* feat = (const float*)d_in[0];
    const int*   ei   = (const int*)d_in[1];     // int32 (JAX x64 disabled)
    const float* W1  = (const float*)d_in[2];
    const float* b1  = (const float*)d_in[3];
    const float* W2  = (const float*)d_in[4];
    const float* b2  = (const float*)d_in[5];
    const float* Wm1 = (const float*)d_in[6];
    const float* bm1 = (const float*)d_in[7];
    const float* Wm2 = (const float*)d_in[8];
    const float* bm2 = (const float*)d_in[9];
    float* out = (float*)d_out;

    const int N = in_sizes[0] / 64;     // 100000
    const int E = in_sizes[1] / 2;      // 1600000

    float *agg, *h1, *h2, *hmT, *wh, *wl;
    int *deg, *off, *cur, *csr, *bsum;
    cudaGetSymbolAddress((void**)&agg, g_agg);
    cudaGetSymbolAddress((void**)&h1,  g_h1);
    cudaGetSymbolAddress((void**)&h2,  g_h2);
    cudaGetSymbolAddress((void**)&hmT, g_hmT);
    cudaGetSymbolAddress((void**)&wh,  g_wh);
    cudaGetSymbolAddress((void**)&wl,  g_wl);
    cudaGetSymbolAddress((void**)&deg, g_deg);
    cudaGetSymbolAddress((void**)&off, g_off);
    cudaGetSymbolAddress((void**)&cur, g_cur);
    cudaGetSymbolAddress((void**)&csr, g_csr);
    cudaGetSymbolAddress((void**)&bsum, g_bsum);

    const int SM_GEMM = SMF_TOTAL * 4;              // 88,064 B -> 2 blocks/SM
    const int SM_MLP2 = (256 * 40 + 256 * 44) * 4;  // 86,016 B
    cudaFuncSetAttribute(combine_kernel<128>, cudaFuncAttributeMaxDynamicSharedMemorySize, SM_GEMM);
    cudaFuncSetAttribute(combine_kernel<256>, cudaFuncAttributeMaxDynamicSharedMemorySize, SM_GEMM);
    cudaFuncSetAttribute(mlp1_kernel,         cudaFuncAttributeMaxDynamicSharedMemorySize, SM_GEMM);
    cudaFuncSetAttribute(mlp2_kernel,         cudaFuncAttributeMaxDynamicSharedMemorySize, SM_MLP2);

    const int nodeBlocks = (N + 127) / 128;      // 782
    const int mlp2Blocks = (N + 255) / 256;      // 391
    const int gatherBlocks = (N + 7) / 8;        // 12500
    const int scanBlocks = (N + 1023) / 1024;    // 98
    const int edgeBlocks = (E + 255) / 256;

    // ---- CSR build (once; reused by both layers) ----
    prep1_kernel<<<2048, 256>>>(deg, N, W1, W2, Wm1, wh, wl);
    hist_kernel<<<edgeBlocks, 256>>>(ei, deg, E, N);
    scan1_kernel<<<scanBlocks, 1024>>>(deg, off, bsum, N);
    scan2_kernel<<<1, 32>>>(bsum, scanBlocks);
    scan3_kernel<<<scanBlocks, 1024>>>(off, cur, bsum, N);
    place_kernel<<<edgeBlocks, 256>>>(ei, cur, csr, E, N);

    // ---- Layer 1 ----
    gather64_kernel<<<gatherBlocks, 256>>>(off, deg, csr, feat, agg, N);
    combine_kernel<128><<<nodeBlocks, 256, SM_GEMM>>>(feat, agg, wh, wl, b1, h1, N);
    // ---- Layer 2 ----
    gather128_kernel<<<gatherBlocks, 256>>>(off, deg, csr, h1, agg, N);
    combine_kernel<256><<<nodeBlocks, 256, SM_GEMM>>>(h1, agg, wh + 16384, wl + 16384, b2, h2, N);
    // ---- MLP ----
    mlp1_kernel<<<nodeBlocks, 256, SM_GEMM>>>(h2, wh + 49152, wl + 49152, bm1, hmT, N);
    mlp2_kernel<<<mlp2Blocks, 256, SM_MLP2>>>(hmT, Wm2, bm2, out, N);
}

// round 12
// speedup vs baseline: 1.8539x; 1.0207x over previous
#include <cuda_runtime.h>
#include <math.h>
#include <stdint.h>

#define NN 100000
#define EE 1600000
#define KP 136    // W split-tile row stride (floats): conflict-free frag loads
#define XRS 36    // raw X tile row stride (floats)
#define FB 13312  // floats per double-buffer: Wh(4352)+Wl(4352)+Xr(4608)
#define OF_WL 4352
#define OF_XR 8704
#define SMF_TOTAL (2 * FB)   // 26,624 floats = 106,496 B -> 2 blocks/SM

// -------- scratch (device globals; no allocation allowed) --------
__device__ float g_agg[(size_t)NN * 128];
__device__ float g_h1[(size_t)NN * 128];
__device__ float g_h2[(size_t)NN * 128];
__device__ float g_hmT[(size_t)NN * 256];   // hidden MLP layer, TRANSPOSED [256][N]
__device__ float g_wh[81920];               // tf32-hi of [W1|W2|Wm1]
__device__ float g_wl[81920];               // tf32-lo of [W1|W2|Wm1]
__device__ int   g_deg[NN];
__device__ int   g_off[NN];
__device__ int   g_cur[NN];
__device__ int   g_csr[EE];
__device__ int   g_bsum[512];

// -------- helpers --------
__device__ __forceinline__ float sigmoidf_(float x) {
    return 1.0f / (1.0f + __expf(-x));
}
__device__ __forceinline__ void fma4(float4& a, float s, const float4& x) {
    a.x = fmaf(s, x.x, a.x); a.y = fmaf(s, x.y, a.y);
    a.z = fmaf(s, x.z, a.z); a.w = fmaf(s, x.w, a.w);
}
__device__ __forceinline__ uint32_t f2tf(float x) {
    uint32_t r;
    asm("cvt.rna.tf32.f32 %0, %1;" : "=r"(r) : "f"(x));
    return r;
}
__device__ __forceinline__ void mma_tf32(float4& d, const uint32_t* a, const uint32_t* b) {
    asm("mma.sync.aligned.m16n8k8.row.col.f32.tf32.tf32.f32 "
        "{%0,%1,%2,%3}, {%4,%5,%6,%7}, {%8,%9}, {%0,%1,%2,%3};"
        : "+f"(d.x), "+f"(d.y), "+f"(d.z), "+f"(d.w)
        : "r"(a[0]), "r"(a[1]), "r"(a[2]), "r"(a[3]), "r"(b[0]), "r"(b[1]));
}
// register-side tf32 hi/lo split
__device__ __forceinline__ void split_reg(float v, uint32_t& hi, uint32_t& lo) {
    hi = f2tf(v);
    lo = f2tf(v - __uint_as_float(hi));
}
__device__ __forceinline__ void cpasync16(uint32_t dst, const void* src, int srcsize) {
    asm volatile("cp.async.ca.shared.global [%0], [%1], 16, %2;"
                 :: "r"(dst), "l"(src), "r"(srcsize) : "memory");
}
#define CP_COMMIT() asm volatile("cp.async.commit_group;" ::: "memory")
#define CP_WAIT1()  asm volatile("cp.async.wait_group 1;" ::: "memory")

// -------- prep: zero deg AND pre-split weights to tf32 hi/lo --------
__global__ void prep1_kernel(int* __restrict__ deg, int n,
                             const float* __restrict__ W1,
                             const float* __restrict__ W2,
                             const float* __restrict__ Wm1,
                             float* __restrict__ wh, float* __restrict__ wl)
{
    int idx = blockIdx.x * blockDim.x + threadIdx.x;
    int stride = gridDim.x * blockDim.x;
    for (int i = idx; i < n; i += stride) deg[i] = 0;
    for (int i = idx; i < 81920; i += stride) {
        float v;
        if (i < 16384)      v = W1[i];
        else if (i < 49152) v = W2[i - 16384];
        else                v = Wm1[i - 49152];
        uint32_t hb = f2tf(v);
        float hi = __uint_as_float(hb);
        wh[i] = hi;
        wl[i] = __uint_as_float(f2tf(v - hi));
    }
}

// -------- CSR build: histogram over dst --------
__global__ void hist_kernel(const int* __restrict__ ei, int* __restrict__ deg,
                            int E, int nNodes) {
    int e = blockIdx.x * blockDim.x + threadIdx.x;
    if (e >= E) return;
    int d = ei[E + e];
    if ((unsigned)d < (unsigned)nNodes) atomicAdd(&deg[d], 1);
}

// -------- scan phase 1 --------
__global__ void scan1_kernel(const int* __restrict__ deg, int* __restrict__ off,
                             int* __restrict__ bsum, int n) {
    __shared__ int sh[1024];
    int tid = threadIdx.x;
    int i = blockIdx.x * 1024 + tid;
    int v = (i < n) ? deg[i] : 0;
    sh[tid] = v;
    __syncthreads();
    #pragma unroll
    for (int d = 1; d < 1024; d <<= 1) {
        int t = (tid >= d) ? sh[tid - d] : 0;
        __syncthreads();
        sh[tid] += t;
        __syncthreads();
    }
    if (i < n) off[i] = sh[tid] - v;
    if (tid == 1023) bsum[blockIdx.x] = sh[1023];
}

// -------- scan phase 2 --------
__global__ void scan2_kernel(int* __restrict__ bsum, int nb) {
    if (threadIdx.x == 0 && blockIdx.x == 0) {
        int acc = 0;
        for (int i = 0; i < nb; ++i) { int v = bsum[i]; bsum[i] = acc; acc += v; }
    }
}

// -------- scan phase 3 --------
__global__ void scan3_kernel(int* __restrict__ off, int* __restrict__ cur,
                             const int* __restrict__ bsum, int n) {
    int i = blockIdx.x * 1024 + threadIdx.x;
    if (i < n) {
        int o = off[i] + bsum[blockIdx.x];
        off[i] = o;
        cur[i] = o;
    }
}

// -------- CSR placement --------
__global__ void place_kernel(const int* __restrict__ ei, int* __restrict__ cur,
                             int* __restrict__ csr, int E, int nNodes) {
    int e = blockIdx.x * blockDim.x + threadIdx.x;
    if (e >= E) return;
    int s = ei[e];
    int d = ei[E + e];
    if ((unsigned)s >= (unsigned)nNodes || (unsigned)d >= (unsigned)nNodes) return;
    int pos = atomicAdd(&cur[d], 1);
    csr[pos] = s;
}

// -------- gather aggregate: warp per node --------
__global__ void __launch_bounds__(256) gather64_kernel(
    const int* __restrict__ off, const int* __restrict__ deg,
    const int* __restrict__ csr, const float* __restrict__ x,
    float* __restrict__ agg, int nNodes)
{
    int node = blockIdx.x * 8 + (threadIdx.x >> 5);
    if (node >= nNodes) return;
    int lane = threadIdx.x & 31;
    int beg = off[node], dg = deg[node];
    float2 acc = make_float2(0.f, 0.f);
    for (int e = beg; e < beg + dg; ++e) {
        int s = csr[e];
        float2 v = *(const float2*)(x + (size_t)s * 64 + lane * 2);
        acc.x += v.x; acc.y += v.y;
    }
    float sc = 1.0f / (float)max(dg, 1);
    acc.x *= sc; acc.y *= sc;
    *(float2*)(agg + (size_t)node * 64 + lane * 2) = acc;
}

__global__ void __launch_bounds__(256) gather128_kernel(
    const int* __restrict__ off, const int* __restrict__ deg,
    const int* __restrict__ csr, const float* __restrict__ x,
    float* __restrict__ agg, int nNodes)
{
    int node = blockIdx.x * 8 + (threadIdx.x >> 5);
    if (node >= nNodes) return;
    int lane = threadIdx.x & 31;
    int beg = off[node], dg = deg[node];
    float4 acc = make_float4(0.f, 0.f, 0.f, 0.f);
    for (int e = beg; e < beg + dg; ++e) {
        int s = csr[e];
        float4 v = *(const float4*)(x + (size_t)s * 128 + lane * 4);
        acc.x += v.x; acc.y += v.y; acc.z += v.z; acc.w += v.w;
    }
    float sc = 1.0f / (float)max(dg, 1);
    acc.x *= sc; acc.y *= sc; acc.z *= sc; acc.w *= sc;
    *(float4*)(agg + (size_t)node * 128 + lane * 4) = acc;
}

// ============================================================================
// GEMM mainloop body (shared): one 32-k chunk from buffer {Wh,Wl,Xr}.
// A split done in REGISTERS from raw Xr (conflict-free scalar LDS).
// ============================================================================
__device__ __forceinline__ void mma_chunk(
    const float* Wh, const float* Wl, const float* Xr,
    int wm, int wn, int ar, int ac, float4 C0[8], float4 C1[8])
{
    #pragma unroll
    for (int s = 0; s < 4; ++s) {
        const int ko = s * 8;
        uint32_t Ah[2][4], Al[2][4];
        #pragma unroll
        for (int mt = 0; mt < 2; ++mt) {
            int nb = wm + mt * 16 + ar;
            float r0 = Xr[nb * XRS + ko + ac];
            float r1 = Xr[(nb + 8) * XRS + ko + ac];
            float r2 = Xr[nb * XRS + ko + ac + 4];
            float r3 = Xr[(nb + 8) * XRS + ko + ac + 4];
            split_reg(r0, Ah[mt][0], Al[mt][0]);
            split_reg(r1, Ah[mt][1], Al[mt][1]);
            split_reg(r2, Ah[mt][2], Al[mt][2]);
            split_reg(r3, Ah[mt][3], Al[mt][3]);
        }
        #pragma unroll
        for (int nt = 0; nt < 8; ++nt) {
            const float* qh = Wh + (ko + ac) * KP + wn + nt * 8 + ar;
            const float* ql = Wl + (ko + ac) * KP + wn + nt * 8 + ar;
            uint32_t Bh[2] = { __float_as_uint(qh[0]), __float_as_uint(qh[4 * KP]) };
            uint32_t Bl[2] = { __float_as_uint(ql[0]), __float_as_uint(ql[4 * KP]) };
            mma_tf32(C0[nt], Ah[0], Bh);
            mma_tf32(C1[nt], Ah[1], Bh);
            mma_tf32(C0[nt], Al[0], Bh);
            mma_tf32(C1[nt], Al[1], Bh);
            mma_tf32(C0[nt], Ah[0], Bl);
            mma_tf32(C1[nt], Ah[1], Bl);
        }
    }
}

// ============================================================================
// combine (tf32 mma, fully double-buffered cp.async):
// out[128n x 128j] = sigmoid(concat(self, agg) @ W + b)   (agg pre-divided)
// ============================================================================
template<int K>
__global__ void __launch_bounds__(256, 2) combine_kernel(
    const float* __restrict__ self,   // [N, K/2]
    const float* __restrict__ agg,    // [N, K/2]  (already mean)
    const float* __restrict__ whG,    // [K][128] tf32-hi
    const float* __restrict__ wlG,    // [K][128] tf32-lo
    const float* __restrict__ b,      // [128]
    float* __restrict__ out,          // [N, 128]
    int nNodes)
{
    constexpr int SELF = K / 2;
    constexpr int NCH = K / 32;
    extern __shared__ float smf[];
    const uint32_t smBase = (uint32_t)__cvta_generic_to_shared(smf);

    const int t = threadIdx.x;
    const int lane = t & 31, warp = t >> 5;
    const int wm = (warp & 3) * 32;
    const int wn = (warp >> 2) * 64;
    const int base = blockIdx.x * 128;
    const int ar = lane >> 2, ac = lane & 3;

    float4 C0[8], C1[8];
    #pragma unroll
    for (int nt = 0; nt < 8; ++nt) {
        int j = wn + nt * 8 + 2 * ac;
        float bx = b[j], by = b[j + 1];
        C0[nt] = make_float4(bx, by, bx, by);
        C1[nt] = make_float4(bx, by, bx, by);
    }

    auto prefetch = [&](int ch, int buf) {
        const uint32_t bb = smBase + (uint32_t)(buf * FB) * 4;
        // X: 4 granules/thread into Xr
        int g = t & 7;
        int kg = ch * 32 + g * 4;
        const float* src0 = (kg < SELF) ? (self + kg) : (agg + (kg - SELF));
        #pragma unroll
        for (int it = 0; it < 4; ++it) {
            int n = (t >> 3) + 32 * it;
            int ngl = base + n;
            int sz = (ngl < nNodes) ? 16 : 0;
            cpasync16(bb + (uint32_t)(OF_XR + n * XRS + g * 4) * 4,
                      src0 + (size_t)ngl * SELF, sz);
        }
        // W: 4+4 granules/thread into Wh/Wl
        #pragma unroll
        for (int r = 0; r < 4; ++r) {
            int i = t + 256 * r;
            int k = i >> 5, q = i & 31;
            cpasync16(bb + (uint32_t)(k * KP + q * 4) * 4,
                      whG + (size_t)(ch * 32 + k) * 128 + q * 4, 16);
            cpasync16(bb + (uint32_t)(OF_WL + k * KP + q * 4) * 4,
                      wlG + (size_t)(ch * 32 + k) * 128 + q * 4, 16);
        }
    };

    prefetch(0, 0); CP_COMMIT();

    for (int ch = 0; ch < NCH; ++ch) {
        __syncthreads();   // all warps done with buffer (ch+1)&1 (used at ch-1)
        if (ch + 1 < NCH) prefetch(ch + 1, (ch + 1) & 1);
        CP_COMMIT();
        CP_WAIT1();        // chunk ch's group complete (latest group may pend)
        __syncthreads();   // visibility across threads
        const float* bufp = smf + (ch & 1) * FB;
        mma_chunk(bufp, bufp + OF_WL, bufp + OF_XR, wm, wn, ar, ac, C0, C1);
    }
    __syncthreads();   // buffers free; reuse smem as staging

    float* Rs = smf;   // [128 node][132]
    #pragma unroll
    for (int mt = 0; mt < 2; ++mt) {
        int row = wm + mt * 16 + ar;
        float4* Cm = (mt == 0) ? C0 : C1;
        #pragma unroll
        for (int nt = 0; nt < 8; ++nt) {
            int col = wn + nt * 8 + 2 * ac;
            float4 c = Cm[nt];
            *(float2*)(Rs + row * 132 + col)       = make_float2(sigmoidf_(c.x), sigmoidf_(c.y));
            *(float2*)(Rs + (row + 8) * 132 + col) = make_float2(sigmoidf_(c.z), sigmoidf_(c.w));
        }
    }
    __syncthreads();

    const float4* Rs4 = (const float4*)Rs;
    float4* out4 = (float4*)out;
    for (int i = t; i < 128 * 32; i += 256) {
        int n = i >> 5, q = i & 31;
        int ngl = base + n;
        if (ngl < nNodes) out4[(size_t)ngl * 32 + q] = Rs4[n * 33 + q];
    }
}

// ============================================================================
// mlp1 (tf32 mma, double-buffered): hmT[j][n] = relu(h2 @ Wm1 + bm1)
// Pipeline drained at each pass boundary (epilogue staging overlaps buffers).
// ============================================================================
__global__ void __launch_bounds__(256, 2) mlp1_kernel(
    const float* __restrict__ h2,     // [N, 128]
    const float* __restrict__ whG,    // Wm1 tf32-hi [128][256]
    const float* __restrict__ wlG,    // Wm1 tf32-lo
    const float* __restrict__ bm1,    // [256]
    float* __restrict__ hmT,          // [256][N]
    int nNodes)
{
    extern __shared__ float smf[];
    const uint32_t smBase = (uint32_t)__cvta_generic_to_shared(smf);

    const int t = threadIdx.x;
    const int lane = t & 31, warp = t >> 5;
    const int wm = (warp & 3) * 32;
    const int wn = (warp >> 2) * 64;
    const int base = blockIdx.x * 128;
    const int ar = lane >> 2, ac = lane & 3;

    auto prefetch = [&](int pass, int ch, int buf) {
        const uint32_t bb = smBase + (uint32_t)(buf * FB) * 4;
        int g = t & 7;
        int col = ch * 32 + g * 4;
        #pragma unroll
        for (int it = 0; it < 4; ++it) {
            int n = (t >> 3) + 32 * it;
            int ngl = base + n;
            int sz = (ngl < nNodes) ? 16 : 0;
            cpasync16(bb + (uint32_t)(OF_XR + n * XRS + g * 4) * 4,
                      h2 + (size_t)ngl * 128 + col, sz);
        }
        #pragma unroll
        for (int r = 0; r < 4; ++r) {
            int i = t + 256 * r;
            int k = i >> 5, q = i & 31;
            cpasync16(bb + (uint32_t)(k * KP + q * 4) * 4,
                      whG + (size_t)(ch * 32 + k) * 256 + pass * 128 + q * 4, 16);
            cpasync16(bb + (uint32_t)(OF_WL + k * KP + q * 4) * 4,
                      wlG + (size_t)(ch * 32 + k) * 256 + pass * 128 + q * 4, 16);
        }
    };

    for (int pass = 0; pass < 2; ++pass) {
        float4 C0[8], C1[8];
        #pragma unroll
        for (int nt = 0; nt < 8; ++nt) {
            int j = pass * 128 + wn + nt * 8 + 2 * ac;
            float bx = bm1[j], by = bm1[j + 1];
            C0[nt] = make_float4(bx, by, bx, by);
            C1[nt] = make_float4(bx, by, bx, by);
        }

        prefetch(pass, 0, 0); CP_COMMIT();
        for (int ch = 0; ch < 4; ++ch) {
            __syncthreads();
            if (ch + 1 < 4) prefetch(pass, ch + 1, (ch + 1) & 1);
            CP_COMMIT();
            CP_WAIT1();
            __syncthreads();
            const float* bufp = smf + (ch & 1) * FB;
            mma_chunk(bufp, bufp + OF_WL, bufp + OF_XR, wm, wn, ar, ac, C0, C1);
        }
        __syncthreads();   // pipeline drained; buffers free for staging

        float* Rs = smf;   // [128 j][132] transposed staging
        #pragma unroll
        for (int mt = 0; mt < 2; ++mt) {
            int row = wm + mt * 16 + ar;   // node
            float4* Cm = (mt == 0) ? C0 : C1;
            #pragma unroll
            for (int nt = 0; nt < 8; ++nt) {
                int col = wn + nt * 8 + 2 * ac;   // j
                float4 c = Cm[nt];
                Rs[col * 132 + row]           = fmaxf(c.x, 0.f);
                Rs[(col + 1) * 132 + row]     = fmaxf(c.y, 0.f);
                Rs[col * 132 + row + 8]       = fmaxf(c.z, 0.f);
                Rs[(col + 1) * 132 + row + 8] = fmaxf(c.w, 0.f);
            }
        }
        __syncthreads();
        if (base + 128 <= nNodes) {
            const float4* Rs4 = (const float4*)Rs;
            for (int i = t; i < 128 * 32; i += 256) {
                int j = i >> 5, q = i & 31;
                *(float4*)(hmT + (size_t)(pass * 128 + j) * nNodes + base + 4 * q) = Rs4[j * 33 + q];
            }
        } else {
            for (int i = t; i < 128 * 128; i += 256) {
                int j = i >> 7, n = i & 127;
                if (base + n < nNodes)
                    hmT[(size_t)(pass * 128 + j) * nNodes + base + n] = Rs[j * 132 + n];
            }
        }
        __syncthreads();   // writeout done before next pass's prefetch overwrites
    }
}

// ============================================================================
// mlp2: out = hmT^T @ Wm2 + bm2  (K=256, NOUT=40) — scalar path
// ============================================================================
__global__ void __launch_bounds__(256) mlp2_kernel(
    const float* __restrict__ hmT,    // [256][N]
    const float* __restrict__ Wm2,    // [256, 40]
    const float* __restrict__ bm2,    // [40]
    float* __restrict__ out,          // [N, 40]
    int nNodes)
{
    extern __shared__ float smf[];
    float* Ws = smf;                  // [256][40]
    float* Rs = smf + 256 * 40;       // [256][44]

    const int t = threadIdx.x;
    const int base = blockIdx.x * 256;
    const int ng = t & 63;
    const int og = t >> 6;
    const int n0 = base + ng * 4;
    const int j0 = og * 10;

    {
        const float4* Wg = (const float4*)Wm2;
        float4* Ws4 = (float4*)Ws;
        for (int i = t; i < 2560; i += 256) Ws4[i] = Wg[i];
    }
    __syncthreads();

    float4 acc[10];
    #pragma unroll
    for (int j = 0; j < 10; ++j) {
        float bv = bm2[j0 + j];
        acc[j] = make_float4(bv, bv, bv, bv);
    }

    if (n0 + 3 < nNodes) {
        #pragma unroll 2
        for (int k = 0; k < 256; ++k) {
            float4 x4 = *(const float4*)(hmT + (size_t)k * nNodes + n0);
            const float2* wr = (const float2*)(Ws + k * 40 + j0);
            float2 w0 = wr[0], w1 = wr[1], w2 = wr[2], w3 = wr[3], w4 = wr[4];
            fma4(acc[0], w0.x, x4); fma4(acc[1], w0.y, x4);
            fma4(acc[2], w1.x, x4); fma4(acc[3], w1.y, x4);
            fma4(acc[4], w2.x, x4); fma4(acc[5], w2.y, x4);
            fma4(acc[6], w3.x, x4); fma4(acc[7], w3.y, x4);
            fma4(acc[8], w4.x, x4); fma4(acc[9], w4.y, x4);
        }
    } else {
        for (int k = 0; k < 256; ++k) {
            float4 x4;
            const float* row = hmT + (size_t)k * nNodes;
            x4.x = (n0 + 0 < nNodes) ? row[n0 + 0] : 0.f;
            x4.y = (n0 + 1 < nNodes) ? row[n0 + 1] : 0.f;
            x4.z = (n0 + 2 < nNodes) ? row[n0 + 2] : 0.f;
            x4.w = (n0 + 3 < nNodes) ? row[n0 + 3] : 0.f;
            const float2* wr = (const float2*)(Ws + k * 40 + j0);
            float2 w0 = wr[0], w1 = wr[1], w2 = wr[2], w3 = wr[3], w4 = wr[4];
            fma4(acc[0], w0.x, x4); fma4(acc[1], w0.y, x4);
            fma4(acc[2], w1.x, x4); fma4(acc[3], w1.y, x4);
            fma4(acc[4], w2.x, x4); fma4(acc[5], w2.y, x4);
            fma4(acc[6], w3.x, x4); fma4(acc[7], w3.y, x4);
            fma4(acc[8], w4.x, x4); fma4(acc[9], w4.y, x4);
        }
    }

    int nl = ng * 4;
    #pragma unroll
    for (int j = 0; j < 10; ++j) {
        Rs[(nl + 0) * 44 + j0 + j] = acc[j].x;
        Rs[(nl + 1) * 44 + j0 + j] = acc[j].y;
        Rs[(nl + 2) * 44 + j0 + j] = acc[j].z;
        Rs[(nl + 3) * 44 + j0 + j] = acc[j].w;
    }
    __syncthreads();

    const float4* Rs4 = (const float4*)Rs;
    float4* out4 = (float4*)out;
    for (int i = t; i < 256 * 10; i += 256) {
        int n = i / 10, q = i - n * 10;
        int ngl = base + n;
        if (ngl < nNodes) out4[(size_t)ngl * 10 + q] = Rs4[n * 11 + q];
    }
}

// -------- launch --------
extern "C" void kernel_launch(void* const* d_in, const int* in_sizes, int n_in,
                              void* d_out, int out_size)
{
    const float* feat = (const float*)d_in[0];
    const int*   ei   = (const int*)d_in[1];     // int32 (JAX x64 disabled)
    const float* W1  = (const float*)d_in[2];
    const float* b1  = (const float*)d_in[3];
    const float* W2  = (const float*)d_in[4];
    const float* b2  = (const float*)d_in[5];
    const float* Wm1 = (const float*)d_in[6];
    const float* bm1 = (const float*)d_in[7];
    const float* Wm2 = (const float*)d_in[8];
    const float* bm2 = (const float*)d_in[9];
    float* out = (float*)d_out;

    const int N = in_sizes[0] / 64;     // 100000
    const int E = in_sizes[1] / 2;      // 1600000

    float *agg, *h1, *h2, *hmT, *wh, *wl;
    int *deg, *off, *cur, *csr, *bsum;
    cudaGetSymbolAddress((void**)&agg, g_agg);
    cudaGetSymbolAddress((void**)&h1,  g_h1);
    cudaGetSymbolAddress((void**)&h2,  g_h2);
    cudaGetSymbolAddress((void**)&hmT, g_hmT);
    cudaGetSymbolAddress((void**)&wh,  g_wh);
    cudaGetSymbolAddress((void**)&wl,  g_wl);
    cudaGetSymbolAddress((void**)&deg, g_deg);
    cudaGetSymbolAddress((void**)&off, g_off);
    cudaGetSymbolAddress((void**)&cur, g_cur);
    cudaGetSymbolAddress((void**)&csr, g_csr);
    cudaGetSymbolAddress((void**)&bsum, g_bsum);

    const int SM_GEMM = SMF_TOTAL * 4;              // 106,496 B -> 2 blocks/SM
    const int SM_MLP2 = (256 * 40 + 256 * 44) * 4;  // 86,016 B
    cudaFuncSetAttribute(combine_kernel<128>, cudaFuncAttributeMaxDynamicSharedMemorySize, SM_GEMM);
    cudaFuncSetAttribute(combine_kernel<256>, cudaFuncAttributeMaxDynamicSharedMemorySize, SM_GEMM);
    cudaFuncSetAttribute(mlp1_kernel,         cudaFuncAttributeMaxDynamicSharedMemorySize, SM_GEMM);
    cudaFuncSetAttribute(mlp2_kernel,         cudaFuncAttributeMaxDynamicSharedMemorySize, SM_MLP2);

    const int nodeBlocks = (N + 127) / 128;      // 782
    const int mlp2Blocks = (N + 255) / 256;      // 391
    const int gatherBlocks = (N + 7) / 8;        // 12500
    const int scanBlocks = (N + 1023) / 1024;    // 98
    const int edgeBlocks = (E + 255) / 256;

    // ---- CSR build (once; reused by both layers) ----
    prep1_kernel<<<2048, 256>>>(deg, N, W1, W2, Wm1, wh, wl);
    hist_kernel<<<edgeBlocks, 256>>>(ei, deg, E, N);
    scan1_kernel<<<scanBlocks, 1024>>>(deg, off, bsum, N);
    scan2_kernel<<<1, 32>>>(bsum, scanBlocks);
    scan3_kernel<<<scanBlocks, 1024>>>(off, cur, bsum, N);
    place_kernel<<<edgeBlocks, 256>>>(ei, cur, csr, E, N);

    // ---- Layer 1 ----
    gather64_kernel<<<gatherBlocks, 256>>>(off, deg, csr, feat, agg, N);
    combine_kernel<128><<<nodeBlocks, 256, SM_GEMM>>>(feat, agg, wh, wl, b1, h1, N);
    // ---- Layer 2 ----
    gather128_kernel<<<gatherBlocks, 256>>>(off, deg, csr, h1, agg, N);
    combine_kernel<256><<<nodeBlocks, 256, SM_GEMM>>>(h1, agg, wh + 16384, wl + 16384, b2, h2, N);
    // ---- MLP ----
    mlp1_kernel<<<nodeBlocks, 256, SM_GEMM>>>(h2, wh + 49152, wl + 49152, bm1, hmT, N);
    mlp2_kernel<<<mlp2Blocks, 256, SM_MLP2>>>(hmT, Wm2, bm2, out, N);
}

// round 13
// speedup vs baseline: 2.4378x; 1.3149x over previous
#include <cuda_runtime.h>
#include <math.h>
#include <stdint.h>

#define NN 100000
#define EE 1600000
#define XRS 40    // raw X tile row stride (floats): LDS.64 at exact 2-phase floor
#define FB 9216   // floats per buffer: Wpack(4096) + Xr(5120)
#define OF_XR 4096
#define SMF_TOTAL (2 * FB)   // 18,432 floats = 73,728 B -> 2 blocks/SM

// -------- scratch (device globals; no allocation allowed) --------
__device__ float g_agg[(size_t)NN * 128];
__device__ float g_h1[(size_t)NN * 128];
__device__ float g_h2[(size_t)NN * 128];
__device__ float g_hmT[(size_t)NN * 256];   // hidden MLP layer, TRANSPOSED [256][N]
__device__ float g_wp[81920];               // frag-major packed bf16 hi/lo of [W1|W2|Wm1]
__device__ int   g_deg[NN];
__device__ int   g_off[NN];
__device__ int   g_cur[NN];
__device__ int   g_csr[EE];
__device__ int   g_bsum[512];

// -------- helpers --------
__device__ __forceinline__ float sigmoidf_(float x) {
    return 1.0f / (1.0f + __expf(-x));
}
__device__ __forceinline__ void fma4(float4& a, float s, const float4& x) {
    a.x = fmaf(s, x.x, a.x); a.y = fmaf(s, x.y, a.y);
    a.z = fmaf(s, x.z, a.z); a.w = fmaf(s, x.w, a.w);
}
// split float2 into packed bf16x2 hi + bf16x2 lo (element0 -> lower half)
__device__ __forceinline__ void split2(float2 v, uint32_t& hp, uint32_t& lp) {
    asm("cvt.rn.bf16x2.f32 %0, %1, %2;" : "=r"(hp) : "f"(v.y), "f"(v.x));
    float hx = __uint_as_float(hp << 16);
    float hy = __uint_as_float(hp & 0xffff0000u);
    float lx = v.x - hx, ly = v.y - hy;
    asm("cvt.rn.bf16x2.f32 %0, %1, %2;" : "=r"(lp) : "f"(ly), "f"(lx));
}
// D += A(16x16 bf16) * B(16x8 bf16), fp32 accumulate
__device__ __forceinline__ void mma_bf16(float4& d, const uint32_t* a, uint32_t b0, uint32_t b1) {
    asm("mma.sync.aligned.m16n8k16.row.col.f32.bf16.bf16.f32 "
        "{%0,%1,%2,%3}, {%4,%5,%6,%7}, {%8,%9}, {%0,%1,%2,%3};"
        : "+f"(d.x), "+f"(d.y), "+f"(d.z), "+f"(d.w)
        : "r"(a[0]), "r"(a[1]), "r"(a[2]), "r"(a[3]), "r"(b0), "r"(b1));
}
__device__ __forceinline__ void cpasync16(uint32_t dst, const void* src, int srcsize) {
    asm volatile("cp.async.ca.shared.global [%0], [%1], 16, %2;"
                 :: "r"(dst), "l"(src), "r"(srcsize) : "memory");
}
#define CP_COMMIT() asm volatile("cp.async.commit_group;" ::: "memory")
#define CP_WAIT1()  asm volatile("cp.async.wait_group 1;" ::: "memory")

// ============================================================================
// prep: zero deg AND pack weights frag-major:
// wp layout per 128-j block: [chunk c(32k)][s(2 k16)][wn2(2)][nt(8)][lane(32)]
//   x float4 {Bh0, Bh1, Bl0, Bl1}  (bf16x2 words; element k-even in lower half)
// W1: floats [0,16384); W2: [16384,49152); Wm1(jb=0,1): [49152,81920)
// ============================================================================
__global__ void prep1_kernel(int* __restrict__ deg, int n,
                             const float* __restrict__ W1,
                             const float* __restrict__ W2,
                             const float* __restrict__ Wm1,
                             float* __restrict__ wp)
{
    int idx = blockIdx.x * blockDim.x + threadIdx.x;
    int stride = gridDim.x * blockDim.x;
    for (int i = idx; i < n; i += stride) deg[i] = 0;
    float4* wp4 = (float4*)wp;
    for (int i = idx; i < 20480; i += stride) {   // 20480 float4 units total
        const float* W; int rs, jb = 0, local;
        if (i < 4096)        { local = i;          W = W1;  rs = 128; }
        else if (i < 12288)  { local = i - 4096;   W = W2;  rs = 128; }
        else                 { local = i - 12288;  jb = local >> 12; local &= 4095; W = Wm1; rs = 256; }
        int c   = local >> 10;
        int s   = (local >> 9) & 1;
        int wn2 = (local >> 8) & 1;
        int nt  = (local >> 5) & 7;
        int l   = local & 31;
        int k0 = c * 32 + s * 16 + 2 * (l & 3);
        int j  = jb * 128 + wn2 * 64 + nt * 8 + (l >> 2);
        float v00 = W[(size_t)k0 * rs + j];
        float v01 = W[(size_t)(k0 + 1) * rs + j];
        float v10 = W[(size_t)(k0 + 8) * rs + j];
        float v11 = W[(size_t)(k0 + 9) * rs + j];
        uint32_t w0, w2, w1, w3;
        split2(make_float2(v00, v01), w0, w2);
        split2(make_float2(v10, v11), w1, w3);
        wp4[i] = make_float4(__uint_as_float(w0), __uint_as_float(w1),
                             __uint_as_float(w2), __uint_as_float(w3));
    }
}

// -------- CSR build: histogram over dst --------
__global__ void hist_kernel(const int* __restrict__ ei, int* __restrict__ deg,
                            int E, int nNodes) {
    int e = blockIdx.x * blockDim.x + threadIdx.x;
    if (e >= E) return;
    int d = ei[E + e];
    if ((unsigned)d < (unsigned)nNodes) atomicAdd(&deg[d], 1);
}

// -------- scan phase 1 --------
__global__ void scan1_kernel(const int* __restrict__ deg, int* __restrict__ off,
                             int* __restrict__ bsum, int n) {
    __shared__ int sh[1024];
    int tid = threadIdx.x;
    int i = blockIdx.x * 1024 + tid;
    int v = (i < n) ? deg[i] : 0;
    sh[tid] = v;
    __syncthreads();
    #pragma unroll
    for (int d = 1; d < 1024; d <<= 1) {
        int t = (tid >= d) ? sh[tid - d] : 0;
        __syncthreads();
        sh[tid] += t;
        __syncthreads();
    }
    if (i < n) off[i] = sh[tid] - v;
    if (tid == 1023) bsum[blockIdx.x] = sh[1023];
}

// -------- scan phase 2 --------
__global__ void scan2_kernel(int* __restrict__ bsum, int nb) {
    if (threadIdx.x == 0 && blockIdx.x == 0) {
        int acc = 0;
        for (int i = 0; i < nb; ++i) { int v = bsum[i]; bsum[i] = acc; acc += v; }
    }
}

// -------- scan phase 3 --------
__global__ void scan3_kernel(int* __restrict__ off, int* __restrict__ cur,
                             const int* __restrict__ bsum, int n) {
    int i = blockIdx.x * 1024 + threadIdx.x;
    if (i < n) {
        int o = off[i] + bsum[blockIdx.x];
        off[i] = o;
        cur[i] = o;
    }
}

// -------- CSR placement --------
__global__ void place_kernel(const int* __restrict__ ei, int* __restrict__ cur,
                             int* __restrict__ csr, int E, int nNodes) {
    int e = blockIdx.x * blockDim.x + threadIdx.x;
    if (e >= E) return;
    int s = ei[e];
    int d = ei[E + e];
    if ((unsigned)s >= (unsigned)nNodes || (unsigned)d >= (unsigned)nNodes) return;
    int pos = atomicAdd(&cur[d], 1);
    csr[pos] = s;
}

// -------- gather aggregate: warp per node --------
__global__ void __launch_bounds__(256) gather64_kernel(
    const int* __restrict__ off, const int* __restrict__ deg,
    const int* __restrict__ csr, const float* __restrict__ x,
    float* __restrict__ agg, int nNodes)
{
    int node = blockIdx.x * 8 + (threadIdx.x >> 5);
    if (node >= nNodes) return;
    int lane = threadIdx.x & 31;
    int beg = off[node], dg = deg[node];
    float2 acc = make_float2(0.f, 0.f);
    for (int e = beg; e < beg + dg; ++e) {
        int s = csr[e];
        float2 v = *(const float2*)(x + (size_t)s * 64 + lane * 2);
        acc.x += v.x; acc.y += v.y;
    }
    float sc = 1.0f / (float)max(dg, 1);
    acc.x *= sc; acc.y *= sc;
    *(float2*)(agg + (size_t)node * 64 + lane * 2) = acc;
}

__global__ void __launch_bounds__(256) gather128_kernel(
    const int* __restrict__ off, const int* __restrict__ deg,
    const int* __restrict__ csr, const float* __restrict__ x,
    float* __restrict__ agg, int nNodes)
{
    int node = blockIdx.x * 8 + (threadIdx.x >> 5);
    if (node >= nNodes) return;
    int lane = threadIdx.x & 31;
    int beg = off[node], dg = deg[node];
    float4 acc = make_float4(0.f, 0.f, 0.f, 0.f);
    for (int e = beg; e < beg + dg; ++e) {
        int s = csr[e];
        float4 v = *(const float4*)(x + (size_t)s * 128 + lane * 4);
        acc.x += v.x; acc.y += v.y; acc.z += v.z; acc.w += v.w;
    }
    float sc = 1.0f / (float)max(dg, 1);
    acc.x *= sc; acc.y *= sc; acc.z *= sc; acc.w *= sc;
    *(float4*)(agg + (size_t)node * 128 + lane * 4) = acc;
}

// ============================================================================
// GEMM mainloop body: one 32-k chunk (2 k16-steps) from buffer {Wpack, Xr}.
// A: 4x LDS.64 raw fp32 + register bf16x2 split. B: 1x LDS.128 frag per nt.
// 48 m16n8k16 bf16 mmas per k16-step (2-term compensated: hh + lh + hl).
// ============================================================================
__device__ __forceinline__ void mma_chunk(
    const float* Wp, const float* Xr,
    int wm, int wn2, int lane, float4 C0[8], float4 C1[8])
{
    const int ar = lane >> 2, ac = lane & 3;
    #pragma unroll
    for (int s = 0; s < 2; ++s) {
        uint32_t Ah[2][4], Al[2][4];
        #pragma unroll
        for (int mt = 0; mt < 2; ++mt) {
            int nb = wm + mt * 16 + ar;
            const float* xp = Xr + nb * XRS + s * 16 + 2 * ac;
            float2 p0 = *(const float2*)(xp);
            float2 p1 = *(const float2*)(xp + 8 * XRS);
            float2 p2 = *(const float2*)(xp + 8);
            float2 p3 = *(const float2*)(xp + 8 * XRS + 8);
            split2(p0, Ah[mt][0], Al[mt][0]);
            split2(p1, Ah[mt][1], Al[mt][1]);
            split2(p2, Ah[mt][2], Al[mt][2]);
            split2(p3, Ah[mt][3], Al[mt][3]);
        }
        const float4* bp = (const float4*)Wp + ((s * 2 + wn2) * 8) * 32 + lane;
        #pragma unroll
        for (int nt = 0; nt < 8; ++nt) {
            float4 bw = bp[nt * 32];
            uint32_t bh0 = __float_as_uint(bw.x), bh1 = __float_as_uint(bw.y);
            uint32_t bl0 = __float_as_uint(bw.z), bl1 = __float_as_uint(bw.w);
            mma_bf16(C0[nt], Ah[0], bh0, bh1);
            mma_bf16(C1[nt], Ah[1], bh0, bh1);
            mma_bf16(C0[nt], Al[0], bh0, bh1);
            mma_bf16(C1[nt], Al[1], bh0, bh1);
            mma_bf16(C0[nt], Ah[0], bl0, bl1);
            mma_bf16(C1[nt], Ah[1], bl0, bl1);
        }
    }
}

// ============================================================================
// combine (bf16 compensated mma, double-buffered cp.async):
// out[128n x 128j] = sigmoid(concat(self, agg) @ W + b)   (agg pre-divided)
// ============================================================================
template<int K>
__global__ void __launch_bounds__(256, 2) combine_kernel(
    const float* __restrict__ self,   // [N, K/2]
    const float* __restrict__ agg,    // [N, K/2]  (already mean)
    const float* __restrict__ wpG,    // packed W (frag-major blobs of 4096 floats/chunk)
    const float* __restrict__ b,      // [128]
    float* __restrict__ out,          // [N, 128]
    int nNodes)
{
    constexpr int SELF = K / 2;
    constexpr int NCH = K / 32;
    extern __shared__ float smf[];
    const uint32_t smBase = (uint32_t)__cvta_generic_to_shared(smf);

    const int t = threadIdx.x;
    const int lane = t & 31, warp = t >> 5;
    const int wm = (warp & 3) * 32;
    const int wn2 = warp >> 2;
    const int wn = wn2 * 64;
    const int base = blockIdx.x * 128;
    const int ar = lane >> 2, ac = lane & 3;

    float4 C0[8], C1[8];
    #pragma unroll
    for (int nt = 0; nt < 8; ++nt) {
        int j = wn + nt * 8 + 2 * ac;
        float bx = b[j], by = b[j + 1];
        C0[nt] = make_float4(bx, by, bx, by);
        C1[nt] = make_float4(bx, by, bx, by);
    }

    auto prefetch = [&](int ch, int buf) {
        const uint32_t bb = smBase + (uint32_t)(buf * FB) * 4;
        // X: 4 granules/thread into Xr
        int g = t & 7;
        int kg = ch * 32 + g * 4;
        const float* src0 = (kg < SELF) ? (self + kg) : (agg + (kg - SELF));
        #pragma unroll
        for (int it = 0; it < 4; ++it) {
            int n = (t >> 3) + 32 * it;
            int ngl = base + n;
            int sz = (ngl < nNodes) ? 16 : 0;
            cpasync16(bb + (uint32_t)(OF_XR + n * XRS + g * 4) * 4,
                      src0 + (size_t)ngl * SELF, sz);
        }
        // W pack: 4 granules/thread (4096 floats = 1024 granules)
        const float* wsrc = wpG + (size_t)ch * 4096;
        #pragma unroll
        for (int r = 0; r < 4; ++r) {
            int i = t + 256 * r;
            cpasync16(bb + (uint32_t)(i * 4) * 4, wsrc + i * 4, 16);
        }
    };

    prefetch(0, 0); CP_COMMIT();

    for (int ch = 0; ch < NCH; ++ch) {
        __syncthreads();
        if (ch + 1 < NCH) prefetch(ch + 1, (ch + 1) & 1);
        CP_COMMIT();
        CP_WAIT1();
        __syncthreads();
        const float* bufp = smf + (ch & 1) * FB;
        mma_chunk(bufp, bufp + OF_XR, wm, wn2, lane, C0, C1);
    }
    __syncthreads();   // buffers free; reuse smem as staging

    float* Rs = smf;   // [128 node][132]
    #pragma unroll
    for (int mt = 0; mt < 2; ++mt) {
        int row = wm + mt * 16 + ar;
        float4* Cm = (mt == 0) ? C0 : C1;
        #pragma unroll
        for (int nt = 0; nt < 8; ++nt) {
            int col = wn + nt * 8 + 2 * ac;
            float4 c = Cm[nt];
            *(float2*)(Rs + row * 132 + col)       = make_float2(sigmoidf_(c.x), sigmoidf_(c.y));
            *(float2*)(Rs + (row + 8) * 132 + col) = make_float2(sigmoidf_(c.z), sigmoidf_(c.w));
        }
    }
    __syncthreads();

    const float4* Rs4 = (const float4*)Rs;
    float4* out4 = (float4*)out;
    for (int i = t; i < 128 * 32; i += 256) {
        int n = i >> 5, q = i & 31;
        int ngl = base + n;
        if (ngl < nNodes) out4[(size_t)ngl * 32 + q] = Rs4[n * 33 + q];
    }
}

// ============================================================================
// mlp1 (bf16 compensated mma, double-buffered): hmT[j][n] = relu(h2 @ Wm1 + bm1)
// ============================================================================
__global__ void __launch_bounds__(256, 2) mlp1_kernel(
    const float* __restrict__ h2,     // [N, 128]
    const float* __restrict__ wpG,    // packed Wm1 (2 jb blobs of 16384 floats)
    const float* __restrict__ bm1,    // [256]
    float* __restrict__ hmT,          // [256][N]
    int nNodes)
{
    extern __shared__ float smf[];
    const uint32_t smBase = (uint32_t)__cvta_generic_to_shared(smf);

    const int t = threadIdx.x;
    const int lane = t & 31, warp = t >> 5;
    const int wm = (warp & 3) * 32;
    const int wn2 = warp >> 2;
    const int wn = wn2 * 64;
    const int base = blockIdx.x * 128;
    const int ar = lane >> 2, ac = lane & 3;

    auto prefetch = [&](int pass, int ch, int buf) {
        const uint32_t bb = smBase + (uint32_t)(buf * FB) * 4;
        int g = t & 7;
        int col = ch * 32 + g * 4;
        #pragma unroll
        for (int it = 0; it < 4; ++it) {
            int n = (t >> 3) + 32 * it;
            int ngl = base + n;
            int sz = (ngl < nNodes) ? 16 : 0;
            cpasync16(bb + (uint32_t)(OF_XR + n * XRS + g * 4) * 4,
                      h2 + (size_t)ngl * 128 + col, sz);
        }
        const float* wsrc = wpG + (size_t)pass * 16384 + (size_t)ch * 4096;
        #pragma unroll
        for (int r = 0; r < 4; ++r) {
            int i = t + 256 * r;
            cpasync16(bb + (uint32_t)(i * 4) * 4, wsrc + i * 4, 16);
        }
    };

    for (int pass = 0; pass < 2; ++pass) {
        float4 C0[8], C1[8];
        #pragma unroll
        for (int nt = 0; nt < 8; ++nt) {
            int j = pass * 128 + wn + nt * 8 + 2 * ac;
            float bx = bm1[j], by = bm1[j + 1];
            C0[nt] = make_float4(bx, by, bx, by);
            C1[nt] = make_float4(bx, by, bx, by);
        }

        prefetch(pass, 0, 0); CP_COMMIT();
        for (int ch = 0; ch < 4; ++ch) {
            __syncthreads();
            if (ch + 1 < 4) prefetch(pass, ch + 1, (ch + 1) & 1);
            CP_COMMIT();
            CP_WAIT1();
            __syncthreads();
            const float* bufp = smf + (ch & 1) * FB;
            mma_chunk(bufp, bufp + OF_XR, wm, wn2, lane, C0, C1);
        }
        __syncthreads();   // pipeline drained; buffers free for staging

        float* Rs = smf;   // [128 j][132] transposed staging
        #pragma unroll
        for (int mt = 0; mt < 2; ++mt) {
            int row = wm + mt * 16 + ar;   // node
            float4* Cm = (mt == 0) ? C0 : C1;
            #pragma unroll
            for (int nt = 0; nt < 8; ++nt) {
                int col = wn + nt * 8 + 2 * ac;   // j
                float4 c = Cm[nt];
                Rs[col * 132 + row]           = fmaxf(c.x, 0.f);
                Rs[(col + 1) * 132 + row]     = fmaxf(c.y, 0.f);
                Rs[col * 132 + row + 8]       = fmaxf(c.z, 0.f);
                Rs[(col + 1) * 132 + row + 8] = fmaxf(c.w, 0.f);
            }
        }
        __syncthreads();
        if (base + 128 <= nNodes) {
            const float4* Rs4 = (const float4*)Rs;
            for (int i = t; i < 128 * 32; i += 256) {
                int j = i >> 5, q = i & 31;
                *(float4*)(hmT + (size_t)(pass * 128 + j) * nNodes + base + 4 * q) = Rs4[j * 33 + q];
            }
        } else {
            for (int i = t; i < 128 * 128; i += 256) {
                int j = i >> 7, n = i & 127;
                if (base + n < nNodes)
                    hmT[(size_t)(pass * 128 + j) * nNodes + base + n] = Rs[j * 132 + n];
            }
        }
        __syncthreads();   // writeout done before next pass's prefetch overwrites
    }
}

// ============================================================================
// mlp2: out = hmT^T @ Wm2 + bm2  (K=256, NOUT=40) — scalar path
// ============================================================================
__global__ void __launch_bounds__(256) mlp2_kernel(
    const float* __restrict__ hmT,    // [256][N]
    const float* __restrict__ Wm2,    // [256, 40]
    const float* __restrict__ bm2,    // [40]
    float* __restrict__ out,          // [N, 40]
    int nNodes)
{
    extern __shared__ float smf[];
    float* Ws = smf;                  // [256][40]
    float* Rs = smf + 256 * 40;       // [256][44]

    const int t = threadIdx.x;
    const int base = blockIdx.x * 256;
    const int ng = t & 63;
    const int og = t >> 6;
    const int n0 = base + ng * 4;
    const int j0 = og * 10;

    {
        const float4* Wg = (const float4*)Wm2;
        float4* Ws4 = (float4*)Ws;
        for (int i = t; i < 2560; i += 256) Ws4[i] = Wg[i];
    }
    __syncthreads();

    float4 acc[10];
    #pragma unroll
    for (int j = 0; j < 10; ++j) {
        float bv = bm2[j0 + j];
        acc[j] = make_float4(bv, bv, bv, bv);
    }

    if (n0 + 3 < nNodes) {
        #pragma unroll 2
        for (int k = 0; k < 256; ++k) {
            float4 x4 = *(const float4*)(hmT + (size_t)k * nNodes + n0);
            const float2* wr = (const float2*)(Ws + k * 40 + j0);
            float2 w0 = wr[0], w1 = wr[1], w2 = wr[2], w3 = wr[3], w4 = wr[4];
            fma4(acc[0], w0.x, x4); fma4(acc[1], w0.y, x4);
            fma4(acc[2], w1.x, x4); fma4(acc[3], w1.y, x4);
            fma4(acc[4], w2.x, x4); fma4(acc[5], w2.y, x4);
            fma4(acc[6], w3.x, x4); fma4(acc[7], w3.y, x4);
            fma4(acc[8], w4.x, x4); fma4(acc[9], w4.y, x4);
        }
    } else {
        for (int k = 0; k < 256; ++k) {
            float4 x4;
            const float* row = hmT + (size_t)k * nNodes;
            x4.x = (n0 + 0 < nNodes) ? row[n0 + 0] : 0.f;
            x4.y = (n0 + 1 < nNodes) ? row[n0 + 1] : 0.f;
            x4.z = (n0 + 2 < nNodes) ? row[n0 + 2] : 0.f;
            x4.w = (n0 + 3 < nNodes) ? row[n0 + 3] : 0.f;
            const float2* wr = (const float2*)(Ws + k * 40 + j0);
            float2 w0 = wr[0], w1 = wr[1], w2 = wr[2], w3 = wr[3], w4 = wr[4];
            fma4(acc[0], w0.x, x4); fma4(acc[1], w0.y, x4);
            fma4(acc[2], w1.x, x4); fma4(acc[3], w1.y, x4);
            fma4(acc[4], w2.x, x4); fma4(acc[5], w2.y, x4);
            fma4(acc[6], w3.x, x4); fma4(acc[7], w3.y, x4);
            fma4(acc[8], w4.x, x4); fma4(acc[9], w4.y, x4);
        }
    }

    int nl = ng * 4;
    #pragma unroll
    for (int j = 0; j < 10; ++j) {
        Rs[(nl + 0) * 44 + j0 + j] = acc[j].x;
        Rs[(nl + 1) * 44 + j0 + j] = acc[j].y;
        Rs[(nl + 2) * 44 + j0 + j] = acc[j].z;
        Rs[(nl + 3) * 44 + j0 + j] = acc[j].w;
    }
    __syncthreads();

    const float4* Rs4 = (const float4*)Rs;
    float4* out4 = (float4*)out;
    for (int i = t; i < 256 * 10; i += 256) {
        int n = i / 10, q = i - n * 10;
        int ngl = base + n;
        if (ngl < nNodes) out4[(size_t)ngl * 10 + q] = Rs4[n * 11 + q];
    }
}

// -------- launch --------
extern "C" void kernel_launch(void* const* d_in, const int* in_sizes, int n_in,
                              void* d_out, int out_size)
{
    const float* feat = (const float*)d_in[0];
    const int*   ei   = (const int*)d_in[1];     // int32 (JAX x64 disabled)
    const float* W1  = (const float*)d_in[2];
    const float* b1  = (const float*)d_in[3];
    const float* W2  = (const float*)d_in[4];
    const float* b2  = (const float*)d_in[5];
    const float* Wm1 = (const float*)d_in[6];
    const float* bm1 = (const float*)d_in[7];
    const float* Wm2 = (const float*)d_in[8];
    const float* bm2 = (const float*)d_in[9];
    float* out = (float*)d_out;

    const int N = in_sizes[0] / 64;     // 100000
    const int E = in_sizes[1] / 2;      // 1600000

    float *agg, *h1, *h2, *hmT, *wp;
    int *deg, *off, *cur, *csr, *bsum;
    cudaGetSymbolAddress((void**)&agg, g_agg);
    cudaGetSymbolAddress((void**)&h1,  g_h1);
    cudaGetSymbolAddress((void**)&h2,  g_h2);
    cudaGetSymbolAddress((void**)&hmT, g_hmT);
    cudaGetSymbolAddress((void**)&wp,  g_wp);
    cudaGetSymbolAddress((void**)&deg, g_deg);
    cudaGetSymbolAddress((void**)&off, g_off);
    cudaGetSymbolAddress((void**)&cur, g_cur);
    cudaGetSymbolAddress((void**)&csr, g_csr);
    cudaGetSymbolAddress((void**)&bsum, g_bsum);

    const int SM_GEMM = SMF_TOTAL * 4;              // 73,728 B -> 2 blocks/SM
    const int SM_MLP2 = (256 * 40 + 256 * 44) * 4;  // 86,016 B
    cudaFuncSetAttribute(combine_kernel<128>, cudaFuncAttributeMaxDynamicSharedMemorySize, SM_GEMM);
    cudaFuncSetAttribute(combine_kernel<256>, cudaFuncAttributeMaxDynamicSharedMemorySize, SM_GEMM);
    cudaFuncSetAttribute(mlp1_kernel,         cudaFuncAttributeMaxDynamicSharedMemorySize, SM_GEMM);
    cudaFuncSetAttribute(mlp2_kernel,         cudaFuncAttributeMaxDynamicSharedMemorySize, SM_MLP2);

    const int nodeBlocks = (N + 127) / 128;      // 782
    const int mlp2Blocks = (N + 255) / 256;      // 391
    const int gatherBlocks = (N + 7) / 8;        // 12500
    const int scanBlocks = (N + 1023) / 1024;    // 98
    const int edgeBlocks = (E + 255) / 256;

    // ---- CSR build (once; reused by both layers) + W packing ----
    prep1_kernel<<<2048, 256>>>(deg, N, W1, W2, Wm1, wp);
    hist_kernel<<<edgeBlocks, 256>>>(ei, deg, E, N);
    scan1_kernel<<<scanBlocks, 1024>>>(deg, off, bsum, N);
    scan2_kernel<<<1, 32>>>(bsum, scanBlocks);
    scan3_kernel<<<scanBlocks, 1024>>>(off, cur, bsum, N);
    place_kernel<<<edgeBlocks, 256>>>(ei, cur, csr, E, N);

    // ---- Layer 1 ----
    gather64_kernel<<<gatherBlocks, 256>>>(off, deg, csr, feat, agg, N);
    combine_kernel<128><<<nodeBlocks, 256, SM_GEMM>>>(feat, agg, wp, b1, h1, N);
    // ---- Layer 2 ----
    gather128_kernel<<<gatherBlocks, 256>>>(off, deg, csr, h1, agg, N);
    combine_kernel<256><<<nodeBlocks, 256, SM_GEMM>>>(h1, agg, wp + 16384, b2, h2, N);
    // ---- MLP ----
    mlp1_kernel<<<nodeBlocks, 256, SM_GEMM>>>(h2, wp + 49152, bm1, hmT, N);
    mlp2_kernel<<<mlp2Blocks, 256, SM_MLP2>>>(hmT, Wm2, bm2, out, N);
}

// round 14
// speedup vs baseline: 3.7046x; 1.5196x over previous
#include <cuda_runtime.h>
#include <math.h>
#include <stdint.h>

#define NN 100000
#define EE 1600000
#define XRS 40    // raw X tile row stride (floats): LDS.64 at exact 2-phase floor
#define FB 9216   // floats per buffer: Wpack(4096) + Xr(5120)
#define OF_XR 4096
#define SMF_TOTAL (2 * FB)   // 18,432 floats = 73,728 B -> 2 blocks/SM

// -------- scratch (device globals; no allocation allowed) --------
__device__ float g_agg[(size_t)NN * 128];
__device__ float g_h1[(size_t)NN * 128];
__device__ float g_h2[(size_t)NN * 128];
__device__ float g_wp[92160];   // frag-major packed bf16 hi/lo of [W1|W2|Wm1|Wm2]
__device__ int   g_deg[NN];
__device__ int   g_off[NN];
__device__ int   g_cur[NN];
__device__ int   g_csr[EE];
__device__ int   g_bsum[512];

// -------- helpers --------
__device__ __forceinline__ float sigmoidf_(float x) {
    return 1.0f / (1.0f + __expf(-x));
}
// split float2 into packed bf16x2 hi + bf16x2 lo (element0 -> lower half)
__device__ __forceinline__ void split2(float2 v, uint32_t& hp, uint32_t& lp) {
    asm("cvt.rn.bf16x2.f32 %0, %1, %2;" : "=r"(hp) : "f"(v.y), "f"(v.x));
    float hx = __uint_as_float(hp << 16);
    float hy = __uint_as_float(hp & 0xffff0000u);
    float lx = v.x - hx, ly = v.y - hy;
    asm("cvt.rn.bf16x2.f32 %0, %1, %2;" : "=r"(lp) : "f"(ly), "f"(lx));
}
// D += A(16x16 bf16) * B(16x8 bf16), fp32 accumulate
__device__ __forceinline__ void mma_bf16(float4& d, const uint32_t* a, uint32_t b0, uint32_t b1) {
    asm("mma.sync.aligned.m16n8k16.row.col.f32.bf16.bf16.f32 "
        "{%0,%1,%2,%3}, {%4,%5,%6,%7}, {%8,%9}, {%0,%1,%2,%3};"
        : "+f"(d.x), "+f"(d.y), "+f"(d.z), "+f"(d.w)
        : "r"(a[0]), "r"(a[1]), "r"(a[2]), "r"(a[3]), "r"(b0), "r"(b1));
}
__device__ __forceinline__ void cpasync16(uint32_t dst, const void* src, int srcsize) {
    asm volatile("cp.async.ca.shared.global [%0], [%1], 16, %2;"
                 :: "r"(dst), "l"(src), "r"(srcsize) : "memory");
}
#define CP_COMMIT() asm volatile("cp.async.commit_group;" ::: "memory")
#define CP_WAIT1()  asm volatile("cp.async.wait_group 1;" ::: "memory")

// ============================================================================
// prep: zero deg AND pack weights frag-major (bf16 hi/lo, mma-lane layout):
// per 128-j block: [chunk c(32k)][s(2 k16)][wn2(2)][nt(8)][lane(32)]
//   x float4 {Bh0, Bh1, Bl0, Bl1}
// W1: f4 units [0,4096); W2: [4096,12288); Wm1: [12288,20480); Wm2: [20480,23040)
// Wm2 pack layout: [sg(16 k16-steps)][nt(5)][lane(32)]
// ============================================================================
__global__ void prep1_kernel(int* __restrict__ deg, int n,
                             const float* __restrict__ W1,
                             const float* __restrict__ W2,
                             const float* __restrict__ Wm1,
                             const float* __restrict__ Wm2,
                             float* __restrict__ wp)
{
    int idx = blockIdx.x * blockDim.x + threadIdx.x;
    int stride = gridDim.x * blockDim.x;
    for (int i = idx; i < n; i += stride) deg[i] = 0;
    float4* wp4 = (float4*)wp;
    for (int i = idx; i < 23040; i += stride) {
        const float* W; int rs, k0, j;
        if (i < 20480) {
            int jb = 0, local;
            if (i < 4096)        { local = i;          W = W1;  rs = 128; }
            else if (i < 12288)  { local = i - 4096;   W = W2;  rs = 128; }
            else                 { local = i - 12288;  jb = local >> 12; local &= 4095; W = Wm1; rs = 256; }
            int c   = local >> 10;
            int s   = (local >> 9) & 1;
            int wn2 = (local >> 8) & 1;
            int nt  = (local >> 5) & 7;
            int l   = local & 31;
            k0 = c * 32 + s * 16 + 2 * (l & 3);
            j  = jb * 128 + wn2 * 64 + nt * 8 + (l >> 2);
        } else {
            int local = i - 20480;          // [sg(16)][nt(5)][lane(32)]
            int sg  = local / 160;
            int rem = local - sg * 160;
            int nt  = rem >> 5;
            int l   = rem & 31;
            W = Wm2; rs = 40;
            k0 = sg * 16 + 2 * (l & 3);
            j  = nt * 8 + (l >> 2);
        }
        float v00 = W[(size_t)k0 * rs + j];
        float v01 = W[(size_t)(k0 + 1) * rs + j];
        float v10 = W[(size_t)(k0 + 8) * rs + j];
        float v11 = W[(size_t)(k0 + 9) * rs + j];
        uint32_t w0, w2, w1, w3;
        split2(make_float2(v00, v01), w0, w2);
        split2(make_float2(v10, v11), w1, w3);
        wp4[i] = make_float4(__uint_as_float(w0), __uint_as_float(w1),
                             __uint_as_float(w2), __uint_as_float(w3));
    }
}

// -------- CSR build: histogram over dst --------
__global__ void hist_kernel(const int* __restrict__ ei, int* __restrict__ deg,
                            int E, int nNodes) {
    int e = blockIdx.x * blockDim.x + threadIdx.x;
    if (e >= E) return;
    int d = ei[E + e];
    if ((unsigned)d < (unsigned)nNodes) atomicAdd(&deg[d], 1);
}

// -------- scan phase 1 --------
__global__ void scan1_kernel(const int* __restrict__ deg, int* __restrict__ off,
                             int* __restrict__ bsum, int n) {
    __shared__ int sh[1024];
    int tid = threadIdx.x;
    int i = blockIdx.x * 1024 + tid;
    int v = (i < n) ? deg[i] : 0;
    sh[tid] = v;
    __syncthreads();
    #pragma unroll
    for (int d = 1; d < 1024; d <<= 1) {
        int t = (tid >= d) ? sh[tid - d] : 0;
        __syncthreads();
        sh[tid] += t;
        __syncthreads();
    }
    if (i < n) off[i] = sh[tid] - v;
    if (tid == 1023) bsum[blockIdx.x] = sh[1023];
}

// -------- scan phase 2 --------
__global__ void scan2_kernel(int* __restrict__ bsum, int nb) {
    if (threadIdx.x == 0 && blockIdx.x == 0) {
        int acc = 0;
        for (int i = 0; i < nb; ++i) { int v = bsum[i]; bsum[i] = acc; acc += v; }
    }
}

// -------- scan phase 3 --------
__global__ void scan3_kernel(int* __restrict__ off, int* __restrict__ cur,
                             const int* __restrict__ bsum, int n) {
    int i = blockIdx.x * 1024 + threadIdx.x;
    if (i < n) {
        int o = off[i] + bsum[blockIdx.x];
        off[i] = o;
        cur[i] = o;
    }
}

// -------- CSR placement --------
__global__ void place_kernel(const int* __restrict__ ei, int* __restrict__ cur,
                             int* __restrict__ csr, int E, int nNodes) {
    int e = blockIdx.x * blockDim.x + threadIdx.x;
    if (e >= E) return;
    int s = ei[e];
    int d = ei[E + e];
    if ((unsigned)s >= (unsigned)nNodes || (unsigned)d >= (unsigned)nNodes) return;
    int pos = atomicAdd(&cur[d], 1);
    csr[pos] = s;
}

// -------- gather aggregate: warp per node --------
__global__ void __launch_bounds__(256) gather64_kernel(
    const int* __restrict__ off, const int* __restrict__ deg,
    const int* __restrict__ csr, const float* __restrict__ x,
    float* __restrict__ agg, int nNodes)
{
    int node = blockIdx.x * 8 + (threadIdx.x >> 5);
    if (node >= nNodes) return;
    int lane = threadIdx.x & 31;
    int beg = off[node], dg = deg[node];
    float2 acc = make_float2(0.f, 0.f);
    for (int e = beg; e < beg + dg; ++e) {
        int s = csr[e];
        float2 v = *(const float2*)(x + (size_t)s * 64 + lane * 2);
        acc.x += v.x; acc.y += v.y;
    }
    float sc = 1.0f / (float)max(dg, 1);
    acc.x *= sc; acc.y *= sc;
    *(float2*)(agg + (size_t)node * 64 + lane * 2) = acc;
}

__global__ void __launch_bounds__(256) gather128_kernel(
    const int* __restrict__ off, const int* __restrict__ deg,
    const int* __restrict__ csr, const float* __restrict__ x,
    float* __restrict__ agg, int nNodes)
{
    int node = blockIdx.x * 8 + (threadIdx.x >> 5);
    if (node >= nNodes) return;
    int lane = threadIdx.x & 31;
    int beg = off[node], dg = deg[node];
    float4 acc = make_float4(0.f, 0.f, 0.f, 0.f);
    for (int e = beg; e < beg + dg; ++e) {
        int s = csr[e];
        float4 v = *(const float4*)(x + (size_t)s * 128 + lane * 4);
        acc.x += v.x; acc.y += v.y; acc.z += v.z; acc.w += v.w;
    }
    float sc = 1.0f / (float)max(dg, 1);
    acc.x *= sc; acc.y *= sc; acc.z *= sc; acc.w *= sc;
    *(float4*)(agg + (size_t)node * 128 + lane * 4) = acc;
}

// ============================================================================
// GEMM mainloop body: one 32-k chunk (2 k16-steps) from buffer {Wpack, Xr}.
// ============================================================================
__device__ __forceinline__ void mma_chunk(
    const float* Wp, const float* Xr,
    int wm, int wn2, int lane, float4 C0[8], float4 C1[8])
{
    const int ar = lane >> 2, ac = lane & 3;
    #pragma unroll
    for (int s = 0; s < 2; ++s) {
        uint32_t Ah[2][4], Al[2][4];
        #pragma unroll
        for (int mt = 0; mt < 2; ++mt) {
            int nb = wm + mt * 16 + ar;
            const float* xp = Xr + nb * XRS + s * 16 + 2 * ac;
            float2 p0 = *(const float2*)(xp);
            float2 p1 = *(const float2*)(xp + 8 * XRS);
            float2 p2 = *(const float2*)(xp + 8);
            float2 p3 = *(const float2*)(xp + 8 * XRS + 8);
            split2(p0, Ah[mt][0], Al[mt][0]);
            split2(p1, Ah[mt][1], Al[mt][1]);
            split2(p2, Ah[mt][2], Al[mt][2]);
            split2(p3, Ah[mt][3], Al[mt][3]);
        }
        const float4* bp = (const float4*)Wp + ((s * 2 + wn2) * 8) * 32 + lane;
        #pragma unroll
        for (int nt = 0; nt < 8; ++nt) {
            float4 bw = bp[nt * 32];
            uint32_t bh0 = __float_as_uint(bw.x), bh1 = __float_as_uint(bw.y);
            uint32_t bl0 = __float_as_uint(bw.z), bl1 = __float_as_uint(bw.w);
            mma_bf16(C0[nt], Ah[0], bh0, bh1);
            mma_bf16(C1[nt], Ah[1], bh0, bh1);
            mma_bf16(C0[nt], Al[0], bh0, bh1);
            mma_bf16(C1[nt], Al[1], bh0, bh1);
            mma_bf16(C0[nt], Ah[0], bl0, bl1);
            mma_bf16(C1[nt], Ah[1], bl0, bl1);
        }
    }
}

// ============================================================================
// combine (bf16 compensated mma, double-buffered cp.async):
// out[128n x 128j] = sigmoid(concat(self, agg) @ W + b)   (agg pre-divided)
// ============================================================================
template<int K>
__global__ void __launch_bounds__(256, 2) combine_kernel(
    const float* __restrict__ self,   // [N, K/2]
    const float* __restrict__ agg,    // [N, K/2]  (already mean)
    const float* __restrict__ wpG,    // packed W (frag-major blobs of 4096 floats/chunk)
    const float* __restrict__ b,      // [128]
    float* __restrict__ out,          // [N, 128]
    int nNodes)
{
    constexpr int SELF = K / 2;
    constexpr int NCH = K / 32;
    extern __shared__ float smf[];
    const uint32_t smBase = (uint32_t)__cvta_generic_to_shared(smf);

    const int t = threadIdx.x;
    const int lane = t & 31, warp = t >> 5;
    const int wm = (warp & 3) * 32;
    const int wn2 = warp >> 2;
    const int wn = wn2 * 64;
    const int base = blockIdx.x * 128;
    const int ar = lane >> 2, ac = lane & 3;

    float4 C0[8], C1[8];
    #pragma unroll
    for (int nt = 0; nt < 8; ++nt) {
        int j = wn + nt * 8 + 2 * ac;
        float bx = b[j], by = b[j + 1];
        C0[nt] = make_float4(bx, by, bx, by);
        C1[nt] = make_float4(bx, by, bx, by);
    }

    auto prefetch = [&](int ch, int buf) {
        const uint32_t bb = smBase + (uint32_t)(buf * FB) * 4;
        int g = t & 7;
        int kg = ch * 32 + g * 4;
        const float* src0 = (kg < SELF) ? (self + kg) : (agg + (kg - SELF));
        #pragma unroll
        for (int it = 0; it < 4; ++it) {
            int n = (t >> 3) + 32 * it;
            int ngl = base + n;
            int sz = (ngl < nNodes) ? 16 : 0;
            cpasync16(bb + (uint32_t)(OF_XR + n * XRS + g * 4) * 4,
                      src0 + (size_t)ngl * SELF, sz);
        }
        const float* wsrc = wpG + (size_t)ch * 4096;
        #pragma unroll
        for (int r = 0; r < 4; ++r) {
            int i = t + 256 * r;
            cpasync16(bb + (uint32_t)(i * 4) * 4, wsrc + i * 4, 16);
        }
    };

    prefetch(0, 0); CP_COMMIT();

    for (int ch = 0; ch < NCH; ++ch) {
        __syncthreads();
        if (ch + 1 < NCH) prefetch(ch + 1, (ch + 1) & 1);
        CP_COMMIT();
        CP_WAIT1();
        __syncthreads();
        const float* bufp = smf + (ch & 1) * FB;
        mma_chunk(bufp, bufp + OF_XR, wm, wn2, lane, C0, C1);
    }
    __syncthreads();   // buffers free; reuse smem as staging

    float* Rs = smf;   // [128 node][132]
    #pragma unroll
    for (int mt = 0; mt < 2; ++mt) {
        int row = wm + mt * 16 + ar;
        float4* Cm = (mt == 0) ? C0 : C1;
        #pragma unroll
        for (int nt = 0; nt < 8; ++nt) {
            int col = wn + nt * 8 + 2 * ac;
            float4 c = Cm[nt];
            *(float2*)(Rs + row * 132 + col)       = make_float2(sigmoidf_(c.x), sigmoidf_(c.y));
            *(float2*)(Rs + (row + 8) * 132 + col) = make_float2(sigmoidf_(c.z), sigmoidf_(c.w));
        }
    }
    __syncthreads();

    const float4* Rs4 = (const float4*)Rs;
    float4* out4 = (float4*)out;
    for (int i = t; i < 128 * 32; i += 256) {
        int n = i >> 5, q = i & 31;
        int ngl = base + n;
        if (ngl < nNodes) out4[(size_t)ngl * 32 + q] = Rs4[n * 33 + q];
    }
}

// ============================================================================
// mlp fused (bf16 compensated mma): out = relu(h2 @ Wm1 + bm1) @ Wm2 + bm2
// Per pass (2 x 128 hidden cols): mainloop -> C, stage relu(C) transposed in
// smem Rs[j][132], then SECOND GEMM accumulates O += split(Rs) @ Wm2pack.
// No hidden-layer global round-trip; mlp2 kernel eliminated.
// Warp layout stage2: warp w -> nodes [w*16, w*16+16), all 40 outs.
// ============================================================================
__global__ void __launch_bounds__(256, 2) mlp_fused_kernel(
    const float* __restrict__ h2,     // [N, 128]
    const float* __restrict__ wpG,    // packed Wm1 (2 jb blobs of 16384 floats)
    const float* __restrict__ bm1,    // [256]
    const float* __restrict__ wp2G,   // packed Wm2 [16 sg][5 nt][32 lane] float4
    const float* __restrict__ bm2,    // [40]
    float* __restrict__ out,          // [N, 40]
    int nNodes)
{
    extern __shared__ float smf[];
    const uint32_t smBase = (uint32_t)__cvta_generic_to_shared(smf);

    const int t = threadIdx.x;
    const int lane = t & 31, warp = t >> 5;
    const int wm = (warp & 3) * 32;
    const int wn2 = warp >> 2;
    const int wn = wn2 * 64;
    const int base = blockIdx.x * 128;
    const int ar = lane >> 2, ac = lane & 3;

    auto prefetch = [&](int pass, int ch, int buf) {
        const uint32_t bb = smBase + (uint32_t)(buf * FB) * 4;
        int g = t & 7;
        int col = ch * 32 + g * 4;
        #pragma unroll
        for (int it = 0; it < 4; ++it) {
            int n = (t >> 3) + 32 * it;
            int ngl = base + n;
            int sz = (ngl < nNodes) ? 16 : 0;
            cpasync16(bb + (uint32_t)(OF_XR + n * XRS + g * 4) * 4,
                      h2 + (size_t)ngl * 128 + col, sz);
        }
        const float* wsrc = wpG + (size_t)pass * 16384 + (size_t)ch * 4096;
        #pragma unroll
        for (int r = 0; r < 4; ++r) {
            int i = t + 256 * r;
            cpasync16(bb + (uint32_t)(i * 4) * 4, wsrc + i * 4, 16);
        }
    };

    // persistent output accumulators: 16 nodes x 40 outs per warp
    float4 O[5];
    #pragma unroll
    for (int nt = 0; nt < 5; ++nt) {
        int j = nt * 8 + 2 * ac;
        float bx = bm2[j], by = bm2[j + 1];
        O[nt] = make_float4(bx, by, bx, by);
    }

    for (int pass = 0; pass < 2; ++pass) {
        float4 C0[8], C1[8];
        #pragma unroll
        for (int nt = 0; nt < 8; ++nt) {
            int j = pass * 128 + wn + nt * 8 + 2 * ac;
            float bx = bm1[j], by = bm1[j + 1];
            C0[nt] = make_float4(bx, by, bx, by);
            C1[nt] = make_float4(bx, by, bx, by);
        }

        prefetch(pass, 0, 0); CP_COMMIT();
        for (int ch = 0; ch < 4; ++ch) {
            __syncthreads();
            if (ch + 1 < 4) prefetch(pass, ch + 1, (ch + 1) & 1);
            CP_COMMIT();
            CP_WAIT1();
            __syncthreads();
            const float* bufp = smf + (ch & 1) * FB;
            mma_chunk(bufp, bufp + OF_XR, wm, wn2, lane, C0, C1);
        }
        __syncthreads();   // pipeline drained; buffers free for staging

        float* Rs = smf;   // [128 j][132] transposed hidden staging (relu applied)
        #pragma unroll
        for (int mt = 0; mt < 2; ++mt) {
            int row = wm + mt * 16 + ar;   // node
            float4* Cm = (mt == 0) ? C0 : C1;
            #pragma unroll
            for (int nt = 0; nt < 8; ++nt) {
                int col = wn + nt * 8 + 2 * ac;   // j (hidden)
                float4 c = Cm[nt];
                Rs[col * 132 + row]           = fmaxf(c.x, 0.f);
                Rs[(col + 1) * 132 + row]     = fmaxf(c.y, 0.f);
                Rs[col * 132 + row + 8]       = fmaxf(c.z, 0.f);
                Rs[(col + 1) * 132 + row + 8] = fmaxf(c.w, 0.f);
            }
        }
        __syncthreads();

        // ---- second GEMM: O += hm(this pass's 128 k) @ Wm2 ----
        {
            const int n0 = warp * 16 + ar;   // this thread's node rows (and +8)
            const float4* wp2f = (const float4*)wp2G;
            #pragma unroll
            for (int s = 0; s < 8; ++s) {
                const int ko = s * 16 + 2 * ac;
                const float* rp = Rs + n0;
                float2 p0 = make_float2(rp[ko * 132],        rp[(ko + 1) * 132]);
                float2 p1 = make_float2(rp[ko * 132 + 8],    rp[(ko + 1) * 132 + 8]);
                float2 p2 = make_float2(rp[(ko + 8) * 132],  rp[(ko + 9) * 132]);
                float2 p3 = make_float2(rp[(ko + 8) * 132 + 8], rp[(ko + 9) * 132 + 8]);
                uint32_t Ah[4], Al[4];
                split2(p0, Ah[0], Al[0]);
                split2(p1, Ah[1], Al[1]);
                split2(p2, Ah[2], Al[2]);
                split2(p3, Ah[3], Al[3]);
                const int sg = pass * 8 + s;
                #pragma unroll
                for (int nt = 0; nt < 5; ++nt) {
                    float4 bw = __ldg(wp2f + (sg * 5 + nt) * 32 + lane);
                    uint32_t bh0 = __float_as_uint(bw.x), bh1 = __float_as_uint(bw.y);
                    uint32_t bl0 = __float_as_uint(bw.z), bl1 = __float_as_uint(bw.w);
                    mma_bf16(O[nt], Ah, bh0, bh1);
                    mma_bf16(O[nt], Al, bh0, bh1);
                    mma_bf16(O[nt], Ah, bl0, bl1);
                }
            }
        }
        __syncthreads();   // stage-2 reads done before next pass's prefetch overwrites
    }

    // ---- final epilogue: stage O [128 node][44], coalesced write ----
    float* Os = smf;
    {
        const int n0 = warp * 16 + ar;
        #pragma unroll
        for (int nt = 0; nt < 5; ++nt) {
            int col = nt * 8 + 2 * ac;
            *(float2*)(Os + n0 * 44 + col)       = make_float2(O[nt].x, O[nt].y);
            *(float2*)(Os + (n0 + 8) * 44 + col) = make_float2(O[nt].z, O[nt].w);
        }
    }
    __syncthreads();

    const float4* Os4 = (const float4*)Os;
    float4* out4 = (float4*)out;
    for (int i = t; i < 128 * 10; i += 256) {
        int n = i / 10, q = i - n * 10;
        int ngl = base + n;
        if (ngl < nNodes) out4[(size_t)ngl * 10 + q] = Os4[n * 11 + q];
    }
}

// -------- launch --------
extern "C" void kernel_launch(void* const* d_in, const int* in_sizes, int n_in,
                              void* d_out, int out_size)
{
    const float* feat = (const float*)d_in[0];
    const int*   ei   = (const int*)d_in[1];     // int32 (JAX x64 disabled)
    const float* W1  = (const float*)d_in[2];
    const float* b1  = (const float*)d_in[3];
    const float* W2  = (const float*)d_in[4];
    const float* b2  = (const float*)d_in[5];
    const float* Wm1 = (const float*)d_in[6];
    const float* bm1 = (const float*)d_in[7];
    const float* Wm2 = (const float*)d_in[8];
    const float* bm2 = (const float*)d_in[9];
    float* out = (float*)d_out;

    const int N = in_sizes[0] / 64;     // 100000
    const int E = in_sizes[1] / 2;      // 1600000

    float *agg, *h1, *h2, *wp;
    int *deg, *off, *cur, *csr, *bsum;
    cudaGetSymbolAddress((void**)&agg, g_agg);
    cudaGetSymbolAddress((void**)&h1,  g_h1);
    cudaGetSymbolAddress((void**)&h2,  g_h2);
    cudaGetSymbolAddress((void**)&wp,  g_wp);
    cudaGetSymbolAddress((void**)&deg, g_deg);
    cudaGetSymbolAddress((void**)&off, g_off);
    cudaGetSymbolAddress((void**)&cur, g_cur);
    cudaGetSymbolAddress((void**)&csr, g_csr);
    cudaGetSymbolAddress((void**)&bsum, g_bsum);

    const int SM_GEMM = SMF_TOTAL * 4;   // 73,728 B -> 2 blocks/SM
    cudaFuncSetAttribute(combine_kernel<128>, cudaFuncAttributeMaxDynamicSharedMemorySize, SM_GEMM);
    cudaFuncSetAttribute(combine_kernel<256>, cudaFuncAttributeMaxDynamicSharedMemorySize, SM_GEMM);
    cudaFuncSetAttribute(mlp_fused_kernel,    cudaFuncAttributeMaxDynamicSharedMemorySize, SM_GEMM);

    const int nodeBlocks = (N + 127) / 128;      // 782
    const int gatherBlocks = (N + 7) / 8;        // 12500
    const int scanBlocks = (N + 1023) / 1024;    // 98
    const int edgeBlocks = (E + 255) / 256;

    // ---- CSR build (once; reused by both layers) + W packing ----
    prep1_kernel<<<2048, 256>>>(deg, N, W1, W2, Wm1, Wm2, wp);
    hist_kernel<<<edgeBlocks, 256>>>(ei, deg, E, N);
    scan1_kernel<<<scanBlocks, 1024>>>(deg, off, bsum, N);
    scan2_kernel<<<1, 32>>>(bsum, scanBlocks);
    scan3_kernel<<<scanBlocks, 1024>>>(off, cur, bsum, N);
    place_kernel<<<edgeBlocks, 256>>>(ei, cur, csr, E, N);

    // ---- Layer 1 ----
    gather64_kernel<<<gatherBlocks, 256>>>(off, deg, csr, feat, agg, N);
    combine_kernel<128><<<nodeBlocks, 256, SM_GEMM>>>(feat, agg, wp, b1, h1, N);
    // ---- Layer 2 ----
    gather128_kernel<<<gatherBlocks, 256>>>(off, deg, csr, h1, agg, N);
    combine_kernel<256><<<nodeBlocks, 256, SM_GEMM>>>(h1, agg, wp + 16384, b2, h2, N);
    // ---- MLP (fused: hidden layer never leaves the SM) ----
    mlp_fused_kernel<<<nodeBlocks, 256, SM_GEMM>>>(h2, wp + 49152, bm1,
                                                   wp + 81920, bm2, out, N);
}